// round 2
// baseline (speedup 1.0000x reference)
#include <cuda_runtime.h>

// ---------------- problem constants ----------------
#define NB   32      // batch
#define C_R  32      // residual channels
#define C_C  32      // conv channels
#define C_S  64      // skip channels
#define NV   500     // nodes
#define NT   64      // input time
#define NK   52      // time after dilated inception
#define NMCOL (NB*C_C*NK)   // 53248 = GEMM N dim (node-major h columns)
#define APAD 512            // padded adjacency row stride
#define HVEC (C_C*NK)       // 1664 floats per (n,b)
#define CNT_PER_B (C_C*NV*NK)  // 832000

// ---------------- device scratch ----------------
__device__ float g_a1[NV*APAD];
__device__ float g_a2[NV*APAD];
__device__ float g_Wf[C_C*C_R*7];
__device__ float g_Wg[C_C*C_R*7];
__device__ float g_fbias[C_C];
__device__ float g_gbias[C_C];
__device__ float g_h  [NV*NB*C_C*NK];
__device__ float g_h1a[NV*NB*C_C*NK];
__device__ float g_h2a[NV*NB*C_C*NK];
__device__ float g_h1b[NV*NB*C_C*NK];
__device__ float g_h2b[NV*NB*C_C*NK];
__device__ float g_xo [NB*C_C*NV*NK];
__device__ float g_stats[2*NB];

// ---------------- prep: pack unified 7-tap weights, zero stats ----------------
__global__ void pack_kernel(const float* __restrict__ fw2, const float* __restrict__ fw3,
                            const float* __restrict__ fw6, const float* __restrict__ fw7,
                            const float* __restrict__ fb2, const float* __restrict__ fb3,
                            const float* __restrict__ fb6, const float* __restrict__ fb7,
                            const float* __restrict__ gw2, const float* __restrict__ gw3,
                            const float* __restrict__ gw6, const float* __restrict__ gw7,
                            const float* __restrict__ gb2, const float* __restrict__ gb3,
                            const float* __restrict__ gb6, const float* __restrict__ gb7)
{
    int tid = threadIdx.x;
    if (tid < 2*NB) g_stats[tid] = 0.f;
    for (int e = tid; e < C_C*C_R*7; e += blockDim.x) {
        int j  = e % 7;
        int i  = (e / 7) % C_R;
        int o  = e / (7*C_R);
        int br = o >> 3, oo = o & 7;
        int k  = (br==0)?2:(br==1)?3:(br==2)?6:7;
        int j0 = 7 - k;
        float vf = 0.f, vg = 0.f;
        if (j >= j0) {
            int si = (oo*C_R + i)*k + (j - j0);
            const float* fw = (br==0)?fw2:(br==1)?fw3:(br==2)?fw6:fw7;
            const float* gw = (br==0)?gw2:(br==1)?gw3:(br==2)?gw6:gw7;
            vf = fw[si]; vg = gw[si];
        }
        g_Wf[e] = vf; g_Wg[e] = vg;
    }
    if (tid < C_C) {
        int br = tid >> 3, oo = tid & 7;
        const float* fb = (br==0)?fb2:(br==1)?fb3:(br==2)?fb6:fb7;
        const float* gb = (br==0)?gb2:(br==1)?gb3:(br==2)?gb6:gb7;
        g_fbias[tid] = fb[oo]; g_gbias[tid] = gb[oo];
    }
}

// ---------------- normalized adjacencies (row-stride padded to 512, zero pad) ----------------
__global__ void adj_kernel(const float* __restrict__ adp)
{
    int v = blockIdx.x % NV;
    int which = blockIdx.x / NV;   // 0: a1 (rows of adp), 1: a2 (rows of adp^T)
    __shared__ float red[256];
    float s = 0.f;
    for (int w = threadIdx.x; w < NV; w += 256)
        s += (which == 0) ? adp[v*NV + w] : adp[w*NV + v];
    red[threadIdx.x] = s; __syncthreads();
    for (int st = 128; st > 0; st >>= 1) {
        if (threadIdx.x < st) red[threadIdx.x] += red[threadIdx.x + st];
        __syncthreads();
    }
    float inv = 1.f / (red[0] + 1.f);   // +1 for identity
    float* dst = (which == 0) ? g_a1 : g_a2;
    for (int w = threadIdx.x; w < APAD; w += 256) {
        float val = 0.f;
        if (w < NV) {
            val = (which == 0) ? adp[v*NV + w] : adp[w*NV + v];
            if (w == v) val += 1.f;
            val *= inv;
        }
        dst[v*APAD + w] = val;
    }
}

// ---------------- fused dilated inception (f,g) + tanh*sigmoid gating ----------------
// h stored node-major: h[((n*NB+b)*C_C + o)*NK + t]
#define INCEPT_SMEM ((4*32*72 + 2*7168 + 64)*4)
__global__ __launch_bounds__(256) void incept_kernel(const float* __restrict__ x)
{
    extern __shared__ __align__(16) float sm[];
    float* xs  = sm;                 // 4 * 32 * 72
    float* Wfs = xs + 4*32*72;       // 7168
    float* Wgs = Wfs + 7168;         // 7168
    float* fbs = Wgs + 7168;         // 32
    float* gbs = fbs + 32;           // 32
    int tid = threadIdx.x;

    for (int e = tid; e < 7168; e += 256) { Wfs[e] = g_Wf[e]; Wgs[e] = g_Wg[e]; }
    if (tid < 32) { fbs[tid] = g_fbias[tid]; gbs[tid] = g_gbias[tid]; }

    int p0 = blockIdx.x * 4;
    #pragma unroll
    for (int it = 0; it < 8; it++) {
        int lin = tid + it*256;        // 2048 float4 total
        int sub = lin >> 9;
        int rem = lin & 511;
        int i   = rem >> 4;
        int tq  = rem & 15;
        int p = p0 + sub;
        int n = p >> 5, b = p & 31;
        float4 v = *(const float4*)&x[((b*C_R + i)*NV + n)*NT + tq*4];
        *(float4*)&xs[(sub*32 + i)*72 + tq*4] = v;
    }
    __syncthreads();

    int sub = tid >> 6;
    int oq  = (tid >> 3) & 7;
    int tg  = tid & 7;

    float accf[4][7], accg[4][7];
    #pragma unroll
    for (int m = 0; m < 4; m++)
        #pragma unroll
        for (int s = 0; s < 7; s++) { accf[m][s] = 0.f; accg[m][s] = 0.f; }

    const float* xb = &xs[sub*32*72];
    for (int i = 0; i < 32; i++) {
        const float* xr = xb + i*72;
        #pragma unroll
        for (int j = 0; j < 7; j++) {
            float xv[7];
            #pragma unroll
            for (int s = 0; s < 7; s++) xv[s] = xr[tg + 8*s + 2*j];
            #pragma unroll
            for (int m = 0; m < 4; m++) {
                float wf = Wfs[(oq + 8*m)*224 + i*7 + j];
                float wg = Wgs[(oq + 8*m)*224 + i*7 + j];
                #pragma unroll
                for (int s = 0; s < 7; s++) {
                    accf[m][s] = fmaf(xv[s], wf, accf[m][s]);
                    accg[m][s] = fmaf(xv[s], wg, accg[m][s]);
                }
            }
        }
    }

    int p = p0 + sub;
    int n = p >> 5, b = p & 31;
    float* hout = &g_h[(n*NB + b)*HVEC];
    #pragma unroll
    for (int m = 0; m < 4; m++) {
        int o = oq + 8*m;
        #pragma unroll
        for (int s = 0; s < 7; s++) {
            int t = tg + 8*s;
            if (t < NK) {
                float f  = tanhf(accf[m][s] + fbs[o]);
                float gz = accg[m][s] + gbs[o];
                float gg = 1.f / (1.f + __expf(-gz));
                hout[o*NK + t] = f * gg;
            }
        }
    }
}

// ---------------- skip conv: s[b,cs,n] = <h[(n,b),:], skip_w[cs,:]> + skip_b ----------------
#define SKIP_SMEM (8*HVEC*4)
__global__ __launch_bounds__(256) void skip_kernel(const float* __restrict__ skipw,
                                                   const float* __restrict__ skipb,
                                                   float* __restrict__ sout)
{
    extern __shared__ __align__(16) float hs[];   // [8][1664]
    int tid = threadIdx.x;
    int b  = blockIdx.y;
    int n0 = blockIdx.x * 8;

    for (int lin = tid; lin < 8*416; lin += 256) {
        int nn = lin / 416, q = lin % 416;
        int n = n0 + nn;
        float4 v = make_float4(0.f, 0.f, 0.f, 0.f);
        if (n < NV) v = *(const float4*)&g_h[(n*NB + b)*HVEC + q*4];
        *(float4*)&hs[nn*HVEC + q*4] = v;
    }
    __syncthreads();

    int warp = tid >> 5, lane = tid & 31;
    int n = n0 + warp;
    if (n >= NV) return;
    const float4* hv = (const float4*)&hs[warp*HVEC];
    for (int cs = 0; cs < C_S; cs++) {
        const float4* wv = (const float4*)&skipw[cs*HVEC];
        float acc = 0.f;
        #pragma unroll
        for (int q = 0; q < 13; q++) {
            float4 w4 = wv[q*32 + lane];
            float4 h4 = hv[q*32 + lane];
            acc = fmaf(w4.x, h4.x, acc);
            acc = fmaf(w4.y, h4.y, acc);
            acc = fmaf(w4.z, h4.z, acc);
            acc = fmaf(w4.w, h4.w, acc);
        }
        #pragma unroll
        for (int off = 16; off > 0; off >>= 1)
            acc += __shfl_down_sync(0xffffffffu, acc, off);
        if (lane == 0) sout[(b*C_S + cs)*NV + n] = acc + skipb[cs];
    }
}

// ---------------- graph propagation GEMM: Hout = 0.05*g_h + 0.95*(A @ Hin) ----------------
// A: [500 x 512-padded], Hin/Hout: [500 x 53248]
__global__ __launch_bounds__(256) void prop_kernel(int step)
{
    const float* A; const float* Hin; float* Hout;
    if (blockIdx.z == 0) { A = g_a1; Hin = (step == 1) ? g_h : g_h1a; Hout = (step == 1) ? g_h1a : g_h2a; }
    else                 { A = g_a2; Hin = (step == 1) ? g_h : g_h1b; Hout = (step == 1) ? g_h1b : g_h2b; }

    __shared__ __align__(16) float As[16][132];
    __shared__ __align__(16) float Bs[16][128];

    int tid = threadIdx.x;
    int ty = tid >> 4, tx = tid & 15;
    int vbase = blockIdx.y * 128;
    int nbase = blockIdx.x * 128;

    float acc[8][8];
    #pragma unroll
    for (int i = 0; i < 8; i++)
        #pragma unroll
        for (int j = 0; j < 8; j++) acc[i][j] = 0.f;

    for (int kk = 0; kk < APAD; kk += 16) {
        #pragma unroll
        for (int it = 0; it < 2; it++) {
            int lin = tid + it*256;
            int row = lin >> 2;
            int kq  = (lin & 3) * 4;
            int v = vbase + row;
            float4 val = make_float4(0.f, 0.f, 0.f, 0.f);
            if (v < NV) val = *(const float4*)&A[v*APAD + kk + kq];
            As[kq+0][row] = val.x; As[kq+1][row] = val.y;
            As[kq+2][row] = val.z; As[kq+3][row] = val.w;
        }
        #pragma unroll
        for (int it = 0; it < 2; it++) {
            int lin = tid + it*256;
            int krow = lin >> 5;
            int nq   = (lin & 31) * 4;
            int kg = kk + krow;
            float4 val = make_float4(0.f, 0.f, 0.f, 0.f);
            if (kg < NV) val = *(const float4*)&Hin[kg*NMCOL + nbase + nq];
            *(float4*)&Bs[krow][nq] = val;
        }
        __syncthreads();
        #pragma unroll
        for (int k = 0; k < 16; k++) {
            float ra[8], rb[8];
            *(float4*)&ra[0] = *(float4*)&As[k][ty*8];
            *(float4*)&ra[4] = *(float4*)&As[k][ty*8 + 4];
            *(float4*)&rb[0] = *(float4*)&Bs[k][tx*8];
            *(float4*)&rb[4] = *(float4*)&Bs[k][tx*8 + 4];
            #pragma unroll
            for (int i = 0; i < 8; i++)
                #pragma unroll
                for (int j = 0; j < 8; j++)
                    acc[i][j] = fmaf(ra[i], rb[j], acc[i][j]);
        }
        __syncthreads();
    }

    #pragma unroll
    for (int i = 0; i < 8; i++) {
        int v = vbase + ty*8 + i;
        if (v < NV) {
            int base = v*NMCOL + nbase + tx*8;
            #pragma unroll
            for (int jq = 0; jq < 2; jq++) {
                float4 hb = *(const float4*)&g_h[base + jq*4];
                float4 o;
                o.x = fmaf(0.95f, acc[i][jq*4+0], 0.05f*hb.x);
                o.y = fmaf(0.95f, acc[i][jq*4+1], 0.05f*hb.y);
                o.z = fmaf(0.95f, acc[i][jq*4+2], 0.05f*hb.z);
                o.w = fmaf(0.95f, acc[i][jq*4+3], 0.05f*hb.w);
                *(float4*)&Hout[base + jq*4] = o;
            }
        }
    }
}

// ---------------- combine: xo = conv1x1(h,h1a,h2a;gc1) + conv1x1(h,h1b,h2b;gc2) + residual ----------------
// also accumulates per-batch sum / sumsq for LayerNorm
#define COMB_SMEM ((4*5*32*56 + 5*1024 + 32)*4)
__global__ __launch_bounds__(256) void combine_kernel(const float* __restrict__ x,
                                                      const float* __restrict__ gc1w,
                                                      const float* __restrict__ gc1b,
                                                      const float* __restrict__ gc2w,
                                                      const float* __restrict__ gc2b)
{
    extern __shared__ __align__(16) float sm[];
    float* ts = sm;                      // [4 sub][5 tensors][32 c'][56]
    float* ws = sm + 4*5*32*56;          // [5][cp][c] (cp-major to avoid bank conflicts)
    float* bs = ws + 5*1024;             // 32
    int tid = threadIdx.x;
    int v  = blockIdx.x;
    int bg = blockIdx.y;

    for (int e = tid; e < 1024; e += 256) {
        int cp = e >> 5, c = e & 31;
        ws[0*1024 + cp*32 + c] = gc1w[c*96 + cp] + gc2w[c*96 + cp];
        ws[1*1024 + cp*32 + c] = gc1w[c*96 + 32 + cp];
        ws[2*1024 + cp*32 + c] = gc1w[c*96 + 64 + cp];
        ws[3*1024 + cp*32 + c] = gc2w[c*96 + 32 + cp];
        ws[4*1024 + cp*32 + c] = gc2w[c*96 + 64 + cp];
    }
    if (tid < 32) bs[tid] = gc1b[tid] + gc2b[tid];

    #pragma unroll
    for (int t = 0; t < 5; t++) {
        const float* src = (t==0)?g_h:(t==1)?g_h1a:(t==2)?g_h2a:(t==3)?g_h1b:g_h2b;
        for (int lin = tid; lin < 4*32*13; lin += 256) {
            int lq = lin % 13;
            int r  = lin / 13;
            int cp = r & 31;
            int sub = r >> 5;
            int b = bg*4 + sub;
            float4 val = *(const float4*)&src[(v*NB + b)*HVEC + cp*NK + lq*4];
            *(float4*)&ts[((sub*5 + t)*32 + cp)*56 + lq*4] = val;
        }
    }
    __syncthreads();

    int sub = tid >> 6;
    int cq  = (tid >> 3) & 7;
    int lg  = tid & 7;
    int b = bg*4 + sub;

    float acc[4][7];
    #pragma unroll
    for (int m = 0; m < 4; m++)
        #pragma unroll
        for (int s = 0; s < 7; s++) acc[m][s] = 0.f;

    const float* tb = &ts[sub*5*32*56];
    for (int cp = 0; cp < 32; cp++) {
        float w0[4], w1[4], w2[4], w3[4], w4[4];
        #pragma unroll
        for (int m = 0; m < 4; m++) {
            int c = cq + 8*m;
            w0[m] = ws[0*1024 + cp*32 + c];
            w1[m] = ws[1*1024 + cp*32 + c];
            w2[m] = ws[2*1024 + cp*32 + c];
            w3[m] = ws[3*1024 + cp*32 + c];
            w4[m] = ws[4*1024 + cp*32 + c];
        }
        #pragma unroll
        for (int s = 0; s < 7; s++) {
            int l = lg + 8*s;
            float v0 = tb[(0*32 + cp)*56 + l];
            float v1 = tb[(1*32 + cp)*56 + l];
            float v2 = tb[(2*32 + cp)*56 + l];
            float v3 = tb[(3*32 + cp)*56 + l];
            float v4 = tb[(4*32 + cp)*56 + l];
            #pragma unroll
            for (int m = 0; m < 4; m++) {
                acc[m][s] = fmaf(w0[m], v0, acc[m][s]);
                acc[m][s] = fmaf(w1[m], v1, acc[m][s]);
                acc[m][s] = fmaf(w2[m], v2, acc[m][s]);
                acc[m][s] = fmaf(w3[m], v3, acc[m][s]);
                acc[m][s] = fmaf(w4[m], v4, acc[m][s]);
            }
        }
    }

    float psum = 0.f, psq = 0.f;
    #pragma unroll
    for (int m = 0; m < 4; m++) {
        int c = cq + 8*m;
        #pragma unroll
        for (int s = 0; s < 7; s++) {
            int l = lg + 8*s;
            if (l < NK) {
                float val = acc[m][s] + bs[c] + x[((b*C_R + c)*NV + v)*NT + 12 + l];
                g_xo[((b*C_C + c)*NV + v)*NK + l] = val;
                psum += val;
                psq  = fmaf(val, val, psq);
            }
        }
    }
    #pragma unroll
    for (int off = 16; off > 0; off >>= 1) {
        psum += __shfl_down_sync(0xffffffffu, psum, off);
        psq  += __shfl_down_sync(0xffffffffu, psq,  off);
    }
    if ((tid & 31) == 0) {
        atomicAdd(&g_stats[2*b],     psum);
        atomicAdd(&g_stats[2*b + 1], psq);
    }
}

// ---------------- LayerNorm apply ----------------
__global__ __launch_bounds__(256) void norm_kernel(const int* __restrict__ idx,
                                                   const float* __restrict__ lnw,
                                                   const float* __restrict__ lnb,
                                                   float* __restrict__ out)
{
    int gid = blockIdx.x * 256 + threadIdx.x;   // one float4 each; 6,656,000 total
    int lq  = gid % 13;
    int row = gid / 13;                         // = ((b*32 + c)*500 + v)
    int v = row % NV;
    int c = (row / NV) % C_C;
    int b = row / (C_C*NV);

    float s1 = g_stats[2*b], s2 = g_stats[2*b + 1];
    float mean = s1 * (1.f / (float)CNT_PER_B);
    float var  = s2 * (1.f / (float)CNT_PER_B) - mean*mean;
    float rstd = rsqrtf(var + 1e-5f);
    int nidx = idx[v];

    float4 xo = *(const float4*)&g_xo[row*NK + lq*4];
    float4 w4 = *(const float4*)&lnw[(c*NV + nidx)*NK + lq*4];
    float4 b4 = *(const float4*)&lnb[(c*NV + nidx)*NK + lq*4];
    float4 o;
    o.x = (xo.x - mean)*rstd*w4.x + b4.x;
    o.y = (xo.y - mean)*rstd*w4.y + b4.y;
    o.z = (xo.z - mean)*rstd*w4.z + b4.z;
    o.w = (xo.w - mean)*rstd*w4.w + b4.w;
    *(float4*)&out[row*NK + lq*4] = o;
}

// ---------------- launch ----------------
extern "C" void kernel_launch(void* const* d_in, const int* in_sizes, int n_in,
                              void* d_out, int out_size)
{
    const float* x = (const float*)d_in[0];
    int ia = (in_sizes[1] == NV*NV) ? 1 : 2;   // adp vs idx position
    const float* adp = (const float*)d_in[ia];
    const int*   idx = (const int*)d_in[3 - ia];
    const float* fw2 = (const float*)d_in[3];
    const float* fb2 = (const float*)d_in[4];
    const float* fw3 = (const float*)d_in[5];
    const float* fb3 = (const float*)d_in[6];
    const float* fw6 = (const float*)d_in[7];
    const float* fb6 = (const float*)d_in[8];
    const float* fw7 = (const float*)d_in[9];
    const float* fb7 = (const float*)d_in[10];
    const float* gw2 = (const float*)d_in[11];
    const float* gb2 = (const float*)d_in[12];
    const float* gw3 = (const float*)d_in[13];
    const float* gb3 = (const float*)d_in[14];
    const float* gw6 = (const float*)d_in[15];
    const float* gb6 = (const float*)d_in[16];
    const float* gw7 = (const float*)d_in[17];
    const float* gb7 = (const float*)d_in[18];
    const float* skipw = (const float*)d_in[19];
    const float* skipb = (const float*)d_in[20];
    const float* gc1w  = (const float*)d_in[21];
    const float* gc1b  = (const float*)d_in[22];
    const float* gc2w  = (const float*)d_in[23];
    const float* gc2b  = (const float*)d_in[24];
    const float* lnw   = (const float*)d_in[25];
    const float* lnb   = (const float*)d_in[26];
    float* out = (float*)d_out;
    float* xn_out = out;                            // [32,32,500,52]
    float* s_out  = out + NB*C_C*NV*NK;             // [32,64,500,1]

    cudaFuncSetAttribute(incept_kernel,  cudaFuncAttributeMaxDynamicSharedMemorySize, INCEPT_SMEM);
    cudaFuncSetAttribute(skip_kernel,    cudaFuncAttributeMaxDynamicSharedMemorySize, SKIP_SMEM);
    cudaFuncSetAttribute(combine_kernel, cudaFuncAttributeMaxDynamicSharedMemorySize, COMB_SMEM);

    pack_kernel<<<1, 256>>>(fw2, fw3, fw6, fw7, fb2, fb3, fb6, fb7,
                            gw2, gw3, gw6, gw7, gb2, gb3, gb6, gb7);
    adj_kernel<<<2*NV, 256>>>(adp);
    incept_kernel<<<(NV*NB)/4, 256, INCEPT_SMEM>>>(x);
    skip_kernel<<<dim3(63, NB), 256, SKIP_SMEM>>>(skipw, skipb, s_out);
    prop_kernel<<<dim3(NMCOL/128, 4, 2), 256>>>(1);
    prop_kernel<<<dim3(NMCOL/128, 4, 2), 256>>>(2);
    combine_kernel<<<dim3(NV, 8), 256, COMB_SMEM>>>(x, gc1w, gc1b, gc2w, gc2b);
    norm_kernel<<<26000, 256>>>(idx, lnw, lnb, xn_out);
}

// round 4
// speedup vs baseline: 1.5888x; 1.5888x over previous
#include <cuda_runtime.h>
#include <cstdint>

// ---------------- problem constants ----------------
#define NB   32
#define C_R  32
#define C_C  32
#define C_S  64
#define NV   500
#define NT   64
#define NK   52
#define NMCOL (NB*C_C*NK)   // 53248
#define VP   512            // padded node dim (K and M for prop GEMM)
#define HVEC (C_C*NK)       // 1664
#define CNT_PER_B (C_C*NV*NK)

// ---------------- device scratch (zero-initialized globals) ----------------
__device__ float g_a1[VP*VP];
__device__ float g_a2[VP*VP];
__device__ float g_Wf[C_C*C_R*7];
__device__ float g_Wg[C_C*C_R*7];
__device__ float g_fbias[C_C];
__device__ float g_gbias[C_C];
// K-rows padded to 512 so prop GEMM can read rows 500..511 (they stay zero)
__device__ float g_h  [VP*NMCOL];
__device__ float g_h1a[VP*NMCOL];
__device__ float g_h2a[VP*NMCOL];
__device__ float g_h1b[VP*NMCOL];
__device__ float g_h2b[VP*NMCOL];
__device__ float g_xo [NB*C_C*NV*NK];
__device__ float g_stats[2*NB];

// ---------------- small helpers ----------------
__device__ __forceinline__ uint32_t smem_u32(const void* p){
    uint32_t a; asm("{ .reg .u64 t; cvta.to.shared.u64 t, %1; cvt.u32.u64 %0, t; }":"=r"(a):"l"(p)); return a;
}
__device__ __forceinline__ float tf32r(float x){
    uint32_t u; asm("cvt.rna.tf32.f32 %0, %1;":"=r"(u):"f"(x)); return __uint_as_float(u);
}
__device__ __forceinline__ uint32_t tf32u(float x){
    uint32_t u; asm("cvt.rna.tf32.f32 %0, %1;":"=r"(u):"f"(x)); return u;
}
#define CP_ASYNC16(s,g) asm volatile("cp.async.cg.shared.global [%0], [%1], 16;"::"r"(s),"l"(g))
#define CP_COMMIT()     asm volatile("cp.async.commit_group;" ::: "memory")
#define CP_WAIT1()      asm volatile("cp.async.wait_group 1;" ::: "memory")
#define CP_WAIT0()      asm volatile("cp.async.wait_group 0;" ::: "memory")

__device__ __forceinline__ void mma_tf32(float* c, const uint32_t* a, const uint32_t* b){
    asm volatile("mma.sync.aligned.m16n8k8.row.col.f32.tf32.tf32.f32 "
        "{%0,%1,%2,%3}, {%4,%5,%6,%7}, {%8,%9}, {%0,%1,%2,%3};"
        : "+f"(c[0]),"+f"(c[1]),"+f"(c[2]),"+f"(c[3])
        : "r"(a[0]),"r"(a[1]),"r"(a[2]),"r"(a[3]), "r"(b[0]),"r"(b[1]));
}

// ---------------- pack unified 7-tap weights, zero stats ----------------
__global__ void pack_kernel(const float* __restrict__ fw2,const float* __restrict__ fw3,
    const float* __restrict__ fw6,const float* __restrict__ fw7,
    const float* __restrict__ fb2,const float* __restrict__ fb3,
    const float* __restrict__ fb6,const float* __restrict__ fb7,
    const float* __restrict__ gw2,const float* __restrict__ gw3,
    const float* __restrict__ gw6,const float* __restrict__ gw7,
    const float* __restrict__ gb2,const float* __restrict__ gb3,
    const float* __restrict__ gb6,const float* __restrict__ gb7)
{
    int tid = threadIdx.x;
    if (tid < 2*NB) g_stats[tid] = 0.f;
    for (int e = tid; e < C_C*C_R*7; e += blockDim.x) {
        int j = e % 7, i = (e/7) % C_R, o = e/(7*C_R);
        int br = o >> 3, oo = o & 7;
        int k = (br==0)?2:(br==1)?3:(br==2)?6:7;
        int j0 = 7 - k;
        float vf = 0.f, vg = 0.f;
        if (j >= j0) {
            int si = (oo*C_R + i)*k + (j - j0);
            const float* fw = (br==0)?fw2:(br==1)?fw3:(br==2)?fw6:fw7;
            const float* gw = (br==0)?gw2:(br==1)?gw3:(br==2)?gw6:gw7;
            vf = fw[si]; vg = gw[si];
        }
        g_Wf[e] = vf; g_Wg[e] = vg;
    }
    if (tid < C_C) {
        int br = tid >> 3, oo = tid & 7;
        const float* fb = (br==0)?fb2:(br==1)?fb3:(br==2)?fb6:fb7;
        const float* gb = (br==0)?gb2:(br==1)?gb3:(br==2)?gb6:gb7;
        g_fbias[tid] = fb[oo]; g_gbias[tid] = gb[oo];
    }
}

// ---------------- normalized adjacencies, tf32-rounded, padded to 512x512 ----------------
__global__ void adj_kernel(const float* __restrict__ adp)
{
    int v = blockIdx.x & 511;
    int which = blockIdx.x >> 9;
    float* dst = which ? g_a2 : g_a1;
    if (v >= NV) {
        for (int w = threadIdx.x; w < VP; w += 256) dst[v*VP + w] = 0.f;
        return;
    }
    __shared__ float red[256];
    float s = 0.f;
    for (int w = threadIdx.x; w < NV; w += 256)
        s += which ? adp[w*NV + v] : adp[v*NV + w];
    red[threadIdx.x] = s; __syncthreads();
    for (int st = 128; st > 0; st >>= 1) {
        if (threadIdx.x < st) red[threadIdx.x] += red[threadIdx.x + st];
        __syncthreads();
    }
    float inv = 1.f / (red[0] + 1.f);
    for (int w = threadIdx.x; w < VP; w += 256) {
        float val = 0.f;
        if (w < NV) {
            val = which ? adp[w*NV + v] : adp[v*NV + w];
            if (w == v) val += 1.f;
            val = tf32r(val * inv);
        }
        dst[v*VP + w] = val;
    }
}

// ---------------- fused dilated inception + gating ----------------
#define INCEPT_SMEM ((4*32*72 + 2*7168 + 64)*4)
__global__ __launch_bounds__(256) void incept_kernel(const float* __restrict__ x)
{
    extern __shared__ __align__(16) float sm[];
    float* xs = sm;
    float* Wfs = xs + 4*32*72;
    float* Wgs = Wfs + 7168;
    float* fbs = Wgs + 7168;
    float* gbs = fbs + 32;
    int tid = threadIdx.x;
    for (int e = tid; e < 7168; e += 256) { Wfs[e] = g_Wf[e]; Wgs[e] = g_Wg[e]; }
    if (tid < 32) { fbs[tid] = g_fbias[tid]; gbs[tid] = g_gbias[tid]; }
    int p0 = blockIdx.x * 4;
    #pragma unroll
    for (int it = 0; it < 8; it++) {
        int lin = tid + it*256;
        int sub = lin >> 9, rem = lin & 511;
        int i = rem >> 4, tq = rem & 15;
        int p = p0 + sub, n = p >> 5, b = p & 31;
        float4 v = *(const float4*)&x[((b*C_R + i)*NV + n)*NT + tq*4];
        *(float4*)&xs[(sub*32 + i)*72 + tq*4] = v;
    }
    __syncthreads();
    int sub = tid >> 6, oq = (tid >> 3) & 7, tg = tid & 7;
    float accf[4][7], accg[4][7];
    #pragma unroll
    for (int m = 0; m < 4; m++)
        #pragma unroll
        for (int s = 0; s < 7; s++) { accf[m][s] = 0.f; accg[m][s] = 0.f; }
    const float* xb = &xs[sub*32*72];
    for (int i = 0; i < 32; i++) {
        const float* xr = xb + i*72;
        #pragma unroll
        for (int j = 0; j < 7; j++) {
            float xv[7];
            #pragma unroll
            for (int s = 0; s < 7; s++) xv[s] = xr[tg + 8*s + 2*j];
            #pragma unroll
            for (int m = 0; m < 4; m++) {
                float wf = Wfs[(oq + 8*m)*224 + i*7 + j];
                float wg = Wgs[(oq + 8*m)*224 + i*7 + j];
                #pragma unroll
                for (int s = 0; s < 7; s++) {
                    accf[m][s] = fmaf(xv[s], wf, accf[m][s]);
                    accg[m][s] = fmaf(xv[s], wg, accg[m][s]);
                }
            }
        }
    }
    int p = p0 + sub, n = p >> 5, b = p & 31;
    float* hout = &g_h[(n*NB + b)*HVEC];
    #pragma unroll
    for (int m = 0; m < 4; m++) {
        int o = oq + 8*m;
        #pragma unroll
        for (int s = 0; s < 7; s++) {
            int t = tg + 8*s;
            if (t < NK) {
                float f = tanhf(accf[m][s] + fbs[o]);
                float gz = accg[m][s] + gbs[o];
                hout[o*NK + t] = f / (1.f + __expf(-gz));
            }
        }
    }
}

// ---------------- skip conv ----------------
#define SKIP_SMEM (8*HVEC*4)
__global__ __launch_bounds__(256) void skip_kernel(const float* __restrict__ skipw,
                                                   const float* __restrict__ skipb,
                                                   float* __restrict__ sout)
{
    extern __shared__ __align__(16) float hs[];
    int tid = threadIdx.x, b = blockIdx.y, n0 = blockIdx.x * 8;
    for (int lin = tid; lin < 8*416; lin += 256) {
        int nn = lin / 416, q = lin % 416;
        int n = n0 + nn;
        float4 v = make_float4(0.f,0.f,0.f,0.f);
        if (n < NV) v = *(const float4*)&g_h[(n*NB + b)*HVEC + q*4];
        *(float4*)&hs[nn*HVEC + q*4] = v;
    }
    __syncthreads();
    int warp = tid >> 5, lane = tid & 31;
    int n = n0 + warp;
    if (n >= NV) return;
    const float4* hv = (const float4*)&hs[warp*HVEC];
    for (int cs = 0; cs < C_S; cs++) {
        const float4* wv = (const float4*)&skipw[cs*HVEC];
        float acc = 0.f;
        #pragma unroll
        for (int q = 0; q < 13; q++) {
            float4 w4 = wv[q*32 + lane];
            float4 h4 = hv[q*32 + lane];
            acc = fmaf(w4.x,h4.x,acc); acc = fmaf(w4.y,h4.y,acc);
            acc = fmaf(w4.z,h4.z,acc); acc = fmaf(w4.w,h4.w,acc);
        }
        #pragma unroll
        for (int off = 16; off > 0; off >>= 1) acc += __shfl_down_sync(0xffffffffu, acc, off);
        if (lane == 0) sout[(b*C_S + cs)*NV + n] = acc + skipb[cs];
    }
}

// ---------------- HMMA tf32 prop: Hout = 0.05*g_h + 0.95*(Adj @ Hin) ----------------
// A = adjacency [512 x 512] tf32-rounded; B = Hin [512 x 53248] (rows 500+ zero)
#define ASTR 36
#define BSTR 132
#define ATILE (128*ASTR)
#define BTILE (32*BSTR)
#define BUFSZ (ATILE+BTILE)
#define PROP_SMEM (2*BUFSZ*4)
__global__ __launch_bounds__(256,2) void prop_mma(int step)
{
    extern __shared__ __align__(16) float smp[];
    const float* Aadj; const float* Hin; float* Hout;
    if (blockIdx.z == 0) { Aadj = g_a1; Hin = (step==1) ? g_h : g_h1a; Hout = (step==1) ? g_h1a : g_h2a; }
    else                 { Aadj = g_a2; Hin = (step==1) ? g_h : g_h1b; Hout = (step==1) ? g_h1b : g_h2b; }

    int tid = threadIdx.x, warp = tid >> 5, lane = tid & 31;
    int gid = lane >> 2, tig = lane & 3;
    int nbase = blockIdx.x * 128;
    int vtile = blockIdx.y;
    int m_off = (warp >> 2) * 64;
    int n_off = (warp & 3) * 32;

    uint32_t sb = smem_u32(smp);

    float c[16][4];
    #pragma unroll
    for (int i = 0; i < 16; i++)
        #pragma unroll
        for (int j = 0; j < 4; j++) c[i][j] = 0.f;

    // async tile loader
    auto load_chunk = [&](int buf, int ch) {
        int w0 = ch * 32;
        uint32_t sA = sb + buf*BUFSZ*4;
        uint32_t sB = sA + ATILE*4;
        #pragma unroll
        for (int j = 0; j < 4; j++) {
            int lin = tid + j*256;
            int r = lin >> 3, q = lin & 7;
            CP_ASYNC16(sA + (r*ASTR + q*4)*4, &Aadj[(vtile*128 + r)*VP + w0 + q*4]);
        }
        #pragma unroll
        for (int j = 0; j < 4; j++) {
            int lin = tid + j*256;
            int r = lin >> 5, q = lin & 31;
            CP_ASYNC16(sB + (r*BSTR + q*4)*4, &Hin[(size_t)(w0 + r)*NMCOL + nbase + q*4]);
        }
        CP_COMMIT();
    };

    load_chunk(0, 0);
    load_chunk(1, 1);

    for (int ch = 0; ch < 16; ch++) {
        if (ch == 15) { CP_WAIT0(); } else { CP_WAIT1(); }
        __syncthreads();
        int buf = ch & 1;
        const float* As = smp + buf*BUFSZ;
        const float* Bs = As + ATILE;
        #pragma unroll
        for (int ks = 0; ks < 4; ks++) {
            int kb = ks*8;
            uint32_t a[4][4];
            #pragma unroll
            for (int mi = 0; mi < 4; mi++) {
                int mr = m_off + mi*16 + gid;
                a[mi][0] = __float_as_uint(As[mr*ASTR + kb + tig]);
                a[mi][1] = __float_as_uint(As[(mr+8)*ASTR + kb + tig]);
                a[mi][2] = __float_as_uint(As[mr*ASTR + kb + tig + 4]);
                a[mi][3] = __float_as_uint(As[(mr+8)*ASTR + kb + tig + 4]);
            }
            uint32_t b[4][2];
            #pragma unroll
            for (int ni = 0; ni < 4; ni++) {
                int nc = n_off + ni*8 + gid;
                b[ni][0] = tf32u(Bs[(kb + tig)*BSTR + nc]);
                b[ni][1] = tf32u(Bs[(kb + 4 + tig)*BSTR + nc]);
            }
            #pragma unroll
            for (int mi = 0; mi < 4; mi++)
                #pragma unroll
                for (int ni = 0; ni < 4; ni++)
                    mma_tf32(c[mi*4+ni], a[mi], b[ni]);
        }
        __syncthreads();
        if (ch + 2 < 16) load_chunk(buf, ch + 2);
    }

    // epilogue: blend 0.05*h + 0.95*acc, skip padded v rows
    #pragma unroll
    for (int mi = 0; mi < 4; mi++) {
        int v0 = vtile*128 + m_off + mi*16 + gid;
        #pragma unroll
        for (int ni = 0; ni < 4; ni++) {
            int col = nbase + n_off + ni*8 + tig*2;
            float* cc = c[mi*4+ni];
            #pragma unroll
            for (int half = 0; half < 2; half++) {
                int v = v0 + half*8;
                if (v < NV) {
                    size_t off = (size_t)v*NMCOL + col;
                    float2 hb = *(const float2*)&g_h[off];
                    float2 o;
                    o.x = fmaf(0.95f, cc[half*2+0], 0.05f*hb.x);
                    o.y = fmaf(0.95f, cc[half*2+1], 0.05f*hb.y);
                    *(float2*)&Hout[off] = o;
                }
            }
        }
    }
}

// ---------------- combine + stats ----------------
#define COMB_SMEM ((4*5*32*56 + 5*1024 + 32)*4)
__global__ __launch_bounds__(256) void combine_kernel(const float* __restrict__ x,
                                                      const float* __restrict__ gc1w,
                                                      const float* __restrict__ gc1b,
                                                      const float* __restrict__ gc2w,
                                                      const float* __restrict__ gc2b)
{
    extern __shared__ __align__(16) float sm2[];
    float* ts = sm2;
    float* ws = sm2 + 4*5*32*56;
    float* bs = ws + 5*1024;
    int tid = threadIdx.x;
    int v = blockIdx.x, bg = blockIdx.y;

    for (int e = tid; e < 1024; e += 256) {
        int cp = e >> 5, cch = e & 31;
        ws[0*1024 + cp*32 + cch] = gc1w[cch*96 + cp] + gc2w[cch*96 + cp];
        ws[1*1024 + cp*32 + cch] = gc1w[cch*96 + 32 + cp];
        ws[2*1024 + cp*32 + cch] = gc1w[cch*96 + 64 + cp];
        ws[3*1024 + cp*32 + cch] = gc2w[cch*96 + 32 + cp];
        ws[4*1024 + cp*32 + cch] = gc2w[cch*96 + 64 + cp];
    }
    if (tid < 32) bs[tid] = gc1b[tid] + gc2b[tid];

    #pragma unroll
    for (int t = 0; t < 5; t++) {
        const float* src = (t==0)?g_h:(t==1)?g_h1a:(t==2)?g_h2a:(t==3)?g_h1b:g_h2b;
        for (int lin = tid; lin < 4*32*13; lin += 256) {
            int lq = lin % 13;
            int r = lin / 13;
            int cp = r & 31, sub = r >> 5;
            int b = bg*4 + sub;
            float4 val = *(const float4*)&src[(v*NB + b)*HVEC + cp*NK + lq*4];
            *(float4*)&ts[((sub*5 + t)*32 + cp)*56 + lq*4] = val;
        }
    }
    __syncthreads();

    int sub = tid >> 6, cq = (tid >> 3) & 7, lg = tid & 7;
    int b = bg*4 + sub;

    float acc[4][7];
    #pragma unroll
    for (int m = 0; m < 4; m++)
        #pragma unroll
        for (int s = 0; s < 7; s++) acc[m][s] = 0.f;

    const float* tb = &ts[sub*5*32*56];
    for (int cp = 0; cp < 32; cp++) {
        float w0[4], w1[4], w2[4], w3[4], w4[4];
        #pragma unroll
        for (int m = 0; m < 4; m++) {
            int cch = cq + 8*m;
            w0[m] = ws[0*1024 + cp*32 + cch];
            w1[m] = ws[1*1024 + cp*32 + cch];
            w2[m] = ws[2*1024 + cp*32 + cch];
            w3[m] = ws[3*1024 + cp*32 + cch];
            w4[m] = ws[4*1024 + cp*32 + cch];
        }
        #pragma unroll
        for (int s = 0; s < 7; s++) {
            int l = lg + 8*s;
            float v0 = tb[(0*32 + cp)*56 + l];
            float v1 = tb[(1*32 + cp)*56 + l];
            float v2 = tb[(2*32 + cp)*56 + l];
            float v3 = tb[(3*32 + cp)*56 + l];
            float v4 = tb[(4*32 + cp)*56 + l];
            #pragma unroll
            for (int m = 0; m < 4; m++) {
                acc[m][s] = fmaf(w0[m], v0, acc[m][s]);
                acc[m][s] = fmaf(w1[m], v1, acc[m][s]);
                acc[m][s] = fmaf(w2[m], v2, acc[m][s]);
                acc[m][s] = fmaf(w3[m], v3, acc[m][s]);
                acc[m][s] = fmaf(w4[m], v4, acc[m][s]);
            }
        }
    }

    float psum = 0.f, psq = 0.f;
    #pragma unroll
    for (int m = 0; m < 4; m++) {
        int cch = cq + 8*m;
        #pragma unroll
        for (int s = 0; s < 7; s++) {
            int l = lg + 8*s;
            if (l < NK) {
                float val = acc[m][s] + bs[cch] + x[((b*C_R + cch)*NV + v)*NT + 12 + l];
                g_xo[((b*C_C + cch)*NV + v)*NK + l] = val;
                psum += val;
                psq = fmaf(val, val, psq);
            }
        }
    }
    #pragma unroll
    for (int off = 16; off > 0; off >>= 1) {
        psum += __shfl_down_sync(0xffffffffu, psum, off);
        psq  += __shfl_down_sync(0xffffffffu, psq,  off);
    }
    if ((tid & 31) == 0) {
        atomicAdd(&g_stats[2*b], psum);
        atomicAdd(&g_stats[2*b + 1], psq);
    }
}

// ---------------- LayerNorm apply ----------------
__global__ __launch_bounds__(256) void norm_kernel(const int* __restrict__ idx,
                                                   const float* __restrict__ lnw,
                                                   const float* __restrict__ lnb,
                                                   float* __restrict__ out)
{
    int gid = blockIdx.x * 256 + threadIdx.x;
    int lq = gid % 13;
    int row = gid / 13;
    int v = row % NV;
    int cch = (row / NV) % C_C;
    int b = row / (C_C*NV);

    float s1 = g_stats[2*b], s2 = g_stats[2*b + 1];
    float mean = s1 * (1.f/(float)CNT_PER_B);
    float var  = s2 * (1.f/(float)CNT_PER_B) - mean*mean;
    float rstd = rsqrtf(var + 1e-5f);
    int nidx = idx[v];

    float4 xo = *(const float4*)&g_xo[row*NK + lq*4];
    float4 w4 = *(const float4*)&lnw[(cch*NV + nidx)*NK + lq*4];
    float4 b4 = *(const float4*)&lnb[(cch*NV + nidx)*NK + lq*4];
    float4 o;
    o.x = (xo.x - mean)*rstd*w4.x + b4.x;
    o.y = (xo.y - mean)*rstd*w4.y + b4.y;
    o.z = (xo.z - mean)*rstd*w4.z + b4.z;
    o.w = (xo.w - mean)*rstd*w4.w + b4.w;
    *(float4*)&out[row*NK + lq*4] = o;
}

// ---------------- launch ----------------
extern "C" void kernel_launch(void* const* d_in, const int* in_sizes, int n_in,
                              void* d_out, int out_size)
{
    const float* x = (const float*)d_in[0];
    int ia = (in_sizes[1] == NV*NV) ? 1 : 2;
    const float* adp = (const float*)d_in[ia];
    const int*   idx = (const int*)d_in[3 - ia];
    const float* fw2 = (const float*)d_in[3];
    const float* fb2 = (const float*)d_in[4];
    const float* fw3 = (const float*)d_in[5];
    const float* fb3 = (const float*)d_in[6];
    const float* fw6 = (const float*)d_in[7];
    const float* fb6 = (const float*)d_in[8];
    const float* fw7 = (const float*)d_in[9];
    const float* fb7 = (const float*)d_in[10];
    const float* gw2 = (const float*)d_in[11];
    const float* gb2 = (const float*)d_in[12];
    const float* gw3 = (const float*)d_in[13];
    const float* gb3 = (const float*)d_in[14];
    const float* gw6 = (const float*)d_in[15];
    const float* gb6 = (const float*)d_in[16];
    const float* gw7 = (const float*)d_in[17];
    const float* gb7 = (const float*)d_in[18];
    const float* skipw = (const float*)d_in[19];
    const float* skipb = (const float*)d_in[20];
    const float* gc1w = (const float*)d_in[21];
    const float* gc1b = (const float*)d_in[22];
    const float* gc2w = (const float*)d_in[23];
    const float* gc2b = (const float*)d_in[24];
    const float* lnw = (const float*)d_in[25];
    const float* lnb = (const float*)d_in[26];
    float* out = (float*)d_out;
    float* s_out = out + NB*C_C*NV*NK;

    cudaFuncSetAttribute(incept_kernel,  cudaFuncAttributeMaxDynamicSharedMemorySize, INCEPT_SMEM);
    cudaFuncSetAttribute(skip_kernel,    cudaFuncAttributeMaxDynamicSharedMemorySize, SKIP_SMEM);
    cudaFuncSetAttribute(prop_mma,       cudaFuncAttributeMaxDynamicSharedMemorySize, PROP_SMEM);
    cudaFuncSetAttribute(combine_kernel, cudaFuncAttributeMaxDynamicSharedMemorySize, COMB_SMEM);

    pack_kernel<<<1, 256>>>(fw2, fw3, fw6, fw7, fb2, fb3, fb6, fb7,
                            gw2, gw3, gw6, gw7, gb2, gb3, gb6, gb7);
    adj_kernel<<<1024, 256>>>(adp);
    incept_kernel<<<(NV*NB)/4, 256, INCEPT_SMEM>>>(x);
    skip_kernel<<<dim3(63, NB), 256, SKIP_SMEM>>>(skipw, skipb, s_out);
    prop_mma<<<dim3(NMCOL/128, 4, 2), 256, PROP_SMEM>>>(1);
    prop_mma<<<dim3(NMCOL/128, 4, 2), 256, PROP_SMEM>>>(2);
    combine_kernel<<<dim3(NV, 8), 256, COMB_SMEM>>>(x, gc1w, gc1b, gc2w, gc2b);
    norm_kernel<<<26000, 256>>>(idx, lnw, lnb, out);
}

// round 5
// speedup vs baseline: 1.9464x; 1.2251x over previous
#include <cuda_runtime.h>
#include <cuda_fp16.h>
#include <cstdint>

// ---------------- problem constants ----------------
#define NB   32
#define C_R  32
#define C_C  32
#define C_S  64
#define NV   500
#define NT   64
#define NK   52
#define NMCOL (NB*C_C*NK)   // 53248
#define VP   512
#define HVEC (C_C*NK)       // 1664
#define CNT_PER_B (C_C*NV*NK)

// ---------------- device scratch (zero-initialized) ----------------
__device__ __half g_a1h[VP*VP];
__device__ __half g_a2h[VP*VP];
__device__ __half g_swh[C_S*HVEC];
__device__ float  g_Wf[C_C*C_R*7];
__device__ float  g_Wg[C_C*C_R*7];
__device__ float  g_fbias[C_C];
__device__ float  g_gbias[C_C];
// rows (nodes) padded to 512; rows >=500 never written, stay zero
__device__ __half g_hh  [VP*NMCOL];
__device__ __half g_h1ah[VP*NMCOL];
__device__ __half g_h1bh[VP*NMCOL];
__device__ __half g_h2ah[VP*NMCOL];
__device__ __half g_h2bh[VP*NMCOL];
__device__ float  g_xo [NB*C_C*NV*NK];
__device__ float  g_stats[2*NB];

// ---------------- helpers ----------------
__device__ __forceinline__ uint32_t smem_u32(const void* p){
    uint32_t a; asm("{ .reg .u64 t; cvta.to.shared.u64 t, %1; cvt.u32.u64 %0, t; }":"=r"(a):"l"(p)); return a;
}
#define CP_ASYNC16(s,g) asm volatile("cp.async.cg.shared.global [%0], [%1], 16;"::"r"(s),"l"(g))
#define CP_COMMIT()     asm volatile("cp.async.commit_group;" ::: "memory")
#define CP_WAIT1()      asm volatile("cp.async.wait_group 1;" ::: "memory")
#define CP_WAIT0()      asm volatile("cp.async.wait_group 0;" ::: "memory")

__device__ __forceinline__ void ldmx4(uint32_t* r, uint32_t addr){
    asm volatile("ldmatrix.sync.aligned.m8n8.x4.shared.b16 {%0,%1,%2,%3}, [%4];"
        : "=r"(r[0]),"=r"(r[1]),"=r"(r[2]),"=r"(r[3]) : "r"(addr));
}
__device__ __forceinline__ void ldmx4t(uint32_t* r, uint32_t addr){
    asm volatile("ldmatrix.sync.aligned.m8n8.x4.trans.shared.b16 {%0,%1,%2,%3}, [%4];"
        : "=r"(r[0]),"=r"(r[1]),"=r"(r[2]),"=r"(r[3]) : "r"(addr));
}
__device__ __forceinline__ void mma_f16(float* c, const uint32_t* a, const uint32_t* b){
    asm volatile("mma.sync.aligned.m16n8k16.row.col.f32.f16.f16.f32 "
        "{%0,%1,%2,%3}, {%4,%5,%6,%7}, {%8,%9}, {%0,%1,%2,%3};"
        : "+f"(c[0]),"+f"(c[1]),"+f"(c[2]),"+f"(c[3])
        : "r"(a[0]),"r"(a[1]),"r"(a[2]),"r"(a[3]), "r"(b[0]),"r"(b[1]));
}

// ---------------- pack: unified 7-tap weights, half skip weights, zero stats ----------------
__global__ void pack_kernel(const float* __restrict__ fw2,const float* __restrict__ fw3,
    const float* __restrict__ fw6,const float* __restrict__ fw7,
    const float* __restrict__ fb2,const float* __restrict__ fb3,
    const float* __restrict__ fb6,const float* __restrict__ fb7,
    const float* __restrict__ gw2,const float* __restrict__ gw3,
    const float* __restrict__ gw6,const float* __restrict__ gw7,
    const float* __restrict__ gb2,const float* __restrict__ gb3,
    const float* __restrict__ gb6,const float* __restrict__ gb7,
    const float* __restrict__ skipw)
{
    int tid = threadIdx.x;
    if (tid < 2*NB) g_stats[tid] = 0.f;
    for (int e = tid; e < C_C*C_R*7; e += blockDim.x) {
        int j = e % 7, i = (e/7) % C_R, o = e/(7*C_R);
        int br = o >> 3, oo = o & 7;
        int k = (br==0)?2:(br==1)?3:(br==2)?6:7;
        int j0 = 7 - k;
        float vf = 0.f, vg = 0.f;
        if (j >= j0) {
            int si = (oo*C_R + i)*k + (j - j0);
            const float* fw = (br==0)?fw2:(br==1)?fw3:(br==2)?fw6:fw7;
            const float* gw = (br==0)?gw2:(br==1)?gw3:(br==2)?gw6:gw7;
            vf = fw[si]; vg = gw[si];
        }
        g_Wf[e] = vf; g_Wg[e] = vg;
    }
    if (tid < C_C) {
        int br = tid >> 3, oo = tid & 7;
        const float* fb = (br==0)?fb2:(br==1)?fb3:(br==2)?fb6:fb7;
        const float* gb = (br==0)?gb2:(br==1)?gb3:(br==2)?gb6:gb7;
        g_fbias[tid] = fb[oo]; g_gbias[tid] = gb[oo];
    }
    for (int e = tid; e < C_S*HVEC; e += blockDim.x)
        g_swh[e] = __float2half_rn(skipw[e]);
}

// ---------------- normalized adjacencies -> fp16, padded to 512x512 ----------------
__global__ void adj_kernel(const float* __restrict__ adp)
{
    int v = blockIdx.x & 511;
    int which = blockIdx.x >> 9;
    __half* dst = which ? g_a2h : g_a1h;
    if (v >= NV) {
        for (int w = threadIdx.x; w < VP; w += 256) dst[v*VP + w] = __float2half_rn(0.f);
        return;
    }
    __shared__ float red[256];
    float s = 0.f;
    for (int w = threadIdx.x; w < NV; w += 256)
        s += which ? adp[w*NV + v] : adp[v*NV + w];
    red[threadIdx.x] = s; __syncthreads();
    for (int st = 128; st > 0; st >>= 1) {
        if (threadIdx.x < st) red[threadIdx.x] += red[threadIdx.x + st];
        __syncthreads();
    }
    float inv = 1.f / (red[0] + 1.f);
    for (int w = threadIdx.x; w < VP; w += 256) {
        float val = 0.f;
        if (w < NV) {
            val = which ? adp[w*NV + v] : adp[v*NV + w];
            if (w == v) val += 1.f;
            val *= inv;
        }
        dst[v*VP + w] = __float2half_rn(val);
    }
}

// ---------------- fused dilated inception + gating -> fp16 h ----------------
#define INCEPT_SMEM ((4*32*72 + 2*7168 + 64)*4)
__global__ __launch_bounds__(256) void incept_kernel(const float* __restrict__ x)
{
    extern __shared__ __align__(16) float sm[];
    float* xs = sm;
    float* Wfs = xs + 4*32*72;
    float* Wgs = Wfs + 7168;
    float* fbs = Wgs + 7168;
    float* gbs = fbs + 32;
    int tid = threadIdx.x;
    for (int e = tid; e < 7168; e += 256) { Wfs[e] = g_Wf[e]; Wgs[e] = g_Wg[e]; }
    if (tid < 32) { fbs[tid] = g_fbias[tid]; gbs[tid] = g_gbias[tid]; }
    int p0 = blockIdx.x * 4;
    #pragma unroll
    for (int it = 0; it < 8; it++) {
        int lin = tid + it*256;
        int sub = lin >> 9, rem = lin & 511;
        int i = rem >> 4, tq = rem & 15;
        int p = p0 + sub, n = p >> 5, b = p & 31;
        float4 v = *(const float4*)&x[((b*C_R + i)*NV + n)*NT + tq*4];
        *(float4*)&xs[(sub*32 + i)*72 + tq*4] = v;
    }
    __syncthreads();
    int sub = tid >> 6, oq = (tid >> 3) & 7, tg = tid & 7;
    float accf[4][7], accg[4][7];
    #pragma unroll
    for (int m = 0; m < 4; m++)
        #pragma unroll
        for (int s = 0; s < 7; s++) { accf[m][s] = 0.f; accg[m][s] = 0.f; }
    const float* xb = &xs[sub*32*72];
    for (int i = 0; i < 32; i++) {
        const float* xr = xb + i*72;
        #pragma unroll
        for (int j = 0; j < 7; j++) {
            float xv[7];
            #pragma unroll
            for (int s = 0; s < 7; s++) xv[s] = xr[tg + 8*s + 2*j];
            #pragma unroll
            for (int m = 0; m < 4; m++) {
                float wf = Wfs[(oq + 8*m)*224 + i*7 + j];
                float wg = Wgs[(oq + 8*m)*224 + i*7 + j];
                #pragma unroll
                for (int s = 0; s < 7; s++) {
                    accf[m][s] = fmaf(xv[s], wf, accf[m][s]);
                    accg[m][s] = fmaf(xv[s], wg, accg[m][s]);
                }
            }
        }
    }
    int p = p0 + sub, n = p >> 5, b = p & 31;
    __half* hout = &g_hh[(size_t)(n*NB + b)*HVEC];
    #pragma unroll
    for (int m = 0; m < 4; m++) {
        int o = oq + 8*m;
        #pragma unroll
        for (int s = 0; s < 7; s++) {
            int t = tg + 8*s;
            if (t < NK) {
                float f = tanhf(accf[m][s] + fbs[o]);
                float gz = accg[m][s] + gbs[o];
                hout[o*NK + t] = __float2half_rn(f / (1.f + __expf(-gz)));
            }
        }
    }
}

// ---------------- skip conv as per-node HMMA GEMM: D[cs][b] = W @ h_n ----------------
// W: [64][1664] half row-major (k contig). h_n: [b][k] (k contig) == col-major B. Zero transposes.
#define SK_WSTR 136
#define SK_WBYTES (64*272)     // 17408
#define SK_BBYTES (32*272)     // 8704
#define SK_BUF (SK_WBYTES + SK_BBYTES)
#define SKIP_SMEM (2*SK_BUF)
__global__ __launch_bounds__(128) void skip_mma(const float* __restrict__ skipb,
                                                float* __restrict__ sout)
{
    extern __shared__ __align__(16) char sks[];
    int n = blockIdx.x;
    int tid = threadIdx.x, warp = tid >> 5, lane = tid & 31;
    int m0 = warp * 16;
    uint32_t sb = smem_u32(sks);

    const __half* Bg = &g_hh[(size_t)n*NMCOL];

    float c[4][4];
    #pragma unroll
    for (int i = 0; i < 4; i++)
        #pragma unroll
        for (int j = 0; j < 4; j++) c[i][j] = 0.f;

    auto load_chunk = [&](int buf, int ch) {
        int k0 = ch * 128;
        uint32_t sW = sb + buf*SK_BUF;
        uint32_t sB = sW + SK_WBYTES;
        #pragma unroll
        for (int j = 0; j < 8; j++) {
            int lin = tid + j*128;
            int r = lin >> 4, q = lin & 15;
            CP_ASYNC16(sW + r*272 + q*16, &g_swh[r*HVEC + k0 + q*8]);
        }
        #pragma unroll
        for (int j = 0; j < 4; j++) {
            int lin = tid + j*128;
            int r = lin >> 4, q = lin & 15;
            CP_ASYNC16(sB + r*272 + q*16, &Bg[r*HVEC + k0 + q*8]);
        }
        CP_COMMIT();
    };

    load_chunk(0, 0);
    load_chunk(1, 1);

    for (int ch = 0; ch < 13; ch++) {
        if (ch == 12) { CP_WAIT0(); } else { CP_WAIT1(); }
        __syncthreads();
        int buf = ch & 1;
        uint32_t sW = sb + buf*SK_BUF;
        uint32_t sB = sW + SK_WBYTES;
        #pragma unroll
        for (int ks = 0; ks < 8; ks++) {
            int k0 = ks * 16;
            uint32_t a[4];
            ldmx4(a, sW + (m0 + (lane & 15))*272 + (k0 + (lane >> 4)*8)*2);
            uint32_t bfr[2][4];
            #pragma unroll
            for (int np = 0; np < 2; np++)
                ldmx4(bfr[np], sB + (np*16 + (lane & 7) + ((lane >> 4) << 3))*272
                               + (k0 + ((lane >> 3) & 1)*8)*2);
            #pragma unroll
            for (int ni = 0; ni < 4; ni++)
                mma_f16(c[ni], a, &bfr[ni >> 1][(ni & 1)*2]);
        }
        __syncthreads();
        if (ch + 2 < 13) load_chunk(buf, ch + 2);
    }

    int gr = lane >> 2, qc = (lane & 3)*2;
    #pragma unroll
    for (int ni = 0; ni < 4; ni++) {
        int b0 = ni*8 + qc;
        int cs0 = m0 + gr;
        float bi0 = skipb[cs0], bi1 = skipb[cs0 + 8];
        sout[(b0*C_S + cs0)*NV + n]       = c[ni][0] + bi0;
        sout[((b0+1)*C_S + cs0)*NV + n]   = c[ni][1] + bi0;
        sout[(b0*C_S + cs0+8)*NV + n]     = c[ni][2] + bi1;
        sout[((b0+1)*C_S + cs0+8)*NV + n] = c[ni][3] + bi1;
    }
}

// ---------------- fp16 HMMA prop: Hout = 0.05*h + 0.95*(Adj @ Hin) ----------------
#define PA_BYTES (128*80)      // A tile 128 x 32 halfs, row stride 80B
#define PB_BYTES (32*272)      // B tile 32 x 128 halfs, row stride 272B
#define PBUF (PA_BYTES + PB_BYTES)
#define PROP_SMEM (2*PBUF)
__global__ __launch_bounds__(256,2) void prop_mma(int step)
{
    extern __shared__ __align__(16) char smp[];
    const __half* Aadj; const __half* Bin; __half* Hout;
    if (blockIdx.z == 0) { Aadj = g_a1h; Bin = (step==1) ? g_hh : g_h1ah; Hout = (step==1) ? g_h1ah : g_h2ah; }
    else                 { Aadj = g_a2h; Bin = (step==1) ? g_hh : g_h1bh; Hout = (step==1) ? g_h1bh : g_h2bh; }

    int tid = threadIdx.x, warp = tid >> 5, lane = tid & 31;
    int nbase = blockIdx.x * 128;
    int vt = blockIdx.y;
    int wm = (warp >> 2)*64, wn = (warp & 3)*32;
    uint32_t sb = smem_u32(smp);

    float c[4][4][4];
    #pragma unroll
    for (int i = 0; i < 4; i++)
        #pragma unroll
        for (int j = 0; j < 4; j++)
            #pragma unroll
            for (int q = 0; q < 4; q++) c[i][j][q] = 0.f;

    auto load_chunk = [&](int buf, int ch) {
        int w0 = ch * 32;
        uint32_t sA = sb + buf*PBUF;
        uint32_t sB = sA + PA_BYTES;
        #pragma unroll
        for (int j = 0; j < 2; j++) {
            int lin = tid + j*256;
            int r = lin >> 2, q = lin & 3;
            CP_ASYNC16(sA + r*80 + q*16, &Aadj[(vt*128 + r)*VP + w0 + q*8]);
        }
        #pragma unroll
        for (int j = 0; j < 2; j++) {
            int lin = tid + j*256;
            int r = lin >> 4, q = lin & 15;
            CP_ASYNC16(sB + r*272 + q*16, &Bin[(size_t)(w0 + r)*NMCOL + nbase + q*8]);
        }
        CP_COMMIT();
    };

    load_chunk(0, 0);
    load_chunk(1, 1);

    for (int ch = 0; ch < 16; ch++) {
        if (ch == 15) { CP_WAIT0(); } else { CP_WAIT1(); }
        __syncthreads();
        int buf = ch & 1;
        uint32_t sA = sb + buf*PBUF;
        uint32_t sB = sA + PA_BYTES;
        #pragma unroll
        for (int ks = 0; ks < 2; ks++) {
            int k0 = ks * 16;
            uint32_t a[4][4];
            #pragma unroll
            for (int mi = 0; mi < 4; mi++)
                ldmx4(a[mi], sA + (wm + mi*16 + (lane & 15))*80 + (k0 + (lane >> 4)*8)*2);
            uint32_t bfr[2][4];
            #pragma unroll
            for (int np = 0; np < 2; np++)
                ldmx4t(bfr[np], sB + (k0 + (lane & 15))*272 + (wn + np*16 + (lane >> 4)*8)*2);
            #pragma unroll
            for (int mi = 0; mi < 4; mi++)
                #pragma unroll
                for (int ni = 0; ni < 4; ni++)
                    mma_f16(c[mi][ni], a[mi], &bfr[ni >> 1][(ni & 1)*2]);
        }
        __syncthreads();
        if (ch + 2 < 16) load_chunk(buf, ch + 2);
    }

    // epilogue: Hout = 0.05*h + 0.95*acc (fp16 out), skip padded v rows
    int gr = lane >> 2, qc = (lane & 3)*2;
    #pragma unroll
    for (int mi = 0; mi < 4; mi++) {
        #pragma unroll
        for (int half = 0; half < 2; half++) {
            int v = vt*128 + wm + mi*16 + gr + half*8;
            if (v < NV) {
                #pragma unroll
                for (int ni = 0; ni < 4; ni++) {
                    size_t off = (size_t)v*NMCOL + nbase + wn + ni*8 + qc;
                    float2 hb = __half22float2(*(const __half2*)&g_hh[off]);
                    float o0 = fmaf(0.95f, c[mi][ni][half*2+0], 0.05f*hb.x);
                    float o1 = fmaf(0.95f, c[mi][ni][half*2+1], 0.05f*hb.y);
                    *(__half2*)&Hout[off] = __floats2half2_rn(o0, o1);
                }
            }
        }
    }
}

// ---------------- combine (reads fp16 tensors) + stats ----------------
#define COMB_SMEM ((4*5*32*56 + 5*1024 + 32)*4)
__global__ __launch_bounds__(256) void combine_kernel(const float* __restrict__ x,
                                                      const float* __restrict__ gc1w,
                                                      const float* __restrict__ gc1b,
                                                      const float* __restrict__ gc2w,
                                                      const float* __restrict__ gc2b)
{
    extern __shared__ __align__(16) float sm2[];
    float* ts = sm2;
    float* ws = sm2 + 4*5*32*56;
    float* bs = ws + 5*1024;
    int tid = threadIdx.x;
    int v = blockIdx.x, bg = blockIdx.y;

    for (int e = tid; e < 1024; e += 256) {
        int cp = e >> 5, cch = e & 31;
        ws[0*1024 + cp*32 + cch] = gc1w[cch*96 + cp] + gc2w[cch*96 + cp];
        ws[1*1024 + cp*32 + cch] = gc1w[cch*96 + 32 + cp];
        ws[2*1024 + cp*32 + cch] = gc1w[cch*96 + 64 + cp];
        ws[3*1024 + cp*32 + cch] = gc2w[cch*96 + 32 + cp];
        ws[4*1024 + cp*32 + cch] = gc2w[cch*96 + 64 + cp];
    }
    if (tid < 32) bs[tid] = gc1b[tid] + gc2b[tid];

    #pragma unroll
    for (int t = 0; t < 5; t++) {
        const __half* src = (t==0)?g_hh:(t==1)?g_h1ah:(t==2)?g_h2ah:(t==3)?g_h1bh:g_h2bh;
        for (int lin = tid; lin < 4*32*13; lin += 256) {
            int lq = lin % 13;
            int r = lin / 13;
            int cp = r & 31, sub = r >> 5;
            int b = bg*4 + sub;
            uint2 raw = *(const uint2*)&src[(size_t)(v*NB + b)*HVEC + cp*NK + lq*4];
            float2 f0 = __half22float2(*(__half2*)&raw.x);
            float2 f1 = __half22float2(*(__half2*)&raw.y);
            *(float4*)&ts[((sub*5 + t)*32 + cp)*56 + lq*4] = make_float4(f0.x, f0.y, f1.x, f1.y);
        }
    }
    __syncthreads();

    int sub = tid >> 6, cq = (tid >> 3) & 7, lg = tid & 7;
    int b = bg*4 + sub;

    float acc[4][7];
    #pragma unroll
    for (int m = 0; m < 4; m++)
        #pragma unroll
        for (int s = 0; s < 7; s++) acc[m][s] = 0.f;

    const float* tb = &ts[sub*5*32*56];
    for (int cp = 0; cp < 32; cp++) {
        float w0[4], w1[4], w2[4], w3[4], w4[4];
        #pragma unroll
        for (int m = 0; m < 4; m++) {
            int cch = cq + 8*m;
            w0[m] = ws[0*1024 + cp*32 + cch];
            w1[m] = ws[1*1024 + cp*32 + cch];
            w2[m] = ws[2*1024 + cp*32 + cch];
            w3[m] = ws[3*1024 + cp*32 + cch];
            w4[m] = ws[4*1024 + cp*32 + cch];
        }
        #pragma unroll
        for (int s = 0; s < 7; s++) {
            int l = lg + 8*s;
            float v0 = tb[(0*32 + cp)*56 + l];
            float v1 = tb[(1*32 + cp)*56 + l];
            float v2 = tb[(2*32 + cp)*56 + l];
            float v3 = tb[(3*32 + cp)*56 + l];
            float v4 = tb[(4*32 + cp)*56 + l];
            #pragma unroll
            for (int m = 0; m < 4; m++) {
                acc[m][s] = fmaf(w0[m], v0, acc[m][s]);
                acc[m][s] = fmaf(w1[m], v1, acc[m][s]);
                acc[m][s] = fmaf(w2[m], v2, acc[m][s]);
                acc[m][s] = fmaf(w3[m], v3, acc[m][s]);
                acc[m][s] = fmaf(w4[m], v4, acc[m][s]);
            }
        }
    }

    float psum = 0.f, psq = 0.f;
    #pragma unroll
    for (int m = 0; m < 4; m++) {
        int cch = cq + 8*m;
        #pragma unroll
        for (int s = 0; s < 7; s++) {
            int l = lg + 8*s;
            if (l < NK) {
                float val = acc[m][s] + bs[cch] + x[((b*C_R + cch)*NV + v)*NT + 12 + l];
                g_xo[((b*C_C + cch)*NV + v)*NK + l] = val;
                psum += val;
                psq = fmaf(val, val, psq);
            }
        }
    }
    #pragma unroll
    for (int off = 16; off > 0; off >>= 1) {
        psum += __shfl_down_sync(0xffffffffu, psum, off);
        psq  += __shfl_down_sync(0xffffffffu, psq,  off);
    }
    if ((tid & 31) == 0) {
        atomicAdd(&g_stats[2*b], psum);
        atomicAdd(&g_stats[2*b + 1], psq);
    }
}

// ---------------- LayerNorm apply ----------------
__global__ __launch_bounds__(256) void norm_kernel(const int* __restrict__ idx,
                                                   const float* __restrict__ lnw,
                                                   const float* __restrict__ lnb,
                                                   float* __restrict__ out)
{
    int gid = blockIdx.x * 256 + threadIdx.x;
    int lq = gid % 13;
    int row = gid / 13;
    int v = row % NV;
    int cch = (row / NV) % C_C;
    int b = row / (C_C*NV);

    float s1 = g_stats[2*b], s2 = g_stats[2*b + 1];
    float mean = s1 * (1.f/(float)CNT_PER_B);
    float var  = s2 * (1.f/(float)CNT_PER_B) - mean*mean;
    float rstd = rsqrtf(var + 1e-5f);
    int nidx = idx[v];

    float4 xo = *(const float4*)&g_xo[row*NK + lq*4];
    float4 w4 = *(const float4*)&lnw[(cch*NV + nidx)*NK + lq*4];
    float4 b4 = *(const float4*)&lnb[(cch*NV + nidx)*NK + lq*4];
    float4 o;
    o.x = (xo.x - mean)*rstd*w4.x + b4.x;
    o.y = (xo.y - mean)*rstd*w4.y + b4.y;
    o.z = (xo.z - mean)*rstd*w4.z + b4.z;
    o.w = (xo.w - mean)*rstd*w4.w + b4.w;
    *(float4*)&out[row*NK + lq*4] = o;
}

// ---------------- launch ----------------
extern "C" void kernel_launch(void* const* d_in, const int* in_sizes, int n_in,
                              void* d_out, int out_size)
{
    const float* x = (const float*)d_in[0];
    int ia = (in_sizes[1] == NV*NV) ? 1 : 2;
    const float* adp = (const float*)d_in[ia];
    const int*   idx = (const int*)d_in[3 - ia];
    const float* fw2 = (const float*)d_in[3];
    const float* fb2 = (const float*)d_in[4];
    const float* fw3 = (const float*)d_in[5];
    const float* fb3 = (const float*)d_in[6];
    const float* fw6 = (const float*)d_in[7];
    const float* fb6 = (const float*)d_in[8];
    const float* fw7 = (const float*)d_in[9];
    const float* fb7 = (const float*)d_in[10];
    const float* gw2 = (const float*)d_in[11];
    const float* gb2 = (const float*)d_in[12];
    const float* gw3 = (const float*)d_in[13];
    const float* gb3 = (const float*)d_in[14];
    const float* gw6 = (const float*)d_in[15];
    const float* gb6 = (const float*)d_in[16];
    const float* gw7 = (const float*)d_in[17];
    const float* gb7 = (const float*)d_in[18];
    const float* skipw = (const float*)d_in[19];
    const float* skipb = (const float*)d_in[20];
    const float* gc1w = (const float*)d_in[21];
    const float* gc1b = (const float*)d_in[22];
    const float* gc2w = (const float*)d_in[23];
    const float* gc2b = (const float*)d_in[24];
    const float* lnw = (const float*)d_in[25];
    const float* lnb = (const float*)d_in[26];
    float* out = (float*)d_out;
    float* s_out = out + NB*C_C*NV*NK;

    cudaFuncSetAttribute(incept_kernel,  cudaFuncAttributeMaxDynamicSharedMemorySize, INCEPT_SMEM);
    cudaFuncSetAttribute(skip_mma,       cudaFuncAttributeMaxDynamicSharedMemorySize, SKIP_SMEM);
    cudaFuncSetAttribute(prop_mma,       cudaFuncAttributeMaxDynamicSharedMemorySize, PROP_SMEM);
    cudaFuncSetAttribute(combine_kernel, cudaFuncAttributeMaxDynamicSharedMemorySize, COMB_SMEM);

    pack_kernel<<<1, 256>>>(fw2, fw3, fw6, fw7, fb2, fb3, fb6, fb7,
                            gw2, gw3, gw6, gw7, gb2, gb3, gb6, gb7, skipw);
    adj_kernel<<<1024, 256>>>(adp);
    incept_kernel<<<(NV*NB)/4, 256, INCEPT_SMEM>>>(x);
    skip_mma<<<NV, 128, SKIP_SMEM>>>(skipb, s_out);
    prop_mma<<<dim3(NMCOL/128, 4, 2), 256, PROP_SMEM>>>(1);
    prop_mma<<<dim3(NMCOL/128, 4, 2), 256, PROP_SMEM>>>(2);
    combine_kernel<<<dim3(NV, 8), 256, COMB_SMEM>>>(x, gc1w, gc1b, gc2w, gc2b);
    norm_kernel<<<26000, 256>>>(idx, lnw, lnb, out);
}

// round 6
// speedup vs baseline: 3.0087x; 1.5458x over previous
#include <cuda_runtime.h>
#include <cuda_fp16.h>
#include <cstdint>

// ---------------- problem constants ----------------
#define NB   32
#define C_R  32
#define C_C  32
#define C_S  64
#define NV   500
#define NT   64
#define NK   52
#define NMCOL (NB*C_C*NK)   // 53248
#define VP   512
#define HVEC (C_C*NK)       // 1664
#define CNT_PER_B (C_C*NV*NK)

// ---------------- device scratch (zero-initialized) ----------------
__device__ __half g_a1h[VP*VP];
__device__ __half g_a2h[VP*VP];
__device__ __half g_swh[C_S*HVEC];
__device__ __half g_Wph[7*64*32];     // packed inception weights [j][o(f0-31,g32-63)][i]
__device__ float  g_fbias[C_C];
__device__ float  g_gbias[C_C];
// rows (nodes) padded to 512; rows >=500 never written, stay zero
__device__ __half g_hh  [VP*NMCOL];
__device__ __half g_h1ah[VP*NMCOL];
__device__ __half g_h1bh[VP*NMCOL];
__device__ __half g_h2ah[VP*NMCOL];
__device__ __half g_h2bh[VP*NMCOL];
__device__ float  g_xo [NB*C_C*NV*NK];
__device__ float  g_stats[2*NB];

// ---------------- helpers ----------------
__device__ __forceinline__ uint32_t smem_u32(const void* p){
    uint32_t a; asm("{ .reg .u64 t; cvta.to.shared.u64 t, %1; cvt.u32.u64 %0, t; }":"=r"(a):"l"(p)); return a;
}
#define CP_ASYNC16(s,g) asm volatile("cp.async.cg.shared.global [%0], [%1], 16;"::"r"(s),"l"(g))
#define CP_COMMIT()     asm volatile("cp.async.commit_group;" ::: "memory")
#define CP_WAIT1()      asm volatile("cp.async.wait_group 1;" ::: "memory")
#define CP_WAIT0()      asm volatile("cp.async.wait_group 0;" ::: "memory")

__device__ __forceinline__ void ldmx4(uint32_t* r, uint32_t addr){
    asm volatile("ldmatrix.sync.aligned.m8n8.x4.shared.b16 {%0,%1,%2,%3}, [%4];"
        : "=r"(r[0]),"=r"(r[1]),"=r"(r[2]),"=r"(r[3]) : "r"(addr));
}
__device__ __forceinline__ void ldmx4t(uint32_t* r, uint32_t addr){
    asm volatile("ldmatrix.sync.aligned.m8n8.x4.trans.shared.b16 {%0,%1,%2,%3}, [%4];"
        : "=r"(r[0]),"=r"(r[1]),"=r"(r[2]),"=r"(r[3]) : "r"(addr));
}
__device__ __forceinline__ void mma_f16(float* c, const uint32_t* a, const uint32_t* b){
    asm volatile("mma.sync.aligned.m16n8k16.row.col.f32.f16.f16.f32 "
        "{%0,%1,%2,%3}, {%4,%5,%6,%7}, {%8,%9}, {%0,%1,%2,%3};"
        : "+f"(c[0]),"+f"(c[1]),"+f"(c[2]),"+f"(c[3])
        : "r"(a[0]),"r"(a[1]),"r"(a[2]),"r"(a[3]), "r"(b[0]),"r"(b[1]));
}

// ---------------- pack: fp16 inception weights [j][o][i], half skip weights, stats ----------------
__global__ void pack_kernel(const float* __restrict__ fw2,const float* __restrict__ fw3,
    const float* __restrict__ fw6,const float* __restrict__ fw7,
    const float* __restrict__ fb2,const float* __restrict__ fb3,
    const float* __restrict__ fb6,const float* __restrict__ fb7,
    const float* __restrict__ gw2,const float* __restrict__ gw3,
    const float* __restrict__ gw6,const float* __restrict__ gw7,
    const float* __restrict__ gb2,const float* __restrict__ gb3,
    const float* __restrict__ gb6,const float* __restrict__ gb7,
    const float* __restrict__ skipw)
{
    int tid = threadIdx.x;
    int gtid = blockIdx.x * blockDim.x + tid;
    // skip weights -> half (grid-wide)
    for (int e = gtid; e < C_S*HVEC; e += gridDim.x * blockDim.x)
        g_swh[e] = __float2half_rn(skipw[e]);
    if (blockIdx.x != 0) return;
    if (tid < 2*NB) g_stats[tid] = 0.f;
    // packed unified 7-tap weights: Wp[j][o][i]; o<32 from f-branches, o>=32 from g
    for (int e = tid; e < 7*64*32; e += blockDim.x) {
        int j = e / 2048;
        int o = (e & 2047) >> 5;
        int i = e & 31;
        int oc = o & 31;
        int br = oc >> 3, oo = oc & 7;
        int k = (br==0)?2:(br==1)?3:(br==2)?6:7;
        int j0 = 7 - k;
        float vv = 0.f;
        if (j >= j0) {
            int si = (oo*C_R + i)*k + (j - j0);
            if (o < 32) {
                const float* fw = (br==0)?fw2:(br==1)?fw3:(br==2)?fw6:fw7;
                vv = fw[si];
            } else {
                const float* gw = (br==0)?gw2:(br==1)?gw3:(br==2)?gw6:gw7;
                vv = gw[si];
            }
        }
        g_Wph[e] = __float2half_rn(vv);
    }
    if (tid < C_C) {
        int br = tid >> 3, oo = tid & 7;
        const float* fb = (br==0)?fb2:(br==1)?fb3:(br==2)?fb6:fb7;
        const float* gb = (br==0)?gb2:(br==1)?gb3:(br==2)?gb6:gb7;
        g_fbias[tid] = fb[oo]; g_gbias[tid] = gb[oo];
    }
}

// ---------------- normalized adjacencies -> fp16, padded to 512x512 ----------------
__global__ void adj_kernel(const float* __restrict__ adp)
{
    int v = blockIdx.x & 511;
    int which = blockIdx.x >> 9;
    __half* dst = which ? g_a2h : g_a1h;
    if (v >= NV) {
        for (int w = threadIdx.x; w < VP; w += 256) dst[v*VP + w] = __float2half_rn(0.f);
        return;
    }
    __shared__ float red[256];
    float s = 0.f;
    for (int w = threadIdx.x; w < NV; w += 256)
        s += which ? adp[w*NV + v] : adp[v*NV + w];
    red[threadIdx.x] = s; __syncthreads();
    for (int st = 128; st > 0; st >>= 1) {
        if (threadIdx.x < st) red[threadIdx.x] += red[threadIdx.x + st];
        __syncthreads();
    }
    float inv = 1.f / (red[0] + 1.f);
    for (int w = threadIdx.x; w < VP; w += 256) {
        float val = 0.f;
        if (w < NV) {
            val = which ? adp[w*NV + v] : adp[v*NV + w];
            if (w == v) val += 1.f;
            val *= inv;
        }
        dst[v*VP + w] = __float2half_rn(val);
    }
}

// ---------------- HMMA dilated inception + gating -> fp16 h ----------------
// One warp per (n,b) pair. D[o64][t56] = sum_j Wp[j] @ xst[t+2j][i], f/g stacked in o.
// xst rows padded: 80 rows x 40 halfs (80B stride, conflict-free for ldmatrix).
#define XST_ROWS 80
#define XST_STRB 80                       // bytes per row
#define XST_WARP (XST_ROWS*XST_STRB)      // 6400 B per warp
#define WP_STRB 80
#define WP_BYTES (7*64*WP_STRB)           // 35840 B
#define INCEPT_SMEM (WP_BYTES + 8*XST_WARP + 512)
__global__ __launch_bounds__(256,1) void incept_mma(const float* __restrict__ x)
{
    extern __shared__ __align__(16) char smi[];
    uint32_t sW = smem_u32(smi);                  // Wp: 7*64 rows, 80B stride
    uint32_t sX0 = sW + WP_BYTES;                 // per-warp xst
    float* fbs = (float*)(smi + WP_BYTES + 8*XST_WARP);
    float* gbs = fbs + 32;

    int tid = threadIdx.x, warp = tid >> 5, lane = tid & 31;

    // stage weights (strided 32->40 halfs)
    for (int e = tid; e < 7*64*32; e += 256) {
        int row = e >> 5, i = e & 31;
        *(__half*)(smi + row*WP_STRB + i*2) = g_Wph[e];
    }
    if (tid < 32) { fbs[tid] = g_fbias[tid]; gbs[tid] = g_gbias[tid]; }

    // stage x transposed: xst[t][i] fp16
    int p = blockIdx.x * 8 + warp;                // (n,b) pair
    int n = p >> 5, b = p & 31;
    uint32_t sX = sX0 + warp*XST_WARP;
    {
        int i0 = (lane & 15) * 2;
        int t0 = (lane >> 4) * 32;
        const float* xr0 = &x[((size_t)(b*C_R + i0)*NV + n)*NT + t0];
        const float* xr1 = xr0 + (size_t)NV*NT;
        #pragma unroll
        for (int q = 0; q < 8; q++) {
            float4 v0 = *(const float4*)&xr0[q*4];
            float4 v1 = *(const float4*)&xr1[q*4];
            const float* a0 = &v0.x; const float* a1 = &v1.x;
            #pragma unroll
            for (int r = 0; r < 4; r++) {
                int t = t0 + q*4 + r;
                *(__half2*)(smi + (sX - smem_u32(smi)) + t*XST_STRB + i0*2) =
                    __floats2half2_rn(a0[r], a1[r]);
            }
        }
    }
    __syncthreads();

    float c[4][7][4];
    #pragma unroll
    for (int mi = 0; mi < 4; mi++)
        #pragma unroll
        for (int nt = 0; nt < 7; nt++)
            #pragma unroll
            for (int q = 0; q < 4; q++) c[mi][nt][q] = 0.f;

    #pragma unroll
    for (int j = 0; j < 7; j++) {
        uint32_t wbase = sW + j*64*WP_STRB;
        #pragma unroll
        for (int kst = 0; kst < 2; kst++) {
            int kb = (kst*16 + (lane >> 4)*8) * 2;
            uint32_t a[4][4];
            #pragma unroll
            for (int mi = 0; mi < 4; mi++)
                ldmx4(a[mi], wbase + (mi*16 + (lane & 15))*WP_STRB + kb);
            uint32_t bf[4][4];
            int kbb = (kst*16 + ((lane >> 3) & 1)*8) * 2;
            #pragma unroll
            for (int nb8 = 0; nb8 < 4; nb8++) {
                int trow = nb8*16 + (lane & 7) + ((lane >> 4) << 3) + 2*j;
                ldmx4(bf[nb8], sX + trow*XST_STRB + kbb);
            }
            #pragma unroll
            for (int mi = 0; mi < 4; mi++)
                #pragma unroll
                for (int nt = 0; nt < 7; nt++)
                    mma_f16(c[mi][nt], a[mi], &bf[nt >> 1][(nt & 1)*2]);
        }
    }

    // epilogue: h = tanh(f)*sigmoid(g); f = tiles 0,1; g = tiles 2,3 (same thread)
    int gr = lane >> 2, qc = (lane & 3)*2;
    __half* hout = &g_hh[(size_t)(n*NB + b)*HVEC];
    #pragma unroll
    for (int mi = 0; mi < 2; mi++) {
        #pragma unroll
        for (int hf = 0; hf < 2; hf++) {
            int o = mi*16 + gr + hf*8;
            float fb = fbs[o], gb = gbs[o];
            #pragma unroll
            for (int nt = 0; nt < 7; nt++) {
                int t = nt*8 + qc;
                if (t < NK) {
                    float f0 = tanhf(c[mi][nt][hf*2+0] + fb);
                    float f1 = tanhf(c[mi][nt][hf*2+1] + fb);
                    float gz0 = c[mi+2][nt][hf*2+0] + gb;
                    float gz1 = c[mi+2][nt][hf*2+1] + gb;
                    float h0 = f0 / (1.f + __expf(-gz0));
                    float h1 = f1 / (1.f + __expf(-gz1));
                    *(__half2*)&hout[o*NK + t] = __floats2half2_rn(h0, h1);
                }
            }
        }
    }
}

// ---------------- skip conv as per-node HMMA GEMM: D[cs][b] = W @ h_n ----------------
#define SK_WBYTES (64*272)
#define SK_BBYTES (32*272)
#define SK_BUF (SK_WBYTES + SK_BBYTES)
#define SKIP_SMEM (2*SK_BUF)
__global__ __launch_bounds__(128) void skip_mma(const float* __restrict__ skipb,
                                                float* __restrict__ sout)
{
    extern __shared__ __align__(16) char sks[];
    int n = blockIdx.x;
    int tid = threadIdx.x, warp = tid >> 5, lane = tid & 31;
    int m0 = warp * 16;
    uint32_t sb = smem_u32(sks);

    const __half* Bg = &g_hh[(size_t)n*NMCOL];

    float c[4][4];
    #pragma unroll
    for (int i = 0; i < 4; i++)
        #pragma unroll
        for (int j = 0; j < 4; j++) c[i][j] = 0.f;

    auto load_chunk = [&](int buf, int ch) {
        int k0 = ch * 128;
        uint32_t sW = sb + buf*SK_BUF;
        uint32_t sB = sW + SK_WBYTES;
        #pragma unroll
        for (int j = 0; j < 8; j++) {
            int lin = tid + j*128;
            int r = lin >> 4, q = lin & 15;
            CP_ASYNC16(sW + r*272 + q*16, &g_swh[r*HVEC + k0 + q*8]);
        }
        #pragma unroll
        for (int j = 0; j < 4; j++) {
            int lin = tid + j*128;
            int r = lin >> 4, q = lin & 15;
            CP_ASYNC16(sB + r*272 + q*16, &Bg[r*HVEC + k0 + q*8]);
        }
        CP_COMMIT();
    };

    load_chunk(0, 0);
    load_chunk(1, 1);

    for (int ch = 0; ch < 13; ch++) {
        if (ch == 12) { CP_WAIT0(); } else { CP_WAIT1(); }
        __syncthreads();
        int buf = ch & 1;
        uint32_t sW = sb + buf*SK_BUF;
        uint32_t sB = sW + SK_WBYTES;
        #pragma unroll
        for (int ks = 0; ks < 8; ks++) {
            int k0 = ks * 16;
            uint32_t a[4];
            ldmx4(a, sW + (m0 + (lane & 15))*272 + (k0 + (lane >> 4)*8)*2);
            uint32_t bfr[2][4];
            #pragma unroll
            for (int np = 0; np < 2; np++)
                ldmx4(bfr[np], sB + (np*16 + (lane & 7) + ((lane >> 4) << 3))*272
                               + (k0 + ((lane >> 3) & 1)*8)*2);
            #pragma unroll
            for (int ni = 0; ni < 4; ni++)
                mma_f16(c[ni], a, &bfr[ni >> 1][(ni & 1)*2]);
        }
        __syncthreads();
        if (ch + 2 < 13) load_chunk(buf, ch + 2);
    }

    int gr = lane >> 2, qc = (lane & 3)*2;
    #pragma unroll
    for (int ni = 0; ni < 4; ni++) {
        int b0 = ni*8 + qc;
        int cs0 = m0 + gr;
        float bi0 = skipb[cs0], bi1 = skipb[cs0 + 8];
        sout[(b0*C_S + cs0)*NV + n]       = c[ni][0] + bi0;
        sout[((b0+1)*C_S + cs0)*NV + n]   = c[ni][1] + bi0;
        sout[(b0*C_S + cs0+8)*NV + n]     = c[ni][2] + bi1;
        sout[((b0+1)*C_S + cs0+8)*NV + n] = c[ni][3] + bi1;
    }
}

// ---------------- fp16 HMMA prop: Hout = 0.05*h + 0.95*(Adj @ Hin) ----------------
#define PA_BYTES (128*80)
#define PB_BYTES (32*272)
#define PBUF (PA_BYTES + PB_BYTES)
#define PROP_SMEM (2*PBUF)
__global__ __launch_bounds__(256,2) void prop_mma(int step)
{
    extern __shared__ __align__(16) char smp[];
    const __half* Aadj; const __half* Bin; __half* Hout;
    if (blockIdx.z == 0) { Aadj = g_a1h; Bin = (step==1) ? g_hh : g_h1ah; Hout = (step==1) ? g_h1ah : g_h2ah; }
    else                 { Aadj = g_a2h; Bin = (step==1) ? g_hh : g_h1bh; Hout = (step==1) ? g_h1bh : g_h2bh; }

    int tid = threadIdx.x, warp = tid >> 5, lane = tid & 31;
    int nbase = blockIdx.x * 128;
    int vt = blockIdx.y;
    int wm = (warp >> 2)*64, wn = (warp & 3)*32;
    uint32_t sb = smem_u32(smp);

    float c[4][4][4];
    #pragma unroll
    for (int i = 0; i < 4; i++)
        #pragma unroll
        for (int j = 0; j < 4; j++)
            #pragma unroll
            for (int q = 0; q < 4; q++) c[i][j][q] = 0.f;

    auto load_chunk = [&](int buf, int ch) {
        int w0 = ch * 32;
        uint32_t sA = sb + buf*PBUF;
        uint32_t sB = sA + PA_BYTES;
        #pragma unroll
        for (int j = 0; j < 2; j++) {
            int lin = tid + j*256;
            int r = lin >> 2, q = lin & 3;
            CP_ASYNC16(sA + r*80 + q*16, &Aadj[(vt*128 + r)*VP + w0 + q*8]);
        }
        #pragma unroll
        for (int j = 0; j < 2; j++) {
            int lin = tid + j*256;
            int r = lin >> 4, q = lin & 15;
            CP_ASYNC16(sB + r*272 + q*16, &Bin[(size_t)(w0 + r)*NMCOL + nbase + q*8]);
        }
        CP_COMMIT();
    };

    load_chunk(0, 0);
    load_chunk(1, 1);

    for (int ch = 0; ch < 16; ch++) {
        if (ch == 15) { CP_WAIT0(); } else { CP_WAIT1(); }
        __syncthreads();
        int buf = ch & 1;
        uint32_t sA = sb + buf*PBUF;
        uint32_t sB = sA + PA_BYTES;
        #pragma unroll
        for (int ks = 0; ks < 2; ks++) {
            int k0 = ks * 16;
            uint32_t a[4][4];
            #pragma unroll
            for (int mi = 0; mi < 4; mi++)
                ldmx4(a[mi], sA + (wm + mi*16 + (lane & 15))*80 + (k0 + (lane >> 4)*8)*2);
            uint32_t bfr[2][4];
            #pragma unroll
            for (int np = 0; np < 2; np++)
                ldmx4t(bfr[np], sB + (k0 + (lane & 15))*272 + (wn + np*16 + (lane >> 4)*8)*2);
            #pragma unroll
            for (int mi = 0; mi < 4; mi++)
                #pragma unroll
                for (int ni = 0; ni < 4; ni++)
                    mma_f16(c[mi][ni], a[mi], &bfr[ni >> 1][(ni & 1)*2]);
        }
        __syncthreads();
        if (ch + 2 < 16) load_chunk(buf, ch + 2);
    }

    int gr = lane >> 2, qc = (lane & 3)*2;
    #pragma unroll
    for (int mi = 0; mi < 4; mi++) {
        #pragma unroll
        for (int hf = 0; hf < 2; hf++) {
            int v = vt*128 + wm + mi*16 + gr + hf*8;
            if (v < NV) {
                #pragma unroll
                for (int ni = 0; ni < 4; ni++) {
                    size_t off = (size_t)v*NMCOL + nbase + wn + ni*8 + qc;
                    float2 hb = __half22float2(*(const __half2*)&g_hh[off]);
                    float o0 = fmaf(0.95f, c[mi][ni][hf*2+0], 0.05f*hb.x);
                    float o1 = fmaf(0.95f, c[mi][ni][hf*2+1], 0.05f*hb.y);
                    *(__half2*)&Hout[off] = __floats2half2_rn(o0, o1);
                }
            }
        }
    }
}

// ---------------- combine (reads fp16 tensors) + stats ----------------
#define COMB_SMEM ((4*5*32*56 + 5*1024 + 32)*4)
__global__ __launch_bounds__(256) void combine_kernel(const float* __restrict__ x,
                                                      const float* __restrict__ gc1w,
                                                      const float* __restrict__ gc1b,
                                                      const float* __restrict__ gc2w,
                                                      const float* __restrict__ gc2b)
{
    extern __shared__ __align__(16) float sm2[];
    float* ts = sm2;
    float* ws = sm2 + 4*5*32*56;
    float* bs = ws + 5*1024;
    int tid = threadIdx.x;
    int v = blockIdx.x, bg = blockIdx.y;

    for (int e = tid; e < 1024; e += 256) {
        int cp = e >> 5, cch = e & 31;
        ws[0*1024 + cp*32 + cch] = gc1w[cch*96 + cp] + gc2w[cch*96 + cp];
        ws[1*1024 + cp*32 + cch] = gc1w[cch*96 + 32 + cp];
        ws[2*1024 + cp*32 + cch] = gc1w[cch*96 + 64 + cp];
        ws[3*1024 + cp*32 + cch] = gc2w[cch*96 + 32 + cp];
        ws[4*1024 + cp*32 + cch] = gc2w[cch*96 + 64 + cp];
    }
    if (tid < 32) bs[tid] = gc1b[tid] + gc2b[tid];

    #pragma unroll
    for (int t = 0; t < 5; t++) {
        const __half* src = (t==0)?g_hh:(t==1)?g_h1ah:(t==2)?g_h2ah:(t==3)?g_h1bh:g_h2bh;
        for (int lin = tid; lin < 4*32*13; lin += 256) {
            int lq = lin % 13;
            int r = lin / 13;
            int cp = r & 31, sub = r >> 5;
            int b = bg*4 + sub;
            uint2 raw = *(const uint2*)&src[(size_t)(v*NB + b)*HVEC + cp*NK + lq*4];
            float2 f0 = __half22float2(*(__half2*)&raw.x);
            float2 f1 = __half22float2(*(__half2*)&raw.y);
            *(float4*)&ts[((sub*5 + t)*32 + cp)*56 + lq*4] = make_float4(f0.x, f0.y, f1.x, f1.y);
        }
    }
    __syncthreads();

    int sub = tid >> 6, cq = (tid >> 3) & 7, lg = tid & 7;
    int b = bg*4 + sub;

    float acc[4][7];
    #pragma unroll
    for (int m = 0; m < 4; m++)
        #pragma unroll
        for (int s = 0; s < 7; s++) acc[m][s] = 0.f;

    const float* tb = &ts[sub*5*32*56];
    for (int cp = 0; cp < 32; cp++) {
        float w0[4], w1[4], w2[4], w3[4], w4[4];
        #pragma unroll
        for (int m = 0; m < 4; m++) {
            int cch = cq + 8*m;
            w0[m] = ws[0*1024 + cp*32 + cch];
            w1[m] = ws[1*1024 + cp*32 + cch];
            w2[m] = ws[2*1024 + cp*32 + cch];
            w3[m] = ws[3*1024 + cp*32 + cch];
            w4[m] = ws[4*1024 + cp*32 + cch];
        }
        #pragma unroll
        for (int s = 0; s < 7; s++) {
            int l = lg + 8*s;
            float v0 = tb[(0*32 + cp)*56 + l];
            float v1 = tb[(1*32 + cp)*56 + l];
            float v2 = tb[(2*32 + cp)*56 + l];
            float v3 = tb[(3*32 + cp)*56 + l];
            float v4 = tb[(4*32 + cp)*56 + l];
            #pragma unroll
            for (int m = 0; m < 4; m++) {
                acc[m][s] = fmaf(w0[m], v0, acc[m][s]);
                acc[m][s] = fmaf(w1[m], v1, acc[m][s]);
                acc[m][s] = fmaf(w2[m], v2, acc[m][s]);
                acc[m][s] = fmaf(w3[m], v3, acc[m][s]);
                acc[m][s] = fmaf(w4[m], v4, acc[m][s]);
            }
        }
    }

    float psum = 0.f, psq = 0.f;
    #pragma unroll
    for (int m = 0; m < 4; m++) {
        int cch = cq + 8*m;
        #pragma unroll
        for (int s = 0; s < 7; s++) {
            int l = lg + 8*s;
            if (l < NK) {
                float val = acc[m][s] + bs[cch] + x[((b*C_R + cch)*NV + v)*NT + 12 + l];
                g_xo[((b*C_C + cch)*NV + v)*NK + l] = val;
                psum += val;
                psq = fmaf(val, val, psq);
            }
        }
    }
    #pragma unroll
    for (int off = 16; off > 0; off >>= 1) {
        psum += __shfl_down_sync(0xffffffffu, psum, off);
        psq  += __shfl_down_sync(0xffffffffu, psq,  off);
    }
    if ((tid & 31) == 0) {
        atomicAdd(&g_stats[2*b], psum);
        atomicAdd(&g_stats[2*b + 1], psq);
    }
}

// ---------------- LayerNorm apply ----------------
__global__ __launch_bounds__(256) void norm_kernel(const int* __restrict__ idx,
                                                   const float* __restrict__ lnw,
                                                   const float* __restrict__ lnb,
                                                   float* __restrict__ out)
{
    int gid = blockIdx.x * 256 + threadIdx.x;
    int lq = gid % 13;
    int row = gid / 13;
    int v = row % NV;
    int cch = (row / NV) % C_C;
    int b = row / (C_C*NV);

    float s1 = g_stats[2*b], s2 = g_stats[2*b + 1];
    float mean = s1 * (1.f/(float)CNT_PER_B);
    float var  = s2 * (1.f/(float)CNT_PER_B) - mean*mean;
    float rstd = rsqrtf(var + 1e-5f);
    int nidx = idx[v];

    float4 xo = *(const float4*)&g_xo[row*NK + lq*4];
    float4 w4 = *(const float4*)&lnw[(cch*NV + nidx)*NK + lq*4];
    float4 b4 = *(const float4*)&lnb[(cch*NV + nidx)*NK + lq*4];
    float4 o;
    o.x = (xo.x - mean)*rstd*w4.x + b4.x;
    o.y = (xo.y - mean)*rstd*w4.y + b4.y;
    o.z = (xo.z - mean)*rstd*w4.z + b4.z;
    o.w = (xo.w - mean)*rstd*w4.w + b4.w;
    *(float4*)&out[row*NK + lq*4] = o;
}

// ---------------- launch ----------------
extern "C" void kernel_launch(void* const* d_in, const int* in_sizes, int n_in,
                              void* d_out, int out_size)
{
    const float* x = (const float*)d_in[0];
    int ia = (in_sizes[1] == NV*NV) ? 1 : 2;
    const float* adp = (const float*)d_in[ia];
    const int*   idx = (const int*)d_in[3 - ia];
    const float* fw2 = (const float*)d_in[3];
    const float* fb2 = (const float*)d_in[4];
    const float* fw3 = (const float*)d_in[5];
    const float* fb3 = (const float*)d_in[6];
    const float* fw6 = (const float*)d_in[7];
    const float* fb6 = (const float*)d_in[8];
    const float* fw7 = (const float*)d_in[9];
    const float* fb7 = (const float*)d_in[10];
    const float* gw2 = (const float*)d_in[11];
    const float* gb2 = (const float*)d_in[12];
    const float* gw3 = (const float*)d_in[13];
    const float* gb3 = (const float*)d_in[14];
    const float* gw6 = (const float*)d_in[15];
    const float* gb6 = (const float*)d_in[16];
    const float* gw7 = (const float*)d_in[17];
    const float* gb7 = (const float*)d_in[18];
    const float* skipw = (const float*)d_in[19];
    const float* skipb = (const float*)d_in[20];
    const float* gc1w = (const float*)d_in[21];
    const float* gc1b = (const float*)d_in[22];
    const float* gc2w = (const float*)d_in[23];
    const float* gc2b = (const float*)d_in[24];
    const float* lnw = (const float*)d_in[25];
    const float* lnb = (const float*)d_in[26];
    float* out = (float*)d_out;
    float* s_out = out + NB*C_C*NV*NK;

    cudaFuncSetAttribute(incept_mma,     cudaFuncAttributeMaxDynamicSharedMemorySize, INCEPT_SMEM);
    cudaFuncSetAttribute(skip_mma,       cudaFuncAttributeMaxDynamicSharedMemorySize, SKIP_SMEM);
    cudaFuncSetAttribute(prop_mma,       cudaFuncAttributeMaxDynamicSharedMemorySize, PROP_SMEM);
    cudaFuncSetAttribute(combine_kernel, cudaFuncAttributeMaxDynamicSharedMemorySize, COMB_SMEM);

    pack_kernel<<<64, 256>>>(fw2, fw3, fw6, fw7, fb2, fb3, fb6, fb7,
                             gw2, gw3, gw6, gw7, gb2, gb3, gb6, gb7, skipw);
    adj_kernel<<<1024, 256>>>(adp);
    incept_mma<<<2000, 256, INCEPT_SMEM>>>(x);
    skip_mma<<<NV, 128, SKIP_SMEM>>>(skipb, s_out);
    prop_mma<<<dim3(NMCOL/128, 4, 2), 256, PROP_SMEM>>>(1);
    prop_mma<<<dim3(NMCOL/128, 4, 2), 256, PROP_SMEM>>>(2);
    combine_kernel<<<dim3(NV, 8), 256, COMB_SMEM>>>(x, gc1w, gc1b, gc2w, gc2b);
    norm_kernel<<<26000, 256>>>(idx, lnw, lnb, out);
}

// round 7
// speedup vs baseline: 3.9964x; 1.3283x over previous
#include <cuda_runtime.h>
#include <cuda_fp16.h>
#include <cstdint>

// ---------------- problem constants ----------------
#define NB   32
#define C_R  32
#define C_C  32
#define C_S  64
#define NV   500
#define NT   64
#define NK   52
#define NMCOL (NB*C_C*NK)   // 53248
#define VP   512
#define HVEC (C_C*NK)       // 1664
#define CNT_PER_B (C_C*NV*NK)

// ---------------- device scratch (zero-initialized) ----------------
__device__ __half g_a1h[VP*VP];
__device__ __half g_a2h[VP*VP];
__device__ __half g_swh[C_S*HVEC];
__device__ __half g_Wph[7*64*40];     // packed inception weights, SMEM-image layout (40-half stride)
__device__ float  g_fbias[C_C];
__device__ float  g_gbias[C_C];
// rows (nodes) padded to 512; rows >=500 never written, stay zero
__device__ __half g_hh  [VP*NMCOL];
__device__ __half g_h1ah[VP*NMCOL];
__device__ __half g_h1bh[VP*NMCOL];
__device__ __half g_h2ah[VP*NMCOL];
__device__ __half g_h2bh[VP*NMCOL];
__device__ float  g_xo [NB*C_C*NV*NK];
__device__ float  g_stats[2*NB];

// ---------------- helpers ----------------
__device__ __forceinline__ uint32_t smem_u32(const void* p){
    uint32_t a; asm("{ .reg .u64 t; cvta.to.shared.u64 t, %1; cvt.u32.u64 %0, t; }":"=r"(a):"l"(p)); return a;
}
#define CP_ASYNC16(s,g) asm volatile("cp.async.cg.shared.global [%0], [%1], 16;"::"r"(s),"l"(g))
#define CP_COMMIT()     asm volatile("cp.async.commit_group;" ::: "memory")
#define CP_WAIT1()      asm volatile("cp.async.wait_group 1;" ::: "memory")
#define CP_WAIT0()      asm volatile("cp.async.wait_group 0;" ::: "memory")

__device__ __forceinline__ void ldmx4(uint32_t* r, uint32_t addr){
    asm volatile("ldmatrix.sync.aligned.m8n8.x4.shared.b16 {%0,%1,%2,%3}, [%4];"
        : "=r"(r[0]),"=r"(r[1]),"=r"(r[2]),"=r"(r[3]) : "r"(addr));
}
__device__ __forceinline__ void ldmx4t(uint32_t* r, uint32_t addr){
    asm volatile("ldmatrix.sync.aligned.m8n8.x4.trans.shared.b16 {%0,%1,%2,%3}, [%4];"
        : "=r"(r[0]),"=r"(r[1]),"=r"(r[2]),"=r"(r[3]) : "r"(addr));
}
__device__ __forceinline__ void mma_f16(float* c, const uint32_t* a, const uint32_t* b){
    asm volatile("mma.sync.aligned.m16n8k16.row.col.f32.f16.f16.f32 "
        "{%0,%1,%2,%3}, {%4,%5,%6,%7}, {%8,%9}, {%0,%1,%2,%3};"
        : "+f"(c[0]),"+f"(c[1]),"+f"(c[2]),"+f"(c[3])
        : "r"(a[0]),"r"(a[1]),"r"(a[2]),"r"(a[3]), "r"(b[0]),"r"(b[1]));
}

// ---------------- pack: fp16 inception weights (padded layout), half skip weights, stats ----------------
__global__ void pack_kernel(const float* __restrict__ fw2,const float* __restrict__ fw3,
    const float* __restrict__ fw6,const float* __restrict__ fw7,
    const float* __restrict__ fb2,const float* __restrict__ fb3,
    const float* __restrict__ fb6,const float* __restrict__ fb7,
    const float* __restrict__ gw2,const float* __restrict__ gw3,
    const float* __restrict__ gw6,const float* __restrict__ gw7,
    const float* __restrict__ gb2,const float* __restrict__ gb3,
    const float* __restrict__ gb6,const float* __restrict__ gb7,
    const float* __restrict__ skipw)
{
    int tid = threadIdx.x;
    int gtid = blockIdx.x * blockDim.x + tid;
    for (int e = gtid; e < C_S*HVEC; e += gridDim.x * blockDim.x)
        g_swh[e] = __float2half_rn(skipw[e]);
    if (blockIdx.x != 0) return;
    if (tid < 2*NB) g_stats[tid] = 0.f;
    for (int e = tid; e < 7*64*32; e += blockDim.x) {
        int j = e / 2048;
        int o = (e & 2047) >> 5;
        int i = e & 31;
        int oc = o & 31;
        int br = oc >> 3, oo = oc & 7;
        int k = (br==0)?2:(br==1)?3:(br==2)?6:7;
        int j0 = 7 - k;
        float vv = 0.f;
        if (j >= j0) {
            int si = (oo*C_R + i)*k + (j - j0);
            if (o < 32) {
                const float* fw = (br==0)?fw2:(br==1)?fw3:(br==2)?fw6:fw7;
                vv = fw[si];
            } else {
                const float* gw = (br==0)?gw2:(br==1)?gw3:(br==2)?gw6:gw7;
                vv = gw[si];
            }
        }
        g_Wph[(j*64 + o)*40 + i] = __float2half_rn(vv);
    }
    if (tid < C_C) {
        int br = tid >> 3, oo = tid & 7;
        const float* fb = (br==0)?fb2:(br==1)?fb3:(br==2)?fb6:fb7;
        const float* gb = (br==0)?gb2:(br==1)?gb3:(br==2)?gb6:gb7;
        g_fbias[tid] = fb[oo]; g_gbias[tid] = gb[oo];
    }
}

// ---------------- normalized adjacencies -> fp16, padded to 512x512 ----------------
__global__ void adj_kernel(const float* __restrict__ adp)
{
    int v = blockIdx.x & 511;
    int which = blockIdx.x >> 9;
    __half* dst = which ? g_a2h : g_a1h;
    if (v >= NV) {
        for (int w = threadIdx.x; w < VP; w += 256) dst[v*VP + w] = __float2half_rn(0.f);
        return;
    }
    __shared__ float red[256];
    float s = 0.f;
    for (int w = threadIdx.x; w < NV; w += 256)
        s += which ? adp[w*NV + v] : adp[v*NV + w];
    red[threadIdx.x] = s; __syncthreads();
    for (int st = 128; st > 0; st >>= 1) {
        if (threadIdx.x < st) red[threadIdx.x] += red[threadIdx.x + st];
        __syncthreads();
    }
    float inv = 1.f / (red[0] + 1.f);
    for (int w = threadIdx.x; w < VP; w += 256) {
        float val = 0.f;
        if (w < NV) {
            val = which ? adp[w*NV + v] : adp[v*NV + w];
            if (w == v) val += 1.f;
            val *= inv;
        }
        dst[v*VP + w] = __float2half_rn(val);
    }
}

// ---------------- HMMA dilated inception + gating -> fp16 h ----------------
#define XST_ROWS 80
#define XST_STRB 80
#define XST_WARP (XST_ROWS*XST_STRB)
#define WP_STRB 80
#define WP_BYTES (7*64*WP_STRB)           // 35840 B
#define INCEPT_SMEM (WP_BYTES + 8*XST_WARP + 512)
__global__ __launch_bounds__(256,1) void incept_mma(const float* __restrict__ x)
{
    extern __shared__ __align__(16) char smi[];
    uint32_t sW = smem_u32(smi);
    uint32_t sX0 = sW + WP_BYTES;
    float* fbs = (float*)(smi + WP_BYTES + 8*XST_WARP);
    float* gbs = fbs + 32;

    int tid = threadIdx.x, warp = tid >> 5, lane = tid & 31;

    // vectorized weight staging (global layout == smem layout)
    for (int e = tid; e < WP_BYTES/16; e += 256)
        *(float4*)(smi + e*16) = *(const float4*)(((const char*)g_Wph) + e*16);
    if (tid < 32) { fbs[tid] = g_fbias[tid]; gbs[tid] = g_gbias[tid]; }

    int p = blockIdx.x * 8 + warp;
    int n = p >> 5, b = p & 31;
    uint32_t sX = sX0 + warp*XST_WARP;
    {
        int i0 = (lane & 15) * 2;
        int t0 = (lane >> 4) * 32;
        const float* xr0 = &x[((size_t)(b*C_R + i0)*NV + n)*NT + t0];
        const float* xr1 = xr0 + (size_t)NV*NT;
        #pragma unroll
        for (int q = 0; q < 8; q++) {
            float4 v0 = *(const float4*)&xr0[q*4];
            float4 v1 = *(const float4*)&xr1[q*4];
            const float* a0 = &v0.x; const float* a1 = &v1.x;
            #pragma unroll
            for (int r = 0; r < 4; r++) {
                int t = t0 + q*4 + r;
                *(__half2*)(smi + (sX - smem_u32(smi)) + t*XST_STRB + i0*2) =
                    __floats2half2_rn(a0[r], a1[r]);
            }
        }
    }
    __syncthreads();

    float c[4][7][4];
    #pragma unroll
    for (int mi = 0; mi < 4; mi++)
        #pragma unroll
        for (int nt = 0; nt < 7; nt++)
            #pragma unroll
            for (int q = 0; q < 4; q++) c[mi][nt][q] = 0.f;

    #pragma unroll
    for (int j = 0; j < 7; j++) {
        uint32_t wbase = sW + j*64*WP_STRB;
        #pragma unroll
        for (int kst = 0; kst < 2; kst++) {
            int kb = (kst*16 + (lane >> 4)*8) * 2;
            uint32_t a[4][4];
            #pragma unroll
            for (int mi = 0; mi < 4; mi++)
                ldmx4(a[mi], wbase + (mi*16 + (lane & 15))*WP_STRB + kb);
            uint32_t bf[4][4];
            int kbb = (kst*16 + ((lane >> 3) & 1)*8) * 2;
            #pragma unroll
            for (int nb8 = 0; nb8 < 4; nb8++) {
                int trow = nb8*16 + (lane & 7) + ((lane >> 4) << 3) + 2*j;
                ldmx4(bf[nb8], sX + trow*XST_STRB + kbb);
            }
            #pragma unroll
            for (int mi = 0; mi < 4; mi++)
                #pragma unroll
                for (int nt = 0; nt < 7; nt++)
                    mma_f16(c[mi][nt], a[mi], &bf[nt >> 1][(nt & 1)*2]);
        }
    }

    int gr = lane >> 2, qc = (lane & 3)*2;
    __half* hout = &g_hh[(size_t)(n*NB + b)*HVEC];
    #pragma unroll
    for (int mi = 0; mi < 2; mi++) {
        #pragma unroll
        for (int hf = 0; hf < 2; hf++) {
            int o = mi*16 + gr + hf*8;
            float fb = fbs[o], gb = gbs[o];
            #pragma unroll
            for (int nt = 0; nt < 7; nt++) {
                int t = nt*8 + qc;
                if (t < NK) {
                    float f0 = tanhf(c[mi][nt][hf*2+0] + fb);
                    float f1 = tanhf(c[mi][nt][hf*2+1] + fb);
                    float gz0 = c[mi+2][nt][hf*2+0] + gb;
                    float gz1 = c[mi+2][nt][hf*2+1] + gb;
                    float h0 = f0 / (1.f + __expf(-gz0));
                    float h1 = f1 / (1.f + __expf(-gz1));
                    *(__half2*)&hout[o*NK + t] = __floats2half2_rn(h0, h1);
                }
            }
        }
    }
}

// ---------------- skip conv as per-node HMMA GEMM ----------------
#define SK_WBYTES (64*272)
#define SK_BBYTES (32*272)
#define SK_BUF (SK_WBYTES + SK_BBYTES)
#define SKIP_SMEM (2*SK_BUF)
__global__ __launch_bounds__(128) void skip_mma(const float* __restrict__ skipb,
                                                float* __restrict__ sout)
{
    extern __shared__ __align__(16) char sks[];
    int n = blockIdx.x;
    int tid = threadIdx.x, warp = tid >> 5, lane = tid & 31;
    int m0 = warp * 16;
    uint32_t sb = smem_u32(sks);

    const __half* Bg = &g_hh[(size_t)n*NMCOL];

    float c[4][4];
    #pragma unroll
    for (int i = 0; i < 4; i++)
        #pragma unroll
        for (int j = 0; j < 4; j++) c[i][j] = 0.f;

    auto load_chunk = [&](int buf, int ch) {
        int k0 = ch * 128;
        uint32_t sW = sb + buf*SK_BUF;
        uint32_t sB = sW + SK_WBYTES;
        #pragma unroll
        for (int j = 0; j < 8; j++) {
            int lin = tid + j*128;
            int r = lin >> 4, q = lin & 15;
            CP_ASYNC16(sW + r*272 + q*16, &g_swh[r*HVEC + k0 + q*8]);
        }
        #pragma unroll
        for (int j = 0; j < 4; j++) {
            int lin = tid + j*128;
            int r = lin >> 4, q = lin & 15;
            CP_ASYNC16(sB + r*272 + q*16, &Bg[r*HVEC + k0 + q*8]);
        }
        CP_COMMIT();
    };

    load_chunk(0, 0);
    load_chunk(1, 1);

    for (int ch = 0; ch < 13; ch++) {
        if (ch == 12) { CP_WAIT0(); } else { CP_WAIT1(); }
        __syncthreads();
        int buf = ch & 1;
        uint32_t sW = sb + buf*SK_BUF;
        uint32_t sB = sW + SK_WBYTES;
        #pragma unroll
        for (int ks = 0; ks < 8; ks++) {
            int k0 = ks * 16;
            uint32_t a[4];
            ldmx4(a, sW + (m0 + (lane & 15))*272 + (k0 + (lane >> 4)*8)*2);
            uint32_t bfr[2][4];
            #pragma unroll
            for (int np = 0; np < 2; np++)
                ldmx4(bfr[np], sB + (np*16 + (lane & 7) + ((lane >> 4) << 3))*272
                               + (k0 + ((lane >> 3) & 1)*8)*2);
            #pragma unroll
            for (int ni = 0; ni < 4; ni++)
                mma_f16(c[ni], a, &bfr[ni >> 1][(ni & 1)*2]);
        }
        __syncthreads();
        if (ch + 2 < 13) load_chunk(buf, ch + 2);
    }

    int gr = lane >> 2, qc = (lane & 3)*2;
    #pragma unroll
    for (int ni = 0; ni < 4; ni++) {
        int b0 = ni*8 + qc;
        int cs0 = m0 + gr;
        float bi0 = skipb[cs0], bi1 = skipb[cs0 + 8];
        sout[(b0*C_S + cs0)*NV + n]       = c[ni][0] + bi0;
        sout[((b0+1)*C_S + cs0)*NV + n]   = c[ni][1] + bi0;
        sout[(b0*C_S + cs0+8)*NV + n]     = c[ni][2] + bi1;
        sout[((b0+1)*C_S + cs0+8)*NV + n] = c[ni][3] + bi1;
    }
}

// ---------------- fp16 HMMA prop: Hout = 0.05*h + 0.95*(Adj @ Hin) ----------------
#define PA_BYTES (128*80)
#define PB_BYTES (32*272)
#define PBUF (PA_BYTES + PB_BYTES)
#define PROP_SMEM (2*PBUF)
__global__ __launch_bounds__(256,2) void prop_mma(int step)
{
    extern __shared__ __align__(16) char smp[];
    const __half* Aadj; const __half* Bin; __half* Hout;
    if (blockIdx.z == 0) { Aadj = g_a1h; Bin = (step==1) ? g_hh : g_h1ah; Hout = (step==1) ? g_h1ah : g_h2ah; }
    else                 { Aadj = g_a2h; Bin = (step==1) ? g_hh : g_h1bh; Hout = (step==1) ? g_h1bh : g_h2bh; }

    int tid = threadIdx.x, warp = tid >> 5, lane = tid & 31;
    int nbase = blockIdx.x * 128;
    int vt = blockIdx.y;
    int wm = (warp >> 2)*64, wn = (warp & 3)*32;
    uint32_t sb = smem_u32(smp);

    float c[4][4][4];
    #pragma unroll
    for (int i = 0; i < 4; i++)
        #pragma unroll
        for (int j = 0; j < 4; j++)
            #pragma unroll
            for (int q = 0; q < 4; q++) c[i][j][q] = 0.f;

    auto load_chunk = [&](int buf, int ch) {
        int w0 = ch * 32;
        uint32_t sA = sb + buf*PBUF;
        uint32_t sB = sA + PA_BYTES;
        #pragma unroll
        for (int j = 0; j < 2; j++) {
            int lin = tid + j*256;
            int r = lin >> 2, q = lin & 3;
            CP_ASYNC16(sA + r*80 + q*16, &Aadj[(vt*128 + r)*VP + w0 + q*8]);
        }
        #pragma unroll
        for (int j = 0; j < 2; j++) {
            int lin = tid + j*256;
            int r = lin >> 4, q = lin & 15;
            CP_ASYNC16(sB + r*272 + q*16, &Bin[(size_t)(w0 + r)*NMCOL + nbase + q*8]);
        }
        CP_COMMIT();
    };

    load_chunk(0, 0);
    load_chunk(1, 1);

    for (int ch = 0; ch < 16; ch++) {
        if (ch == 15) { CP_WAIT0(); } else { CP_WAIT1(); }
        __syncthreads();
        int buf = ch & 1;
        uint32_t sA = sb + buf*PBUF;
        uint32_t sB = sA + PA_BYTES;
        #pragma unroll
        for (int ks = 0; ks < 2; ks++) {
            int k0 = ks * 16;
            uint32_t a[4][4];
            #pragma unroll
            for (int mi = 0; mi < 4; mi++)
                ldmx4(a[mi], sA + (wm + mi*16 + (lane & 15))*80 + (k0 + (lane >> 4)*8)*2);
            uint32_t bfr[2][4];
            #pragma unroll
            for (int np = 0; np < 2; np++)
                ldmx4t(bfr[np], sB + (k0 + (lane & 15))*272 + (wn + np*16 + (lane >> 4)*8)*2);
            #pragma unroll
            for (int mi = 0; mi < 4; mi++)
                #pragma unroll
                for (int ni = 0; ni < 4; ni++)
                    mma_f16(c[mi][ni], a[mi], &bfr[ni >> 1][(ni & 1)*2]);
        }
        __syncthreads();
        if (ch + 2 < 16) load_chunk(buf, ch + 2);
    }

    int gr = lane >> 2, qc = (lane & 3)*2;
    #pragma unroll
    for (int mi = 0; mi < 4; mi++) {
        #pragma unroll
        for (int hf = 0; hf < 2; hf++) {
            int v = vt*128 + wm + mi*16 + gr + hf*8;
            if (v < NV) {
                #pragma unroll
                for (int ni = 0; ni < 4; ni++) {
                    size_t off = (size_t)v*NMCOL + nbase + wn + ni*8 + qc;
                    float2 hb = __half22float2(*(const __half2*)&g_hh[off]);
                    float o0 = fmaf(0.95f, c[mi][ni][hf*2+0], 0.05f*hb.x);
                    float o1 = fmaf(0.95f, c[mi][ni][hf*2+1], 0.05f*hb.y);
                    *(__half2*)&Hout[off] = __floats2half2_rn(o0, o1);
                }
            }
        }
    }
}

// ---------------- combine as per-(v,b) HMMA GEMM: out[c][l] = W[32x160] @ T[160x52] ----------------
// W rows: k = t*32+cp, tensors t: {h(gc1+gc2), h1a, h2a, h1b, h2b}
#define CW_STRB 336                        // 32 rows x 160 halfs, padded
#define CW_BYTES (32*CW_STRB)              // 10752
#define CT_STRB 144                        // 160 rows x 64 halfs padded (cols 52..63 garbage, unused)
#define CT_WARP (160*CT_STRB)              // 23040 per warp
#define COMB_SMEM (CW_BYTES + 128 + 8*CT_WARP)
__global__ __launch_bounds__(256,1) void combine_mma(const float* __restrict__ x,
                                                     const float* __restrict__ gc1w,
                                                     const float* __restrict__ gc1b,
                                                     const float* __restrict__ gc2w,
                                                     const float* __restrict__ gc2b)
{
    extern __shared__ __align__(16) char smc[];
    uint32_t sW = smem_u32(smc);
    float* bias = (float*)(smc + CW_BYTES);
    uint32_t sT0 = sW + CW_BYTES + 128;

    int tid = threadIdx.x, warp = tid >> 5, lane = tid & 31;

    // stage fused weights -> fp16 [c][k], k = t*32+cp
    for (int e = tid; e < 5120; e += 256) {
        int cch = e / 160, k = e % 160;
        int t = k >> 5, cp = k & 31;
        float val;
        if      (t == 0) val = gc1w[cch*96 + cp] + gc2w[cch*96 + cp];
        else if (t == 1) val = gc1w[cch*96 + 32 + cp];
        else if (t == 2) val = gc1w[cch*96 + 64 + cp];
        else if (t == 3) val = gc2w[cch*96 + 32 + cp];
        else             val = gc2w[cch*96 + 64 + cp];
        *(__half*)(smc + cch*CW_STRB + k*2) = __float2half_rn(val);
    }
    if (tid < 32) bias[tid] = gc1b[tid] + gc2b[tid];

    // stage T: rows k = t*32+cp, cols l (52, pad to 64)
    int p = blockIdx.x * 8 + warp;
    int n = p >> 5, b = p & 31;
    uint32_t sT = sT0 + warp*CT_WARP;
    size_t slab_off = (size_t)(n*NB + b)*HVEC;
    for (int e = lane; e < 160*13; e += 32) {
        int r = e / 13, j = e % 13;
        const __half* slab = (r < 32) ? g_hh : (r < 64) ? g_h1ah : (r < 96) ? g_h2ah
                            : (r < 128) ? g_h1bh : g_h2bh;
        uint2 v = *(const uint2*)&slab[slab_off + (size_t)(r & 31)*NK + j*4];
        *(uint2*)((char*)smc + (sT - smem_u32(smc)) + r*CT_STRB + j*8) = v;
    }
    __syncthreads();

    float c[2][7][4];
    #pragma unroll
    for (int mi = 0; mi < 2; mi++)
        #pragma unroll
        for (int nt = 0; nt < 7; nt++)
            #pragma unroll
            for (int q = 0; q < 4; q++) c[mi][nt][q] = 0.f;

    #pragma unroll
    for (int ks = 0; ks < 10; ks++) {
        int k0 = ks * 16;
        uint32_t a[2][4];
        #pragma unroll
        for (int mi = 0; mi < 2; mi++)
            ldmx4(a[mi], sW + (mi*16 + (lane & 15))*CW_STRB + (k0 + (lane >> 4)*8)*2);
        uint32_t bq[4][4];
        #pragma unroll
        for (int nq = 0; nq < 4; nq++)
            ldmx4t(bq[nq], sT + (k0 + (lane & 15))*CT_STRB + (nq*16 + (lane >> 4)*8)*2);
        #pragma unroll
        for (int mi = 0; mi < 2; mi++)
            #pragma unroll
            for (int nt = 0; nt < 7; nt++)
                mma_f16(c[mi][nt], a[mi], &bq[nt >> 1][(nt & 1)*2]);
    }

    // epilogue: + bias + residual, write xo, accumulate LN stats
    int gr = lane >> 2, qc = (lane & 3)*2;
    float psum = 0.f, psq = 0.f;
    #pragma unroll
    for (int mi = 0; mi < 2; mi++) {
        #pragma unroll
        for (int hf = 0; hf < 2; hf++) {
            int cch = mi*16 + gr + hf*8;
            float bi = bias[cch];
            const float* xr = &x[((size_t)(b*C_R + cch)*NV + n)*NT + 12];
            float* xor_ = &g_xo[((size_t)(b*C_C + cch)*NV + n)*NK];
            #pragma unroll
            for (int nt = 0; nt < 7; nt++) {
                int l = nt*8 + qc;
                if (l < NK) {
                    float v0 = c[mi][nt][hf*2+0] + bi + xr[l];
                    float v1 = c[mi][nt][hf*2+1] + bi + xr[l+1];
                    *(float2*)&xor_[l] = make_float2(v0, v1);
                    psum += v0 + v1;
                    psq  = fmaf(v0, v0, psq);
                    psq  = fmaf(v1, v1, psq);
                }
            }
        }
    }
    #pragma unroll
    for (int off = 16; off > 0; off >>= 1) {
        psum += __shfl_down_sync(0xffffffffu, psum, off);
        psq  += __shfl_down_sync(0xffffffffu, psq,  off);
    }
    if (lane == 0) {
        atomicAdd(&g_stats[2*b], psum);
        atomicAdd(&g_stats[2*b + 1], psq);
    }
}

// ---------------- LayerNorm apply ----------------
__global__ __launch_bounds__(256) void norm_kernel(const int* __restrict__ idx,
                                                   const float* __restrict__ lnw,
                                                   const float* __restrict__ lnb,
                                                   float* __restrict__ out)
{
    int gid = blockIdx.x * 256 + threadIdx.x;
    int lq = gid % 13;
    int row = gid / 13;
    int v = row % NV;
    int cch = (row / NV) % C_C;
    int b = row / (C_C*NV);

    float s1 = g_stats[2*b], s2 = g_stats[2*b + 1];
    float mean = s1 * (1.f/(float)CNT_PER_B);
    float var  = s2 * (1.f/(float)CNT_PER_B) - mean*mean;
    float rstd = rsqrtf(var + 1e-5f);
    int nidx = idx[v];

    float4 xo = *(const float4*)&g_xo[row*NK + lq*4];
    float4 w4 = *(const float4*)&lnw[(cch*NV + nidx)*NK + lq*4];
    float4 b4 = *(const float4*)&lnb[(cch*NV + nidx)*NK + lq*4];
    float4 o;
    o.x = (xo.x - mean)*rstd*w4.x + b4.x;
    o.y = (xo.y - mean)*rstd*w4.y + b4.y;
    o.z = (xo.z - mean)*rstd*w4.z + b4.z;
    o.w = (xo.w - mean)*rstd*w4.w + b4.w;
    *(float4*)&out[row*NK + lq*4] = o;
}

// ---------------- launch ----------------
extern "C" void kernel_launch(void* const* d_in, const int* in_sizes, int n_in,
                              void* d_out, int out_size)
{
    const float* x = (const float*)d_in[0];
    int ia = (in_sizes[1] == NV*NV) ? 1 : 2;
    const float* adp = (const float*)d_in[ia];
    const int*   idx = (const int*)d_in[3 - ia];
    const float* fw2 = (const float*)d_in[3];
    const float* fb2 = (const float*)d_in[4];
    const float* fw3 = (const float*)d_in[5];
    const float* fb3 = (const float*)d_in[6];
    const float* fw6 = (const float*)d_in[7];
    const float* fb6 = (const float*)d_in[8];
    const float* fw7 = (const float*)d_in[9];
    const float* fb7 = (const float*)d_in[10];
    const float* gw2 = (const float*)d_in[11];
    const float* gb2 = (const float*)d_in[12];
    const float* gw3 = (const float*)d_in[13];
    const float* gb3 = (const float*)d_in[14];
    const float* gw6 = (const float*)d_in[15];
    const float* gb6 = (const float*)d_in[16];
    const float* gw7 = (const float*)d_in[17];
    const float* gb7 = (const float*)d_in[18];
    const float* skipw = (const float*)d_in[19];
    const float* skipb = (const float*)d_in[20];
    const float* gc1w = (const float*)d_in[21];
    const float* gc1b = (const float*)d_in[22];
    const float* gc2w = (const float*)d_in[23];
    const float* gc2b = (const float*)d_in[24];
    const float* lnw = (const float*)d_in[25];
    const float* lnb = (const float*)d_in[26];
    float* out = (float*)d_out;
    float* s_out = out + NB*C_C*NV*NK;

    cudaFuncSetAttribute(incept_mma,  cudaFuncAttributeMaxDynamicSharedMemorySize, INCEPT_SMEM);
    cudaFuncSetAttribute(skip_mma,    cudaFuncAttributeMaxDynamicSharedMemorySize, SKIP_SMEM);
    cudaFuncSetAttribute(prop_mma,    cudaFuncAttributeMaxDynamicSharedMemorySize, PROP_SMEM);
    cudaFuncSetAttribute(combine_mma, cudaFuncAttributeMaxDynamicSharedMemorySize, COMB_SMEM);

    pack_kernel<<<64, 256>>>(fw2, fw3, fw6, fw7, fb2, fb3, fb6, fb7,
                             gw2, gw3, gw6, gw7, gb2, gb3, gb6, gb7, skipw);
    adj_kernel<<<1024, 256>>>(adp);
    incept_mma<<<2000, 256, INCEPT_SMEM>>>(x);
    skip_mma<<<NV, 128, SKIP_SMEM>>>(skipb, s_out);
    prop_mma<<<dim3(NMCOL/128, 4, 2), 256, PROP_SMEM>>>(1);
    prop_mma<<<dim3(NMCOL/128, 4, 2), 256, PROP_SMEM>>>(2);
    combine_mma<<<2000, 256, COMB_SMEM>>>(x, gc1w, gc1b, gc2w, gc2b);
    norm_kernel<<<26000, 256>>>(idx, lnw, lnb, out);
}

// round 8
// speedup vs baseline: 4.1554x; 1.0398x over previous
#include <cuda_runtime.h>
#include <cuda_fp16.h>
#include <cstdint>

// ---------------- problem constants ----------------
#define NB   32
#define C_R  32
#define C_C  32
#define C_S  64
#define NV   500
#define NT   64
#define NK   52
#define NMCOL (NB*C_C*NK)   // 53248
#define VP   512
#define HVEC (C_C*NK)       // 1664
#define CNT_PER_B (C_C*NV*NK)

// ---------------- device scratch (zero-initialized) ----------------
__device__ float  g_a1f[VP*VP];
__device__ float  g_a2f[VP*VP];
__device__ __half g_B1h[2][VP*VP];
__device__ __half g_B2h[2][VP*VP];
__device__ float  g_rs[NV];
__device__ float  g_cs[NV];
__device__ __half g_swh[C_S*HVEC];
__device__ __half g_Wph[7*64*40];     // packed inception weights, SMEM-image layout
__device__ float  g_fbias[C_C];
__device__ float  g_gbias[C_C];
// rows (nodes) padded to 512; rows >=500 never written, stay zero
__device__ __half g_hh  [VP*NMCOL];
__device__ __half g_h1ah[VP*NMCOL];
__device__ __half g_h1bh[VP*NMCOL];
__device__ __half g_h2ah[VP*NMCOL];
__device__ __half g_h2bh[VP*NMCOL];
__device__ float  g_xo [NB*C_C*NV*NK];
__device__ float  g_stats[2*NB];

// ---------------- helpers ----------------
__device__ __forceinline__ uint32_t smem_u32(const void* p){
    uint32_t a; asm("{ .reg .u64 t; cvta.to.shared.u64 t, %1; cvt.u32.u64 %0, t; }":"=r"(a):"l"(p)); return a;
}
#define CP_ASYNC16(s,g) asm volatile("cp.async.cg.shared.global [%0], [%1], 16;"::"r"(s),"l"(g))
#define CP_COMMIT()     asm volatile("cp.async.commit_group;" ::: "memory")
#define CP_WAIT1()      asm volatile("cp.async.wait_group 1;" ::: "memory")
#define CP_WAIT0()      asm volatile("cp.async.wait_group 0;" ::: "memory")

__device__ __forceinline__ void ldmx4(uint32_t* r, uint32_t addr){
    asm volatile("ldmatrix.sync.aligned.m8n8.x4.shared.b16 {%0,%1,%2,%3}, [%4];"
        : "=r"(r[0]),"=r"(r[1]),"=r"(r[2]),"=r"(r[3]) : "r"(addr));
}
__device__ __forceinline__ void ldmx4t(uint32_t* r, uint32_t addr){
    asm volatile("ldmatrix.sync.aligned.m8n8.x4.trans.shared.b16 {%0,%1,%2,%3}, [%4];"
        : "=r"(r[0]),"=r"(r[1]),"=r"(r[2]),"=r"(r[3]) : "r"(addr));
}
__device__ __forceinline__ void mma_f16(float* c, const uint32_t* a, const uint32_t* b){
    asm volatile("mma.sync.aligned.m16n8k16.row.col.f32.f16.f16.f32 "
        "{%0,%1,%2,%3}, {%4,%5,%6,%7}, {%8,%9}, {%0,%1,%2,%3};"
        : "+f"(c[0]),"+f"(c[1]),"+f"(c[2]),"+f"(c[3])
        : "r"(a[0]),"r"(a[1]),"r"(a[2]),"r"(a[3]), "r"(b[0]),"r"(b[1]));
}
__device__ __forceinline__ float fast_tanh(float z){
    float e2 = __expf(fminf(-2.f*z, 40.f));
    return __fdividef(1.f - e2, 1.f + e2);
}
__device__ __forceinline__ float fast_sig(float z){
    return __fdividef(1.f, 1.f + __expf(fminf(-z, 40.f)));
}

// ---------------- pack: fp16 inception weights, half skip weights, zero sums/stats ----------------
__global__ void pack_kernel(const float* __restrict__ fw2,const float* __restrict__ fw3,
    const float* __restrict__ fw6,const float* __restrict__ fw7,
    const float* __restrict__ fb2,const float* __restrict__ fb3,
    const float* __restrict__ fb6,const float* __restrict__ fb7,
    const float* __restrict__ gw2,const float* __restrict__ gw3,
    const float* __restrict__ gw6,const float* __restrict__ gw7,
    const float* __restrict__ gb2,const float* __restrict__ gb3,
    const float* __restrict__ gb6,const float* __restrict__ gb7,
    const float* __restrict__ skipw)
{
    int tid = threadIdx.x;
    int gtid = blockIdx.x * blockDim.x + tid;
    for (int e = gtid; e < C_S*HVEC; e += gridDim.x * blockDim.x)
        g_swh[e] = __float2half_rn(skipw[e]);
    if (blockIdx.x != 0) return;
    if (tid < 2*NB) g_stats[tid] = 0.f;
    for (int e = tid; e < NV; e += blockDim.x) g_cs[e] = 0.f;
    for (int e = tid; e < 7*64*32; e += blockDim.x) {
        int j = e / 2048;
        int o = (e & 2047) >> 5;
        int i = e & 31;
        int oc = o & 31;
        int br = oc >> 3, oo = oc & 7;
        int k = (br==0)?2:(br==1)?3:(br==2)?6:7;
        int j0 = 7 - k;
        float vv = 0.f;
        if (j >= j0) {
            int si = (oo*C_R + i)*k + (j - j0);
            if (o < 32) {
                const float* fw = (br==0)?fw2:(br==1)?fw3:(br==2)?fw6:fw7;
                vv = fw[si];
            } else {
                const float* gw = (br==0)?gw2:(br==1)?gw3:(br==2)?gw6:gw7;
                vv = gw[si];
            }
        }
        g_Wph[(j*64 + o)*40 + i] = __float2half_rn(vv);
    }
    if (tid < C_C) {
        int br = tid >> 3, oo = tid & 7;
        const float* fb = (br==0)?fb2:(br==1)?fb3:(br==2)?fb6:fb7;
        const float* gb = (br==0)?gb2:(br==1)?gb3:(br==2)?gb6:gb7;
        g_fbias[tid] = fb[oo]; g_gbias[tid] = gb[oo];
    }
}

// ---------------- row sums (coalesced) + col sums (atomics) ----------------
__global__ void sums_kernel(const float* __restrict__ adp)
{
    int v = blockIdx.x;
    __shared__ float red[256];
    int tid = threadIdx.x;
    float s = 0.f;
    for (int w = tid; w < NV; w += 256) {
        float val = adp[v*NV + w];
        s += val;
        atomicAdd(&g_cs[w], val);
    }
    red[tid] = s; __syncthreads();
    for (int st = 128; st > 0; st >>= 1) {
        if (tid < st) red[tid] += red[tid + st];
        __syncthreads();
    }
    if (tid == 0) g_rs[v] = red[0] + 1.f;
}

// ---------------- build a1f/a2f fp32 (padded 512) + B1 fp16 for both sides ----------------
__global__ void buildAB_kernel(const float* __restrict__ adp)
{
    __shared__ float tile[32][33];
    int tid = threadIdx.x;
    int I = blockIdx.y*32, J = blockIdx.x*32;
    #pragma unroll
    for (int l = 0; l < 4; l++) {
        int ii = (tid >> 5) + l*8, jj = tid & 31;
        int r = I + ii, c = J + jj;
        tile[ii][jj] = (r < NV && c < NV) ? adp[r*NV + c] : 0.f;
    }
    __syncthreads();
    #pragma unroll
    for (int l = 0; l < 4; l++) {
        int ii = (tid >> 5) + l*8, jj = tid & 31;
        int r = I + ii, c = J + jj;
        float a1 = 0.f;
        if (r < NV && c < NV)
            a1 = (tile[ii][jj] + (r == c ? 1.f : 0.f)) * (1.f / g_rs[r]);
        g_a1f[r*VP + c] = a1;
        g_B1h[0][r*VP + c] = __float2half_rn(0.95f*a1 + ((r == c && r < NV) ? 0.05f : 0.f));
    }
    #pragma unroll
    for (int l = 0; l < 4; l++) {
        int ii = (tid >> 5) + l*8, jj = tid & 31;
        int rr = J + ii, cc = I + jj;      // a2f[rr][cc] = (adp[cc][rr]+d)/(cs[rr]+1)
        float a2 = 0.f;
        if (rr < NV && cc < NV)
            a2 = (tile[jj][ii] + (rr == cc ? 1.f : 0.f)) * (1.f / (g_cs[rr] + 1.f));
        g_a2f[rr*VP + cc] = a2;
        g_B1h[1][rr*VP + cc] = __float2half_rn(0.95f*a2 + ((rr == cc && rr < NV) ? 0.05f : 0.f));
    }
}

// ---------------- B2 = fp16(0.9025*A^2 + 0.0475*A + 0.05*I), both sides ----------------
__global__ void asq_kernel()
{
    const float* A = blockIdx.z ? g_a2f : g_a1f;
    __half* B2 = g_B2h[blockIdx.z];
    __shared__ float As[64][17];
    __shared__ float Bs[16][65];
    int tx = threadIdx.x, ty = threadIdx.y;
    int tid = ty*16 + tx;
    int vb = blockIdx.y*64, cb = blockIdx.x*64;
    float c[4][4];
    #pragma unroll
    for (int i = 0; i < 4; i++)
        #pragma unroll
        for (int j = 0; j < 4; j++) c[i][j] = 0.f;
    for (int k0 = 0; k0 < VP; k0 += 16) {
        #pragma unroll
        for (int i = 0; i < 4; i++) {
            int e = tid + i*256;
            int r = e >> 4, k = e & 15;
            As[r][k] = A[(vb + r)*VP + k0 + k];
        }
        #pragma unroll
        for (int i = 0; i < 4; i++) {
            int e = tid + i*256;
            int k = e >> 6, cc = e & 63;
            Bs[k][cc] = A[(k0 + k)*VP + cb + cc];
        }
        __syncthreads();
        #pragma unroll
        for (int k = 0; k < 16; k++) {
            float av[4], bv[4];
            #pragma unroll
            for (int i = 0; i < 4; i++) av[i] = As[ty*4 + i][k];
            #pragma unroll
            for (int j = 0; j < 4; j++) bv[j] = Bs[k][tx*4 + j];
            #pragma unroll
            for (int i = 0; i < 4; i++)
                #pragma unroll
                for (int j = 0; j < 4; j++)
                    c[i][j] = fmaf(av[i], bv[j], c[i][j]);
        }
        __syncthreads();
    }
    #pragma unroll
    for (int i = 0; i < 4; i++)
        #pragma unroll
        for (int j = 0; j < 4; j++) {
            int r = vb + ty*4 + i, cc = cb + tx*4 + j;
            float val = 0.9025f*c[i][j] + 0.0475f*A[r*VP + cc]
                      + ((r == cc && r < NV) ? 0.05f : 0.f);
            B2[r*VP + cc] = __float2half_rn(val);
        }
}

// ---------------- HMMA dilated inception + gating -> fp16 h ----------------
#define XST_ROWS 80
#define XST_STRB 80
#define XST_WARP (XST_ROWS*XST_STRB)
#define WP_STRB 80
#define WP_BYTES (7*64*WP_STRB)           // 35840 B
#define INCEPT_SMEM (WP_BYTES + 8*XST_WARP + 512)
__global__ __launch_bounds__(256,1) void incept_mma(const float* __restrict__ x)
{
    extern __shared__ __align__(16) char smi[];
    uint32_t sW = smem_u32(smi);
    uint32_t sX0 = sW + WP_BYTES;
    float* fbs = (float*)(smi + WP_BYTES + 8*XST_WARP);
    float* gbs = fbs + 32;

    int tid = threadIdx.x, warp = tid >> 5, lane = tid & 31;

    for (int e = tid; e < WP_BYTES/16; e += 256)
        *(float4*)(smi + e*16) = *(const float4*)(((const char*)g_Wph) + e*16);
    if (tid < 32) { fbs[tid] = g_fbias[tid]; gbs[tid] = g_gbias[tid]; }

    int p = blockIdx.x * 8 + warp;
    int n = p >> 5, b = p & 31;
    uint32_t sX = sX0 + warp*XST_WARP;
    {
        int i0 = (lane & 15) * 2;
        int t0 = (lane >> 4) * 32;
        const float* xr0 = &x[((size_t)(b*C_R + i0)*NV + n)*NT + t0];
        const float* xr1 = xr0 + (size_t)NV*NT;
        #pragma unroll
        for (int q = 0; q < 8; q++) {
            float4 v0 = *(const float4*)&xr0[q*4];
            float4 v1 = *(const float4*)&xr1[q*4];
            const float* a0 = &v0.x; const float* a1 = &v1.x;
            #pragma unroll
            for (int r = 0; r < 4; r++) {
                int t = t0 + q*4 + r;
                *(__half2*)(smi + (sX - smem_u32(smi)) + t*XST_STRB + i0*2) =
                    __floats2half2_rn(a0[r], a1[r]);
            }
        }
    }
    __syncthreads();

    float c[4][7][4];
    #pragma unroll
    for (int mi = 0; mi < 4; mi++)
        #pragma unroll
        for (int nt = 0; nt < 7; nt++)
            #pragma unroll
            for (int q = 0; q < 4; q++) c[mi][nt][q] = 0.f;

    #pragma unroll
    for (int j = 0; j < 7; j++) {
        uint32_t wbase = sW + j*64*WP_STRB;
        #pragma unroll
        for (int kst = 0; kst < 2; kst++) {
            int kb = (kst*16 + (lane >> 4)*8) * 2;
            uint32_t a[4][4];
            #pragma unroll
            for (int mi = 0; mi < 4; mi++)
                ldmx4(a[mi], wbase + (mi*16 + (lane & 15))*WP_STRB + kb);
            uint32_t bf[4][4];
            int kbb = (kst*16 + ((lane >> 3) & 1)*8) * 2;
            #pragma unroll
            for (int nb8 = 0; nb8 < 4; nb8++) {
                int trow = nb8*16 + (lane & 7) + ((lane >> 4) << 3) + 2*j;
                ldmx4(bf[nb8], sX + trow*XST_STRB + kbb);
            }
            #pragma unroll
            for (int mi = 0; mi < 4; mi++)
                #pragma unroll
                for (int nt = 0; nt < 7; nt++)
                    mma_f16(c[mi][nt], a[mi], &bf[nt >> 1][(nt & 1)*2]);
        }
    }

    int gr = lane >> 2, qc = (lane & 3)*2;
    __half* hout = &g_hh[(size_t)(n*NB + b)*HVEC];
    #pragma unroll
    for (int mi = 0; mi < 2; mi++) {
        #pragma unroll
        for (int hf = 0; hf < 2; hf++) {
            int o = mi*16 + gr + hf*8;
            float fb = fbs[o], gb = gbs[o];
            #pragma unroll
            for (int nt = 0; nt < 7; nt++) {
                int t = nt*8 + qc;
                if (t < NK) {
                    float h0 = fast_tanh(c[mi][nt][hf*2+0] + fb) * fast_sig(c[mi+2][nt][hf*2+0] + gb);
                    float h1 = fast_tanh(c[mi][nt][hf*2+1] + fb) * fast_sig(c[mi+2][nt][hf*2+1] + gb);
                    *(__half2*)&hout[o*NK + t] = __floats2half2_rn(h0, h1);
                }
            }
        }
    }
}

// ---------------- skip conv as per-node HMMA GEMM ----------------
#define SK_WBYTES (64*272)
#define SK_BBYTES (32*272)
#define SK_BUF (SK_WBYTES + SK_BBYTES)
#define SKIP_SMEM (2*SK_BUF)
__global__ __launch_bounds__(128) void skip_mma(const float* __restrict__ skipb,
                                                float* __restrict__ sout)
{
    extern __shared__ __align__(16) char sks[];
    int n = blockIdx.x;
    int tid = threadIdx.x, warp = tid >> 5, lane = tid & 31;
    int m0 = warp * 16;
    uint32_t sb = smem_u32(sks);

    const __half* Bg = &g_hh[(size_t)n*NMCOL];

    float c[4][4];
    #pragma unroll
    for (int i = 0; i < 4; i++)
        #pragma unroll
        for (int j = 0; j < 4; j++) c[i][j] = 0.f;

    auto load_chunk = [&](int buf, int ch) {
        int k0 = ch * 128;
        uint32_t sW = sb + buf*SK_BUF;
        uint32_t sB = sW + SK_WBYTES;
        #pragma unroll
        for (int j = 0; j < 8; j++) {
            int lin = tid + j*128;
            int r = lin >> 4, q = lin & 15;
            CP_ASYNC16(sW + r*272 + q*16, &g_swh[r*HVEC + k0 + q*8]);
        }
        #pragma unroll
        for (int j = 0; j < 4; j++) {
            int lin = tid + j*128;
            int r = lin >> 4, q = lin & 15;
            CP_ASYNC16(sB + r*272 + q*16, &Bg[r*HVEC + k0 + q*8]);
        }
        CP_COMMIT();
    };

    load_chunk(0, 0);
    load_chunk(1, 1);

    for (int ch = 0; ch < 13; ch++) {
        if (ch == 12) { CP_WAIT0(); } else { CP_WAIT1(); }
        __syncthreads();
        int buf = ch & 1;
        uint32_t sW = sb + buf*SK_BUF;
        uint32_t sB = sW + SK_WBYTES;
        #pragma unroll
        for (int ks = 0; ks < 8; ks++) {
            int k0 = ks * 16;
            uint32_t a[4];
            ldmx4(a, sW + (m0 + (lane & 15))*272 + (k0 + (lane >> 4)*8)*2);
            uint32_t bfr[2][4];
            #pragma unroll
            for (int np = 0; np < 2; np++)
                ldmx4(bfr[np], sB + (np*16 + (lane & 7) + ((lane >> 4) << 3))*272
                               + (k0 + ((lane >> 3) & 1)*8)*2);
            #pragma unroll
            for (int ni = 0; ni < 4; ni++)
                mma_f16(c[ni], a, &bfr[ni >> 1][(ni & 1)*2]);
        }
        __syncthreads();
        if (ch + 2 < 13) load_chunk(buf, ch + 2);
    }

    int gr = lane >> 2, qc = (lane & 3)*2;
    #pragma unroll
    for (int ni = 0; ni < 4; ni++) {
        int b0 = ni*8 + qc;
        int cs0 = m0 + gr;
        float bi0 = skipb[cs0], bi1 = skipb[cs0 + 8];
        sout[(b0*C_S + cs0)*NV + n]       = c[ni][0] + bi0;
        sout[((b0+1)*C_S + cs0)*NV + n]   = c[ni][1] + bi0;
        sout[(b0*C_S + cs0+8)*NV + n]     = c[ni][2] + bi1;
        sout[((b0+1)*C_S + cs0+8)*NV + n] = c[ni][3] + bi1;
    }
}

// ---------------- single-launch fp16 HMMA prop: {h1,h2} x {side a,b} = B{1,2}[side] @ h ----------------
#define PA_BYTES (128*80)
#define PB_BYTES (32*272)
#define PBUF (PA_BYTES + PB_BYTES)
#define PROP_SMEM (2*PBUF)
__global__ __launch_bounds__(256,2) void prop_mma()
{
    extern __shared__ __align__(16) char smp[];
    int z = blockIdx.z;
    int side = z >> 1, which = z & 1;
    const __half* Aadj = which ? g_B2h[side] : g_B1h[side];
    const __half* Bin = g_hh;
    __half* Hout = (z == 0) ? g_h1ah : (z == 1) ? g_h2ah : (z == 2) ? g_h1bh : g_h2bh;

    int tid = threadIdx.x, warp = tid >> 5, lane = tid & 31;
    int nbase = blockIdx.x * 128;
    int vt = blockIdx.y;
    int wm = (warp >> 2)*64, wn = (warp & 3)*32;
    uint32_t sb = smem_u32(smp);

    float c[4][4][4];
    #pragma unroll
    for (int i = 0; i < 4; i++)
        #pragma unroll
        for (int j = 0; j < 4; j++)
            #pragma unroll
            for (int q = 0; q < 4; q++) c[i][j][q] = 0.f;

    auto load_chunk = [&](int buf, int ch) {
        int w0 = ch * 32;
        uint32_t sA = sb + buf*PBUF;
        uint32_t sB = sA + PA_BYTES;
        #pragma unroll
        for (int j = 0; j < 2; j++) {
            int lin = tid + j*256;
            int r = lin >> 2, q = lin & 3;
            CP_ASYNC16(sA + r*80 + q*16, &Aadj[(vt*128 + r)*VP + w0 + q*8]);
        }
        #pragma unroll
        for (int j = 0; j < 2; j++) {
            int lin = tid + j*256;
            int r = lin >> 4, q = lin & 15;
            CP_ASYNC16(sB + r*272 + q*16, &Bin[(size_t)(w0 + r)*NMCOL + nbase + q*8]);
        }
        CP_COMMIT();
    };

    load_chunk(0, 0);
    load_chunk(1, 1);

    for (int ch = 0; ch < 16; ch++) {
        if (ch == 15) { CP_WAIT0(); } else { CP_WAIT1(); }
        __syncthreads();
        int buf = ch & 1;
        uint32_t sA = sb + buf*PBUF;
        uint32_t sB = sA + PA_BYTES;
        #pragma unroll
        for (int ks = 0; ks < 2; ks++) {
            int k0 = ks * 16;
            uint32_t a[4][4];
            #pragma unroll
            for (int mi = 0; mi < 4; mi++)
                ldmx4(a[mi], sA + (wm + mi*16 + (lane & 15))*80 + (k0 + (lane >> 4)*8)*2);
            uint32_t bfr[2][4];
            #pragma unroll
            for (int np = 0; np < 2; np++)
                ldmx4t(bfr[np], sB + (k0 + (lane & 15))*272 + (wn + np*16 + (lane >> 4)*8)*2);
            #pragma unroll
            for (int mi = 0; mi < 4; mi++)
                #pragma unroll
                for (int ni = 0; ni < 4; ni++)
                    mma_f16(c[mi][ni], a[mi], &bfr[ni >> 1][(ni & 1)*2]);
        }
        __syncthreads();
        if (ch + 2 < 16) load_chunk(buf, ch + 2);
    }

    // identity already folded into B1/B2 -> direct store
    int gr = lane >> 2, qc = (lane & 3)*2;
    #pragma unroll
    for (int mi = 0; mi < 4; mi++) {
        #pragma unroll
        for (int hf = 0; hf < 2; hf++) {
            int v = vt*128 + wm + mi*16 + gr + hf*8;
            if (v < NV) {
                #pragma unroll
                for (int ni = 0; ni < 4; ni++) {
                    size_t off = (size_t)v*NMCOL + nbase + wn + ni*8 + qc;
                    *(__half2*)&Hout[off] =
                        __floats2half2_rn(c[mi][ni][hf*2+0], c[mi][ni][hf*2+1]);
                }
            }
        }
    }
}

// ---------------- combine as per-(v,b) HMMA GEMM: out[c][l] = W[32x160] @ T[160x52] ----------------
#define CW_STRB 336
#define CW_BYTES (32*CW_STRB)              // 10752
#define CT_STRB 144
#define CT_WARP (160*CT_STRB)              // 23040 per warp
#define COMB_SMEM (CW_BYTES + 128 + 4*CT_WARP)
__global__ __launch_bounds__(128,2) void combine_mma(const float* __restrict__ x,
                                                     const float* __restrict__ gc1w,
                                                     const float* __restrict__ gc1b,
                                                     const float* __restrict__ gc2w,
                                                     const float* __restrict__ gc2b)
{
    extern __shared__ __align__(16) char smc[];
    uint32_t sW = smem_u32(smc);
    float* bias = (float*)(smc + CW_BYTES);
    uint32_t sT0 = sW + CW_BYTES + 128;

    int tid = threadIdx.x, warp = tid >> 5, lane = tid & 31;

    for (int e = tid; e < 5120; e += 128) {
        int cch = e / 160, k = e % 160;
        int t = k >> 5, cp = k & 31;
        float val;
        if      (t == 0) val = gc1w[cch*96 + cp] + gc2w[cch*96 + cp];
        else if (t == 1) val = gc1w[cch*96 + 32 + cp];
        else if (t == 2) val = gc1w[cch*96 + 64 + cp];
        else if (t == 3) val = gc2w[cch*96 + 32 + cp];
        else             val = gc2w[cch*96 + 64 + cp];
        *(__half*)(smc + cch*CW_STRB + k*2) = __float2half_rn(val);
    }
    if (tid < 32) bias[tid] = gc1b[tid] + gc2b[tid];

    int p = blockIdx.x * 4 + warp;
    int n = p >> 5, b = p & 31;
    uint32_t sT = sT0 + warp*CT_WARP;
    size_t slab_off = (size_t)(n*NB + b)*HVEC;
    for (int e = lane; e < 160*13; e += 32) {
        int r = e / 13, j = e % 13;
        const __half* slab = (r < 32) ? g_hh : (r < 64) ? g_h1ah : (r < 96) ? g_h2ah
                            : (r < 128) ? g_h1bh : g_h2bh;
        uint2 v = *(const uint2*)&slab[slab_off + (size_t)(r & 31)*NK + j*4];
        *(uint2*)((char*)smc + (sT - smem_u32(smc)) + r*CT_STRB + j*8) = v;
    }
    __syncthreads();

    float c[2][7][4];
    #pragma unroll
    for (int mi = 0; mi < 2; mi++)
        #pragma unroll
        for (int nt = 0; nt < 7; nt++)
            #pragma unroll
            for (int q = 0; q < 4; q++) c[mi][nt][q] = 0.f;

    #pragma unroll
    for (int ks = 0; ks < 10; ks++) {
        int k0 = ks * 16;
        uint32_t a[2][4];
        #pragma unroll
        for (int mi = 0; mi < 2; mi++)
            ldmx4(a[mi], sW + (mi*16 + (lane & 15))*CW_STRB + (k0 + (lane >> 4)*8)*2);
        uint32_t bq[4][4];
        #pragma unroll
        for (int nq = 0; nq < 4; nq++)
            ldmx4t(bq[nq], sT + (k0 + (lane & 15))*CT_STRB + (nq*16 + (lane >> 4)*8)*2);
        #pragma unroll
        for (int mi = 0; mi < 2; mi++)
            #pragma unroll
            for (int nt = 0; nt < 7; nt++)
                mma_f16(c[mi][nt], a[mi], &bq[nt >> 1][(nt & 1)*2]);
    }

    int gr = lane >> 2, qc = (lane & 3)*2;
    float psum = 0.f, psq = 0.f;
    #pragma unroll
    for (int mi = 0; mi < 2; mi++) {
        #pragma unroll
        for (int hf = 0; hf < 2; hf++) {
            int cch = mi*16 + gr + hf*8;
            float bi = bias[cch];
            const float* xr = &x[((size_t)(b*C_R + cch)*NV + n)*NT + 12];
            float* xor_ = &g_xo[((size_t)(b*C_C + cch)*NV + n)*NK];
            #pragma unroll
            for (int nt = 0; nt < 7; nt++) {
                int l = nt*8 + qc;
                if (l < NK) {
                    float v0 = c[mi][nt][hf*2+0] + bi + xr[l];
                    float v1 = c[mi][nt][hf*2+1] + bi + xr[l+1];
                    *(float2*)&xor_[l] = make_float2(v0, v1);
                    psum += v0 + v1;
                    psq  = fmaf(v0, v0, psq);
                    psq  = fmaf(v1, v1, psq);
                }
            }
        }
    }
    #pragma unroll
    for (int off = 16; off > 0; off >>= 1) {
        psum += __shfl_down_sync(0xffffffffu, psum, off);
        psq  += __shfl_down_sync(0xffffffffu, psq,  off);
    }
    if (lane == 0) {
        atomicAdd(&g_stats[2*b], psum);
        atomicAdd(&g_stats[2*b + 1], psq);
    }
}

// ---------------- LayerNorm apply ----------------
__global__ __launch_bounds__(256) void norm_kernel(const int* __restrict__ idx,
                                                   const float* __restrict__ lnw,
                                                   const float* __restrict__ lnb,
                                                   float* __restrict__ out)
{
    int gid = blockIdx.x * 256 + threadIdx.x;
    int lq = gid % 13;
    int row = gid / 13;
    int v = row % NV;
    int cch = (row / NV) % C_C;
    int b = row / (C_C*NV);

    float s1 = g_stats[2*b], s2 = g_stats[2*b + 1];
    float mean = s1 * (1.f/(float)CNT_PER_B);
    float var  = s2 * (1.f/(float)CNT_PER_B) - mean*mean;
    float rstd = rsqrtf(var + 1e-5f);
    int nidx = idx[v];

    float4 xo = *(const float4*)&g_xo[row*NK + lq*4];
    float4 w4 = *(const float4*)&lnw[(cch*NV + nidx)*NK + lq*4];
    float4 b4 = *(const float4*)&lnb[(cch*NV + nidx)*NK + lq*4];
    float4 o;
    o.x = (xo.x - mean)*rstd*w4.x + b4.x;
    o.y = (xo.y - mean)*rstd*w4.y + b4.y;
    o.z = (xo.z - mean)*rstd*w4.z + b4.z;
    o.w = (xo.w - mean)*rstd*w4.w + b4.w;
    *(float4*)&out[row*NK + lq*4] = o;
}

// ---------------- launch ----------------
extern "C" void kernel_launch(void* const* d_in, const int* in_sizes, int n_in,
                              void* d_out, int out_size)
{
    const float* x = (const float*)d_in[0];
    int ia = (in_sizes[1] == NV*NV) ? 1 : 2;
    const float* adp = (const float*)d_in[ia];
    const int*   idx = (const int*)d_in[3 - ia];
    const float* fw2 = (const float*)d_in[3];
    const float* fb2 = (const float*)d_in[4];
    const float* fw3 = (const float*)d_in[5];
    const float* fb3 = (const float*)d_in[6];
    const float* fw6 = (const float*)d_in[7];
    const float* fb6 = (const float*)d_in[8];
    const float* fw7 = (const float*)d_in[9];
    const float* fb7 = (const float*)d_in[10];
    const float* gw2 = (const float*)d_in[11];
    const float* gb2 = (const float*)d_in[12];
    const float* gw3 = (const float*)d_in[13];
    const float* gb3 = (const float*)d_in[14];
    const float* gw6 = (const float*)d_in[15];
    const float* gb6 = (const float*)d_in[16];
    const float* gw7 = (const float*)d_in[17];
    const float* gb7 = (const float*)d_in[18];
    const float* skipw = (const float*)d_in[19];
    const float* skipb = (const float*)d_in[20];
    const float* gc1w = (const float*)d_in[21];
    const float* gc1b = (const float*)d_in[22];
    const float* gc2w = (const float*)d_in[23];
    const float* gc2b = (const float*)d_in[24];
    const float* lnw = (const float*)d_in[25];
    const float* lnb = (const float*)d_in[26];
    float* out = (float*)d_out;
    float* s_out = out + NB*C_C*NV*NK;

    cudaFuncSetAttribute(incept_mma,  cudaFuncAttributeMaxDynamicSharedMemorySize, INCEPT_SMEM);
    cudaFuncSetAttribute(skip_mma,    cudaFuncAttributeMaxDynamicSharedMemorySize, SKIP_SMEM);
    cudaFuncSetAttribute(prop_mma,    cudaFuncAttributeMaxDynamicSharedMemorySize, PROP_SMEM);
    cudaFuncSetAttribute(combine_mma, cudaFuncAttributeMaxDynamicSharedMemorySize, COMB_SMEM);

    pack_kernel<<<64, 256>>>(fw2, fw3, fw6, fw7, fb2, fb3, fb6, fb7,
                             gw2, gw3, gw6, gw7, gb2, gb3, gb6, gb7, skipw);
    sums_kernel<<<NV, 256>>>(adp);
    buildAB_kernel<<<dim3(16, 16), 256>>>(adp);
    asq_kernel<<<dim3(8, 8, 2), dim3(16, 16)>>>();
    incept_mma<<<2000, 256, INCEPT_SMEM>>>(x);
    skip_mma<<<NV, 128, SKIP_SMEM>>>(skipb, s_out);
    prop_mma<<<dim3(NMCOL/128, 4, 4), 256, PROP_SMEM>>>();
    combine_mma<<<4000, 128, COMB_SMEM>>>(x, gc1w, gc1b, gc2w, gc2b);
    norm_kernel<<<26000, 256>>>(idx, lnw, lnb, out);
}

// round 9
// speedup vs baseline: 4.2900x; 1.0324x over previous
#include <cuda_runtime.h>
#include <cuda_fp16.h>
#include <cstdint>

// ---------------- problem constants ----------------
#define NB   32
#define C_R  32
#define C_C  32
#define C_S  64
#define NV   500
#define NT   64
#define NK   52
#define NMCOL (NB*C_C*NK)   // 53248
#define VP   512
#define HVEC (C_C*NK)       // 1664
#define CNT_PER_B (C_C*NV*NK)

// ---------------- device scratch (zero-initialized) ----------------
__device__ float  g_a1f[VP*VP];
__device__ float  g_a2f[VP*VP];
__device__ __half g_B1h[2][VP*VP];
__device__ __half g_B2h[2][VP*VP];
__device__ float  g_rs[NV];
__device__ float  g_cs[NV];
__device__ __half g_swh[C_S*HVEC];
__device__ __half g_Wph[7*64*40];     // packed inception weights, SMEM-image layout
__device__ float  g_fbias[C_C];
__device__ float  g_gbias[C_C];
// rows (nodes) padded to 512; rows >=500 never written, stay zero
__device__ __half g_hh  [VP*NMCOL];
__device__ __half g_h1ah[VP*NMCOL];
__device__ __half g_h1bh[VP*NMCOL];
__device__ __half g_h2ah[VP*NMCOL];
__device__ __half g_h2bh[VP*NMCOL];
__device__ float  g_xo [NB*C_C*NV*NK];
__device__ float  g_stats[2*NB];

// ---------------- helpers ----------------
__device__ __forceinline__ uint32_t smem_u32(const void* p){
    uint32_t a; asm("{ .reg .u64 t; cvta.to.shared.u64 t, %1; cvt.u32.u64 %0, t; }":"=r"(a):"l"(p)); return a;
}
#define CP_ASYNC16(s,g) asm volatile("cp.async.cg.shared.global [%0], [%1], 16;"::"r"(s),"l"(g))
#define CP_COMMIT()     asm volatile("cp.async.commit_group;" ::: "memory")
#define CP_WAIT1()      asm volatile("cp.async.wait_group 1;" ::: "memory")
#define CP_WAIT0()      asm volatile("cp.async.wait_group 0;" ::: "memory")

__device__ __forceinline__ void ldmx4(uint32_t* r, uint32_t addr){
    asm volatile("ldmatrix.sync.aligned.m8n8.x4.shared.b16 {%0,%1,%2,%3}, [%4];"
        : "=r"(r[0]),"=r"(r[1]),"=r"(r[2]),"=r"(r[3]) : "r"(addr));
}
__device__ __forceinline__ void ldmx4t(uint32_t* r, uint32_t addr){
    asm volatile("ldmatrix.sync.aligned.m8n8.x4.trans.shared.b16 {%0,%1,%2,%3}, [%4];"
        : "=r"(r[0]),"=r"(r[1]),"=r"(r[2]),"=r"(r[3]) : "r"(addr));
}
__device__ __forceinline__ void mma_f16(float* c, const uint32_t* a, const uint32_t* b){
    asm volatile("mma.sync.aligned.m16n8k16.row.col.f32.f16.f16.f32 "
        "{%0,%1,%2,%3}, {%4,%5,%6,%7}, {%8,%9}, {%0,%1,%2,%3};"
        : "+f"(c[0]),"+f"(c[1]),"+f"(c[2]),"+f"(c[3])
        : "r"(a[0]),"r"(a[1]),"r"(a[2]),"r"(a[3]), "r"(b[0]),"r"(b[1]));
}
__device__ __forceinline__ float fast_tanh(float z){
    float e2 = __expf(fminf(-2.f*z, 40.f));
    return __fdividef(1.f - e2, 1.f + e2);
}
__device__ __forceinline__ float fast_sig(float z){
    return __fdividef(1.f, 1.f + __expf(fminf(-z, 40.f)));
}

// ---------------- pack: fp16 inception weights, half skip weights, zero sums/stats ----------------
__global__ void pack_kernel(const float* __restrict__ fw2,const float* __restrict__ fw3,
    const float* __restrict__ fw6,const float* __restrict__ fw7,
    const float* __restrict__ fb2,const float* __restrict__ fb3,
    const float* __restrict__ fb6,const float* __restrict__ fb7,
    const float* __restrict__ gw2,const float* __restrict__ gw3,
    const float* __restrict__ gw6,const float* __restrict__ gw7,
    const float* __restrict__ gb2,const float* __restrict__ gb3,
    const float* __restrict__ gb6,const float* __restrict__ gb7,
    const float* __restrict__ skipw)
{
    int tid = threadIdx.x;
    int gtid = blockIdx.x * blockDim.x + tid;
    for (int e = gtid; e < C_S*HVEC; e += gridDim.x * blockDim.x)
        g_swh[e] = __float2half_rn(skipw[e]);
    if (blockIdx.x != 0) return;
    if (tid < 2*NB) g_stats[tid] = 0.f;
    for (int e = tid; e < NV; e += blockDim.x) g_cs[e] = 0.f;
    for (int e = tid; e < 7*64*32; e += blockDim.x) {
        int j = e / 2048;
        int o = (e & 2047) >> 5;
        int i = e & 31;
        int oc = o & 31;
        int br = oc >> 3, oo = oc & 7;
        int k = (br==0)?2:(br==1)?3:(br==2)?6:7;
        int j0 = 7 - k;
        float vv = 0.f;
        if (j >= j0) {
            int si = (oo*C_R + i)*k + (j - j0);
            if (o < 32) {
                const float* fw = (br==0)?fw2:(br==1)?fw3:(br==2)?fw6:fw7;
                vv = fw[si];
            } else {
                const float* gw = (br==0)?gw2:(br==1)?gw3:(br==2)?gw6:gw7;
                vv = gw[si];
            }
        }
        g_Wph[(j*64 + o)*40 + i] = __float2half_rn(vv);
    }
    if (tid < C_C) {
        int br = tid >> 3, oo = tid & 7;
        const float* fb = (br==0)?fb2:(br==1)?fb3:(br==2)?fb6:fb7;
        const float* gb = (br==0)?gb2:(br==1)?gb3:(br==2)?gb6:gb7;
        g_fbias[tid] = fb[oo]; g_gbias[tid] = gb[oo];
    }
}

// ---------------- row sums (coalesced) + col sums (atomics) ----------------
__global__ void sums_kernel(const float* __restrict__ adp)
{
    int v = blockIdx.x;
    __shared__ float red[256];
    int tid = threadIdx.x;
    float s = 0.f;
    for (int w = tid; w < NV; w += 256) {
        float val = adp[v*NV + w];
        s += val;
        atomicAdd(&g_cs[w], val);
    }
    red[tid] = s; __syncthreads();
    for (int st = 128; st > 0; st >>= 1) {
        if (tid < st) red[tid] += red[tid + st];
        __syncthreads();
    }
    if (tid == 0) g_rs[v] = red[0] + 1.f;
}

// ---------------- build a1f/a2f fp32 (padded 512) + B1 fp16 for both sides ----------------
__global__ void buildAB_kernel(const float* __restrict__ adp)
{
    __shared__ float tile[32][33];
    int tid = threadIdx.x;
    int I = blockIdx.y*32, J = blockIdx.x*32;
    #pragma unroll
    for (int l = 0; l < 4; l++) {
        int ii = (tid >> 5) + l*8, jj = tid & 31;
        int r = I + ii, c = J + jj;
        tile[ii][jj] = (r < NV && c < NV) ? adp[r*NV + c] : 0.f;
    }
    __syncthreads();
    #pragma unroll
    for (int l = 0; l < 4; l++) {
        int ii = (tid >> 5) + l*8, jj = tid & 31;
        int r = I + ii, c = J + jj;
        float a1 = 0.f;
        if (r < NV && c < NV)
            a1 = (tile[ii][jj] + (r == c ? 1.f : 0.f)) * (1.f / g_rs[r]);
        g_a1f[r*VP + c] = a1;
        g_B1h[0][r*VP + c] = __float2half_rn(0.95f*a1 + ((r == c && r < NV) ? 0.05f : 0.f));
    }
    #pragma unroll
    for (int l = 0; l < 4; l++) {
        int ii = (tid >> 5) + l*8, jj = tid & 31;
        int rr = J + ii, cc = I + jj;      // a2f[rr][cc] = (adp[cc][rr]+d)/(cs[rr]+1)
        float a2 = 0.f;
        if (rr < NV && cc < NV)
            a2 = (tile[jj][ii] + (rr == cc ? 1.f : 0.f)) * (1.f / (g_cs[rr] + 1.f));
        g_a2f[rr*VP + cc] = a2;
        g_B1h[1][rr*VP + cc] = __float2half_rn(0.95f*a2 + ((rr == cc && rr < NV) ? 0.05f : 0.f));
    }
}

// ---------------- B2 = fp16(0.9025*A^2 + 0.0475*A + 0.05*I), both sides ----------------
// 32x32 tiles, grid (16,16,2) = 512 blocks for full-chip occupancy
__global__ __launch_bounds__(256) void asq_kernel()
{
    const float* A = blockIdx.z ? g_a2f : g_a1f;
    __half* B2 = g_B2h[blockIdx.z];
    __shared__ float As[32][33];
    __shared__ float Bs[32][33];
    int tid = threadIdx.x;
    int tx = tid & 15, ty = tid >> 4;
    int vb = blockIdx.y*32, cb = blockIdx.x*32;
    float c[2][2] = {{0.f,0.f},{0.f,0.f}};
    for (int k0 = 0; k0 < VP; k0 += 32) {
        #pragma unroll
        for (int i = 0; i < 4; i++) {
            int e = tid + i*256;
            int r = e >> 5, k = e & 31;
            As[r][k] = A[(vb + r)*VP + k0 + k];
            Bs[r][k] = A[(k0 + r)*VP + cb + k];
        }
        __syncthreads();
        #pragma unroll
        for (int k = 0; k < 32; k++) {
            float a0 = As[ty*2][k],  a1 = As[ty*2+1][k];
            float b0 = Bs[k][tx*2],  b1 = Bs[k][tx*2+1];
            c[0][0] = fmaf(a0, b0, c[0][0]);
            c[0][1] = fmaf(a0, b1, c[0][1]);
            c[1][0] = fmaf(a1, b0, c[1][0]);
            c[1][1] = fmaf(a1, b1, c[1][1]);
        }
        __syncthreads();
    }
    #pragma unroll
    for (int i = 0; i < 2; i++)
        #pragma unroll
        for (int j = 0; j < 2; j++) {
            int r = vb + ty*2 + i, cc = cb + tx*2 + j;
            float val = 0.9025f*c[i][j] + 0.0475f*A[r*VP + cc]
                      + ((r == cc && r < NV) ? 0.05f : 0.f);
            B2[r*VP + cc] = __float2half_rn(val);
        }
}

// ---------------- HMMA dilated inception + gating -> fp16 h ----------------
#define XST_ROWS 80
#define XST_STRB 80
#define XST_WARP (XST_ROWS*XST_STRB)
#define WP_STRB 80
#define WP_BYTES (7*64*WP_STRB)           // 35840 B
#define INCEPT_SMEM (WP_BYTES + 4*XST_WARP + 512)
__global__ __launch_bounds__(128,2) void incept_mma(const float* __restrict__ x)
{
    extern __shared__ __align__(16) char smi[];
    uint32_t sW = smem_u32(smi);
    uint32_t sX0 = sW + WP_BYTES;
    float* fbs = (float*)(smi + WP_BYTES + 4*XST_WARP);
    float* gbs = fbs + 32;

    int tid = threadIdx.x, warp = tid >> 5, lane = tid & 31;

    for (int e = tid; e < WP_BYTES/16; e += 128)
        *(float4*)(smi + e*16) = *(const float4*)(((const char*)g_Wph) + e*16);
    if (tid < 32) { fbs[tid] = g_fbias[tid]; gbs[tid] = g_gbias[tid]; }

    int p = blockIdx.x * 4 + warp;
    int n = p >> 5, b = p & 31;
    uint32_t sX = sX0 + warp*XST_WARP;
    {
        int i0 = (lane & 15) * 2;
        int t0 = (lane >> 4) * 32;
        const float* xr0 = &x[((size_t)(b*C_R + i0)*NV + n)*NT + t0];
        const float* xr1 = xr0 + (size_t)NV*NT;
        #pragma unroll
        for (int q = 0; q < 8; q++) {
            float4 v0 = *(const float4*)&xr0[q*4];
            float4 v1 = *(const float4*)&xr1[q*4];
            const float* a0 = &v0.x; const float* a1 = &v1.x;
            #pragma unroll
            for (int r = 0; r < 4; r++) {
                int t = t0 + q*4 + r;
                *(__half2*)(smi + (sX - smem_u32(smi)) + t*XST_STRB + i0*2) =
                    __floats2half2_rn(a0[r], a1[r]);
            }
        }
    }
    __syncthreads();

    float c[4][7][4];
    #pragma unroll
    for (int mi = 0; mi < 4; mi++)
        #pragma unroll
        for (int nt = 0; nt < 7; nt++)
            #pragma unroll
            for (int q = 0; q < 4; q++) c[mi][nt][q] = 0.f;

    #pragma unroll
    for (int j = 0; j < 7; j++) {
        uint32_t wbase = sW + j*64*WP_STRB;
        #pragma unroll
        for (int kst = 0; kst < 2; kst++) {
            int kb = (kst*16 + (lane >> 4)*8) * 2;
            uint32_t a[4][4];
            #pragma unroll
            for (int mi = 0; mi < 4; mi++)
                ldmx4(a[mi], wbase + (mi*16 + (lane & 15))*WP_STRB + kb);
            uint32_t bf[4][4];
            int kbb = (kst*16 + ((lane >> 3) & 1)*8) * 2;
            #pragma unroll
            for (int nb8 = 0; nb8 < 4; nb8++) {
                int trow = nb8*16 + (lane & 7) + ((lane >> 4) << 3) + 2*j;
                ldmx4(bf[nb8], sX + trow*XST_STRB + kbb);
            }
            #pragma unroll
            for (int mi = 0; mi < 4; mi++)
                #pragma unroll
                for (int nt = 0; nt < 7; nt++)
                    mma_f16(c[mi][nt], a[mi], &bf[nt >> 1][(nt & 1)*2]);
        }
    }

    int gr = lane >> 2, qc = (lane & 3)*2;
    __half* hout = &g_hh[(size_t)(n*NB + b)*HVEC];
    #pragma unroll
    for (int mi = 0; mi < 2; mi++) {
        #pragma unroll
        for (int hf = 0; hf < 2; hf++) {
            int o = mi*16 + gr + hf*8;
            float fb = fbs[o], gb = gbs[o];
            #pragma unroll
            for (int nt = 0; nt < 7; nt++) {
                int t = nt*8 + qc;
                if (t < NK) {
                    float h0 = fast_tanh(c[mi][nt][hf*2+0] + fb) * fast_sig(c[mi+2][nt][hf*2+0] + gb);
                    float h1 = fast_tanh(c[mi][nt][hf*2+1] + fb) * fast_sig(c[mi+2][nt][hf*2+1] + gb);
                    *(__half2*)&hout[o*NK + t] = __floats2half2_rn(h0, h1);
                }
            }
        }
    }
}

// ---------------- skip conv as per-node HMMA GEMM ----------------
#define SK_WBYTES (64*272)
#define SK_BBYTES (32*272)
#define SK_BUF (SK_WBYTES + SK_BBYTES)
#define SKIP_SMEM (2*SK_BUF)
__global__ __launch_bounds__(128) void skip_mma(const float* __restrict__ skipb,
                                                float* __restrict__ sout)
{
    extern __shared__ __align__(16) char sks[];
    int n = blockIdx.x;
    int tid = threadIdx.x, warp = tid >> 5, lane = tid & 31;
    int m0 = warp * 16;
    uint32_t sb = smem_u32(sks);

    const __half* Bg = &g_hh[(size_t)n*NMCOL];

    float c[4][4];
    #pragma unroll
    for (int i = 0; i < 4; i++)
        #pragma unroll
        for (int j = 0; j < 4; j++) c[i][j] = 0.f;

    auto load_chunk = [&](int buf, int ch) {
        int k0 = ch * 128;
        uint32_t sW = sb + buf*SK_BUF;
        uint32_t sB = sW + SK_WBYTES;
        #pragma unroll
        for (int j = 0; j < 8; j++) {
            int lin = tid + j*128;
            int r = lin >> 4, q = lin & 15;
            CP_ASYNC16(sW + r*272 + q*16, &g_swh[r*HVEC + k0 + q*8]);
        }
        #pragma unroll
        for (int j = 0; j < 4; j++) {
            int lin = tid + j*128;
            int r = lin >> 4, q = lin & 15;
            CP_ASYNC16(sB + r*272 + q*16, &Bg[r*HVEC + k0 + q*8]);
        }
        CP_COMMIT();
    };

    load_chunk(0, 0);
    load_chunk(1, 1);

    for (int ch = 0; ch < 13; ch++) {
        if (ch == 12) { CP_WAIT0(); } else { CP_WAIT1(); }
        __syncthreads();
        int buf = ch & 1;
        uint32_t sW = sb + buf*SK_BUF;
        uint32_t sB = sW + SK_WBYTES;
        #pragma unroll
        for (int ks = 0; ks < 8; ks++) {
            int k0 = ks * 16;
            uint32_t a[4];
            ldmx4(a, sW + (m0 + (lane & 15))*272 + (k0 + (lane >> 4)*8)*2);
            uint32_t bfr[2][4];
            #pragma unroll
            for (int np = 0; np < 2; np++)
                ldmx4(bfr[np], sB + (np*16 + (lane & 7) + ((lane >> 4) << 3))*272
                               + (k0 + ((lane >> 3) & 1)*8)*2);
            #pragma unroll
            for (int ni = 0; ni < 4; ni++)
                mma_f16(c[ni], a, &bfr[ni >> 1][(ni & 1)*2]);
        }
        __syncthreads();
        if (ch + 2 < 13) load_chunk(buf, ch + 2);
    }

    int gr = lane >> 2, qc = (lane & 3)*2;
    #pragma unroll
    for (int ni = 0; ni < 4; ni++) {
        int b0 = ni*8 + qc;
        int cs0 = m0 + gr;
        float bi0 = skipb[cs0], bi1 = skipb[cs0 + 8];
        sout[(b0*C_S + cs0)*NV + n]       = c[ni][0] + bi0;
        sout[((b0+1)*C_S + cs0)*NV + n]   = c[ni][1] + bi0;
        sout[(b0*C_S + cs0+8)*NV + n]     = c[ni][2] + bi1;
        sout[((b0+1)*C_S + cs0+8)*NV + n] = c[ni][3] + bi1;
    }
}

// ---------------- single-launch fp16 HMMA prop (BK=64): {h1,h2} x {a,b} = B{1,2}[side] @ h ----------------
#define PA_STRB 144
#define PA_BYTES (128*PA_STRB)     // 18432
#define PB_STRB 272
#define PB_BYTES (64*PB_STRB)      // 17408
#define PBUF (PA_BYTES + PB_BYTES) // 35840
#define PROP_SMEM (2*PBUF)
__global__ __launch_bounds__(256,2) void prop_mma()
{
    extern __shared__ __align__(16) char smp[];
    int z = blockIdx.z;
    int side = z >> 1, which = z & 1;
    const __half* Aadj = which ? g_B2h[side] : g_B1h[side];
    const __half* Bin = g_hh;
    __half* Hout = (z == 0) ? g_h1ah : (z == 1) ? g_h2ah : (z == 2) ? g_h1bh : g_h2bh;

    int tid = threadIdx.x, warp = tid >> 5, lane = tid & 31;
    int nbase = blockIdx.x * 128;
    int vt = blockIdx.y;
    int wm = (warp >> 2)*64, wn = (warp & 3)*32;
    uint32_t sb = smem_u32(smp);

    float c[4][4][4];
    #pragma unroll
    for (int i = 0; i < 4; i++)
        #pragma unroll
        for (int j = 0; j < 4; j++)
            #pragma unroll
            for (int q = 0; q < 4; q++) c[i][j][q] = 0.f;

    auto load_chunk = [&](int buf, int ch) {
        int w0 = ch * 64;
        uint32_t sA = sb + buf*PBUF;
        uint32_t sB = sA + PA_BYTES;
        #pragma unroll
        for (int j = 0; j < 4; j++) {
            int lin = tid + j*256;
            int r = lin >> 3, q = lin & 7;
            CP_ASYNC16(sA + r*PA_STRB + q*16, &Aadj[(vt*128 + r)*VP + w0 + q*8]);
        }
        #pragma unroll
        for (int j = 0; j < 4; j++) {
            int lin = tid + j*256;
            int r = lin >> 4, q = lin & 15;
            CP_ASYNC16(sB + r*PB_STRB + q*16, &Bin[(size_t)(w0 + r)*NMCOL + nbase + q*8]);
        }
        CP_COMMIT();
    };

    load_chunk(0, 0);
    load_chunk(1, 1);

    for (int ch = 0; ch < 8; ch++) {
        if (ch == 7) { CP_WAIT0(); } else { CP_WAIT1(); }
        __syncthreads();
        int buf = ch & 1;
        uint32_t sA = sb + buf*PBUF;
        uint32_t sB = sA + PA_BYTES;
        #pragma unroll
        for (int ks = 0; ks < 4; ks++) {
            int k0 = ks * 16;
            uint32_t a[4][4];
            #pragma unroll
            for (int mi = 0; mi < 4; mi++)
                ldmx4(a[mi], sA + (wm + mi*16 + (lane & 15))*PA_STRB + (k0 + (lane >> 4)*8)*2);
            uint32_t bfr[2][4];
            #pragma unroll
            for (int np = 0; np < 2; np++)
                ldmx4t(bfr[np], sB + (k0 + (lane & 15))*PB_STRB + (wn + np*16 + (lane >> 4)*8)*2);
            #pragma unroll
            for (int mi = 0; mi < 4; mi++)
                #pragma unroll
                for (int ni = 0; ni < 4; ni++)
                    mma_f16(c[mi][ni], a[mi], &bfr[ni >> 1][(ni & 1)*2]);
        }
        __syncthreads();
        if (ch + 2 < 8) load_chunk(buf, ch + 2);
    }

    // identity already folded into B1/B2 -> direct store
    int gr = lane >> 2, qc = (lane & 3)*2;
    #pragma unroll
    for (int mi = 0; mi < 4; mi++) {
        #pragma unroll
        for (int hf = 0; hf < 2; hf++) {
            int v = vt*128 + wm + mi*16 + gr + hf*8;
            if (v < NV) {
                #pragma unroll
                for (int ni = 0; ni < 4; ni++) {
                    size_t off = (size_t)v*NMCOL + nbase + wn + ni*8 + qc;
                    *(__half2*)&Hout[off] =
                        __floats2half2_rn(c[mi][ni][hf*2+0], c[mi][ni][hf*2+1]);
                }
            }
        }
    }
}

// ---------------- combine as per-(v,b) HMMA GEMM: out[c][l] = W[32x160] @ T[160x52] ----------------
#define CW_STRB 336
#define CW_BYTES (32*CW_STRB)              // 10752
#define CT_STRB 144
#define CT_WARP (160*CT_STRB)              // 23040 per warp
#define COMB_SMEM (CW_BYTES + 128 + 4*CT_WARP)
__global__ __launch_bounds__(128,2) void combine_mma(const float* __restrict__ x,
                                                     const float* __restrict__ gc1w,
                                                     const float* __restrict__ gc1b,
                                                     const float* __restrict__ gc2w,
                                                     const float* __restrict__ gc2b)
{
    extern __shared__ __align__(16) char smc[];
    uint32_t sW = smem_u32(smc);
    float* bias = (float*)(smc + CW_BYTES);
    uint32_t sT0 = sW + CW_BYTES + 128;

    int tid = threadIdx.x, warp = tid >> 5, lane = tid & 31;

    for (int e = tid; e < 5120; e += 128) {
        int cch = e / 160, k = e % 160;
        int t = k >> 5, cp = k & 31;
        float val;
        if      (t == 0) val = gc1w[cch*96 + cp] + gc2w[cch*96 + cp];
        else if (t == 1) val = gc1w[cch*96 + 32 + cp];
        else if (t == 2) val = gc1w[cch*96 + 64 + cp];
        else if (t == 3) val = gc2w[cch*96 + 32 + cp];
        else             val = gc2w[cch*96 + 64 + cp];
        *(__half*)(smc + cch*CW_STRB + k*2) = __float2half_rn(val);
    }
    if (tid < 32) bias[tid] = gc1b[tid] + gc2b[tid];

    int p = blockIdx.x * 4 + warp;
    int n = p >> 5, b = p & 31;
    uint32_t sT = sT0 + warp*CT_WARP;
    size_t slab_off = (size_t)(n*NB + b)*HVEC;
    for (int e = lane; e < 160*13; e += 32) {
        int r = e / 13, j = e % 13;
        const __half* slab = (r < 32) ? g_hh : (r < 64) ? g_h1ah : (r < 96) ? g_h2ah
                            : (r < 128) ? g_h1bh : g_h2bh;
        uint2 v = *(const uint2*)&slab[slab_off + (size_t)(r & 31)*NK + j*4];
        *(uint2*)((char*)smc + (sT - smem_u32(smc)) + r*CT_STRB + j*8) = v;
    }
    __syncthreads();

    float c[2][7][4];
    #pragma unroll
    for (int mi = 0; mi < 2; mi++)
        #pragma unroll
        for (int nt = 0; nt < 7; nt++)
            #pragma unroll
            for (int q = 0; q < 4; q++) c[mi][nt][q] = 0.f;

    #pragma unroll
    for (int ks = 0; ks < 10; ks++) {
        int k0 = ks * 16;
        uint32_t a[2][4];
        #pragma unroll
        for (int mi = 0; mi < 2; mi++)
            ldmx4(a[mi], sW + (mi*16 + (lane & 15))*CW_STRB + (k0 + (lane >> 4)*8)*2);
        uint32_t bq[4][4];
        #pragma unroll
        for (int nq = 0; nq < 4; nq++)
            ldmx4t(bq[nq], sT + (k0 + (lane & 15))*CT_STRB + (nq*16 + (lane >> 4)*8)*2);
        #pragma unroll
        for (int mi = 0; mi < 2; mi++)
            #pragma unroll
            for (int nt = 0; nt < 7; nt++)
                mma_f16(c[mi][nt], a[mi], &bq[nt >> 1][(nt & 1)*2]);
    }

    int gr = lane >> 2, qc = (lane & 3)*2;
    float psum = 0.f, psq = 0.f;
    #pragma unroll
    for (int mi = 0; mi < 2; mi++) {
        #pragma unroll
        for (int hf = 0; hf < 2; hf++) {
            int cch = mi*16 + gr + hf*8;
            float bi = bias[cch];
            const float* xr = &x[((size_t)(b*C_R + cch)*NV + n)*NT + 12];
            float* xor_ = &g_xo[((size_t)(b*C_C + cch)*NV + n)*NK];
            #pragma unroll
            for (int nt = 0; nt < 7; nt++) {
                int l = nt*8 + qc;
                if (l < NK) {
                    float v0 = c[mi][nt][hf*2+0] + bi + xr[l];
                    float v1 = c[mi][nt][hf*2+1] + bi + xr[l+1];
                    *(float2*)&xor_[l] = make_float2(v0, v1);
                    psum += v0 + v1;
                    psq  = fmaf(v0, v0, psq);
                    psq  = fmaf(v1, v1, psq);
                }
            }
        }
    }
    #pragma unroll
    for (int off = 16; off > 0; off >>= 1) {
        psum += __shfl_down_sync(0xffffffffu, psum, off);
        psq  += __shfl_down_sync(0xffffffffu, psq,  off);
    }
    if (lane == 0) {
        atomicAdd(&g_stats[2*b], psum);
        atomicAdd(&g_stats[2*b + 1], psq);
    }
}

// ---------------- LayerNorm apply ----------------
__global__ __launch_bounds__(256) void norm_kernel(const int* __restrict__ idx,
                                                   const float* __restrict__ lnw,
                                                   const float* __restrict__ lnb,
                                                   float* __restrict__ out)
{
    int gid = blockIdx.x * 256 + threadIdx.x;
    int lq = gid % 13;
    int row = gid / 13;
    int v = row % NV;
    int cch = (row / NV) % C_C;
    int b = row / (C_C*NV);

    float s1 = g_stats[2*b], s2 = g_stats[2*b + 1];
    float mean = s1 * (1.f/(float)CNT_PER_B);
    float var  = s2 * (1.f/(float)CNT_PER_B) - mean*mean;
    float rstd = rsqrtf(var + 1e-5f);
    int nidx = idx[v];

    float4 xo = *(const float4*)&g_xo[row*NK + lq*4];
    float4 w4 = *(const float4*)&lnw[(cch*NV + nidx)*NK + lq*4];
    float4 b4 = *(const float4*)&lnb[(cch*NV + nidx)*NK + lq*4];
    float4 o;
    o.x = (xo.x - mean)*rstd*w4.x + b4.x;
    o.y = (xo.y - mean)*rstd*w4.y + b4.y;
    o.z = (xo.z - mean)*rstd*w4.z + b4.z;
    o.w = (xo.w - mean)*rstd*w4.w + b4.w;
    *(float4*)&out[row*NK + lq*4] = o;
}

// ---------------- launch ----------------
extern "C" void kernel_launch(void* const* d_in, const int* in_sizes, int n_in,
                              void* d_out, int out_size)
{
    const float* x = (const float*)d_in[0];
    int ia = (in_sizes[1] == NV*NV) ? 1 : 2;
    const float* adp = (const float*)d_in[ia];
    const int*   idx = (const int*)d_in[3 - ia];
    const float* fw2 = (const float*)d_in[3];
    const float* fb2 = (const float*)d_in[4];
    const float* fw3 = (const float*)d_in[5];
    const float* fb3 = (const float*)d_in[6];
    const float* fw6 = (const float*)d_in[7];
    const float* fb6 = (const float*)d_in[8];
    const float* fw7 = (const float*)d_in[9];
    const float* fb7 = (const float*)d_in[10];
    const float* gw2 = (const float*)d_in[11];
    const float* gb2 = (const float*)d_in[12];
    const float* gw3 = (const float*)d_in[13];
    const float* gb3 = (const float*)d_in[14];
    const float* gw6 = (const float*)d_in[15];
    const float* gb6 = (const float*)d_in[16];
    const float* gw7 = (const float*)d_in[17];
    const float* gb7 = (const float*)d_in[18];
    const float* skipw = (const float*)d_in[19];
    const float* skipb = (const float*)d_in[20];
    const float* gc1w = (const float*)d_in[21];
    const float* gc1b = (const float*)d_in[22];
    const float* gc2w = (const float*)d_in[23];
    const float* gc2b = (const float*)d_in[24];
    const float* lnw = (const float*)d_in[25];
    const float* lnb = (const float*)d_in[26];
    float* out = (float*)d_out;
    float* s_out = out + NB*C_C*NV*NK;

    cudaFuncSetAttribute(incept_mma,  cudaFuncAttributeMaxDynamicSharedMemorySize, INCEPT_SMEM);
    cudaFuncSetAttribute(skip_mma,    cudaFuncAttributeMaxDynamicSharedMemorySize, SKIP_SMEM);
    cudaFuncSetAttribute(prop_mma,    cudaFuncAttributeMaxDynamicSharedMemorySize, PROP_SMEM);
    cudaFuncSetAttribute(combine_mma, cudaFuncAttributeMaxDynamicSharedMemorySize, COMB_SMEM);

    pack_kernel<<<64, 256>>>(fw2, fw3, fw6, fw7, fb2, fb3, fb6, fb7,
                             gw2, gw3, gw6, gw7, gb2, gb3, gb6, gb7, skipw);
    sums_kernel<<<NV, 256>>>(adp);
    buildAB_kernel<<<dim3(16, 16), 256>>>(adp);
    asq_kernel<<<dim3(16, 16, 2), 256>>>();
    incept_mma<<<4000, 128, INCEPT_SMEM>>>(x);
    skip_mma<<<NV, 128, SKIP_SMEM>>>(skipb, s_out);
    prop_mma<<<dim3(NMCOL/128, 4, 4), 256, PROP_SMEM>>>();
    combine_mma<<<4000, 128, COMB_SMEM>>>(x, gc1w, gc1b, gc2w, gc2b);
    norm_kernel<<<26000, 256>>>(idx, lnw, lnb, out);
}

// round 10
// speedup vs baseline: 4.3630x; 1.0170x over previous
#include <cuda_runtime.h>
#include <cuda_fp16.h>
#include <cstdint>

// ---------------- problem constants ----------------
#define NB   32
#define C_R  32
#define C_C  32
#define C_S  64
#define NV   500
#define NT   64
#define NK   52
#define NMCOL (NB*C_C*NK)   // 53248
#define VP   512
#define HVEC (C_C*NK)       // 1664
#define CNT_PER_B (C_C*NV*NK)

// ---------------- device scratch (zero-initialized) ----------------
__device__ float  g_a1f[VP*VP];
__device__ float  g_a2f[VP*VP];
__device__ __half g_B1h[2][VP*VP];
__device__ __half g_B2h[2][VP*VP];
__device__ float  g_A2p[8][VP*VP];    // A^2 k-split partials (side*4 + kc)
__device__ float  g_rs[NV];
__device__ float  g_cs[NV];
__device__ __half g_swh[C_S*HVEC];
__device__ __half g_Wph[7*64*40];     // packed inception weights, SMEM-image layout
__device__ float  g_fbias[C_C];
__device__ float  g_gbias[C_C];
// rows (nodes) padded to 512; rows >=500 never written, stay zero
__device__ __half g_hh  [VP*NMCOL];
__device__ __half g_h1ah[VP*NMCOL];
__device__ __half g_h1bh[VP*NMCOL];
__device__ __half g_h2ah[VP*NMCOL];
__device__ __half g_h2bh[VP*NMCOL];
__device__ __half g_xoh[NB*C_C*NV*NK];
__device__ float  g_stats[2*NB];

// ---------------- helpers ----------------
__device__ __forceinline__ uint32_t smem_u32(const void* p){
    uint32_t a; asm("{ .reg .u64 t; cvta.to.shared.u64 t, %1; cvt.u32.u64 %0, t; }":"=r"(a):"l"(p)); return a;
}
#define CP_ASYNC16(s,g) asm volatile("cp.async.cg.shared.global [%0], [%1], 16;"::"r"(s),"l"(g))
#define CP_COMMIT()     asm volatile("cp.async.commit_group;" ::: "memory")
#define CP_WAIT1()      asm volatile("cp.async.wait_group 1;" ::: "memory")
#define CP_WAIT0()      asm volatile("cp.async.wait_group 0;" ::: "memory")

__device__ __forceinline__ void ldmx4(uint32_t* r, uint32_t addr){
    asm volatile("ldmatrix.sync.aligned.m8n8.x4.shared.b16 {%0,%1,%2,%3}, [%4];"
        : "=r"(r[0]),"=r"(r[1]),"=r"(r[2]),"=r"(r[3]) : "r"(addr));
}
__device__ __forceinline__ void ldmx4t(uint32_t* r, uint32_t addr){
    asm volatile("ldmatrix.sync.aligned.m8n8.x4.trans.shared.b16 {%0,%1,%2,%3}, [%4];"
        : "=r"(r[0]),"=r"(r[1]),"=r"(r[2]),"=r"(r[3]) : "r"(addr));
}
__device__ __forceinline__ void mma_f16(float* c, const uint32_t* a, const uint32_t* b){
    asm volatile("mma.sync.aligned.m16n8k16.row.col.f32.f16.f16.f32 "
        "{%0,%1,%2,%3}, {%4,%5,%6,%7}, {%8,%9}, {%0,%1,%2,%3};"
        : "+f"(c[0]),"+f"(c[1]),"+f"(c[2]),"+f"(c[3])
        : "r"(a[0]),"r"(a[1]),"r"(a[2]),"r"(a[3]), "r"(b[0]),"r"(b[1]));
}
__device__ __forceinline__ float fast_tanh(float z){
    float e2 = __expf(fminf(-2.f*z, 40.f));
    return __fdividef(1.f - e2, 1.f + e2);
}
__device__ __forceinline__ float fast_sig(float z){
    return __fdividef(1.f, 1.f + __expf(fminf(-z, 40.f)));
}

// ---------------- pack: fp16 inception weights, half skip weights, zero sums/stats ----------------
__global__ void pack_kernel(const float* __restrict__ fw2,const float* __restrict__ fw3,
    const float* __restrict__ fw6,const float* __restrict__ fw7,
    const float* __restrict__ fb2,const float* __restrict__ fb3,
    const float* __restrict__ fb6,const float* __restrict__ fb7,
    const float* __restrict__ gw2,const float* __restrict__ gw3,
    const float* __restrict__ gw6,const float* __restrict__ gw7,
    const float* __restrict__ gb2,const float* __restrict__ gb3,
    const float* __restrict__ gb6,const float* __restrict__ gb7,
    const float* __restrict__ skipw)
{
    int tid = threadIdx.x;
    int gtid = blockIdx.x * blockDim.x + tid;
    for (int e = gtid; e < C_S*HVEC; e += gridDim.x * blockDim.x)
        g_swh[e] = __float2half_rn(skipw[e]);
    if (blockIdx.x != 0) return;
    if (tid < 2*NB) g_stats[tid] = 0.f;
    for (int e = tid; e < NV; e += blockDim.x) g_cs[e] = 0.f;
    for (int e = tid; e < 7*64*32; e += blockDim.x) {
        int j = e / 2048;
        int o = (e & 2047) >> 5;
        int i = e & 31;
        int oc = o & 31;
        int br = oc >> 3, oo = oc & 7;
        int k = (br==0)?2:(br==1)?3:(br==2)?6:7;
        int j0 = 7 - k;
        float vv = 0.f;
        if (j >= j0) {
            int si = (oo*C_R + i)*k + (j - j0);
            if (o < 32) {
                const float* fw = (br==0)?fw2:(br==1)?fw3:(br==2)?fw6:fw7;
                vv = fw[si];
            } else {
                const float* gw = (br==0)?gw2:(br==1)?gw3:(br==2)?gw6:gw7;
                vv = gw[si];
            }
        }
        g_Wph[(j*64 + o)*40 + i] = __float2half_rn(vv);
    }
    if (tid < C_C) {
        int br = tid >> 3, oo = tid & 7;
        const float* fb = (br==0)?fb2:(br==1)?fb3:(br==2)?fb6:fb7;
        const float* gb = (br==0)?gb2:(br==1)?gb3:(br==2)?gb6:gb7;
        g_fbias[tid] = fb[oo]; g_gbias[tid] = gb[oo];
    }
}

// ---------------- row sums (coalesced) + col sums (atomics) ----------------
__global__ void sums_kernel(const float* __restrict__ adp)
{
    int v = blockIdx.x;
    __shared__ float red[256];
    int tid = threadIdx.x;
    float s = 0.f;
    for (int w = tid; w < NV; w += 256) {
        float val = adp[v*NV + w];
        s += val;
        atomicAdd(&g_cs[w], val);
    }
    red[tid] = s; __syncthreads();
    for (int st = 128; st > 0; st >>= 1) {
        if (tid < st) red[tid] += red[tid + st];
        __syncthreads();
    }
    if (tid == 0) g_rs[v] = red[0] + 1.f;
}

// ---------------- build a1f/a2f fp32 (padded 512) + B1 fp16 for both sides ----------------
__global__ void buildAB_kernel(const float* __restrict__ adp)
{
    __shared__ float tile[32][33];
    int tid = threadIdx.x;
    int I = blockIdx.y*32, J = blockIdx.x*32;
    #pragma unroll
    for (int l = 0; l < 4; l++) {
        int ii = (tid >> 5) + l*8, jj = tid & 31;
        int r = I + ii, c = J + jj;
        tile[ii][jj] = (r < NV && c < NV) ? adp[r*NV + c] : 0.f;
    }
    __syncthreads();
    #pragma unroll
    for (int l = 0; l < 4; l++) {
        int ii = (tid >> 5) + l*8, jj = tid & 31;
        int r = I + ii, c = J + jj;
        float a1 = 0.f;
        if (r < NV && c < NV)
            a1 = (tile[ii][jj] + (r == c ? 1.f : 0.f)) * (1.f / g_rs[r]);
        g_a1f[r*VP + c] = a1;
        g_B1h[0][r*VP + c] = __float2half_rn(0.95f*a1 + ((r == c && r < NV) ? 0.05f : 0.f));
    }
    #pragma unroll
    for (int l = 0; l < 4; l++) {
        int ii = (tid >> 5) + l*8, jj = tid & 31;
        int rr = J + ii, cc = I + jj;      // a2f[rr][cc] = (adp[cc][rr]+d)/(cs[rr]+1)
        float a2 = 0.f;
        if (rr < NV && cc < NV)
            a2 = (tile[jj][ii] + (rr == cc ? 1.f : 0.f)) * (1.f / (g_cs[rr] + 1.f));
        g_a2f[rr*VP + cc] = a2;
        g_B1h[1][rr*VP + cc] = __float2half_rn(0.95f*a2 + ((rr == cc && rr < NV) ? 0.05f : 0.f));
    }
}

// ---------------- A^2 partials: 64x64 tile, 4x4 microtile, K split by 4 ----------------
__global__ __launch_bounds__(256) void asq_part()
{
    int z = blockIdx.z;
    int side = z >> 2, kc = z & 3;
    const float* A = side ? g_a2f : g_a1f;
    float* P = g_A2p[z];
    __shared__ float As[64][17];
    __shared__ float Bs[16][65];
    int tid = threadIdx.x;
    int tx = tid & 15, ty = tid >> 4;
    int vb = blockIdx.y*64, cb = blockIdx.x*64;
    float c[4][4];
    #pragma unroll
    for (int i = 0; i < 4; i++)
        #pragma unroll
        for (int j = 0; j < 4; j++) c[i][j] = 0.f;
    int kbeg = kc * 128;
    for (int k0 = kbeg; k0 < kbeg + 128; k0 += 16) {
        #pragma unroll
        for (int i = 0; i < 4; i++) {
            int e = tid + i*256;
            int r = e >> 4, k = e & 15;
            As[r][k] = A[(vb + r)*VP + k0 + k];
        }
        #pragma unroll
        for (int i = 0; i < 4; i++) {
            int e = tid + i*256;
            int k = e >> 6, cc = e & 63;
            Bs[k][cc] = A[(k0 + k)*VP + cb + cc];
        }
        __syncthreads();
        #pragma unroll
        for (int k = 0; k < 16; k++) {
            float av[4], bv[4];
            #pragma unroll
            for (int i = 0; i < 4; i++) av[i] = As[ty*4 + i][k];
            #pragma unroll
            for (int j = 0; j < 4; j++) bv[j] = Bs[k][tx*4 + j];
            #pragma unroll
            for (int i = 0; i < 4; i++)
                #pragma unroll
                for (int j = 0; j < 4; j++)
                    c[i][j] = fmaf(av[i], bv[j], c[i][j]);
        }
        __syncthreads();
    }
    #pragma unroll
    for (int i = 0; i < 4; i++)
        #pragma unroll
        for (int j = 0; j < 4; j++)
            P[(vb + ty*4 + i)*VP + cb + tx*4 + j] = c[i][j];
}

// ---------------- finalize: B2 = fp16(0.9025*sum(P) + 0.0475*A + 0.05*I) ----------------
__global__ __launch_bounds__(256) void asq_fin()
{
    int side = blockIdx.y;
    const float* A = side ? g_a2f : g_a1f;
    __half* B2 = g_B2h[side];
    int e = blockIdx.x * 256 + threadIdx.x;   // 0 .. VP*VP-1 (grid.x = 1024)
    int r = e >> 9, cc = e & 511;
    float s = g_A2p[side*4 + 0][e] + g_A2p[side*4 + 1][e]
            + g_A2p[side*4 + 2][e] + g_A2p[side*4 + 3][e];
    float val = 0.9025f*s + 0.0475f*A[e] + ((r == cc && r < NV) ? 0.05f : 0.f);
    B2[e] = __float2half_rn(val);
}

// ---------------- HMMA dilated inception + gating -> fp16 h ----------------
#define XST_ROWS 80
#define XST_STRB 80
#define XST_WARP (XST_ROWS*XST_STRB)
#define WP_STRB 80
#define WP_BYTES (7*64*WP_STRB)           // 35840 B
#define INCEPT_SMEM (WP_BYTES + 4*XST_WARP + 512)
__global__ __launch_bounds__(128,2) void incept_mma(const float* __restrict__ x)
{
    extern __shared__ __align__(16) char smi[];
    uint32_t sW = smem_u32(smi);
    uint32_t sX0 = sW + WP_BYTES;
    float* fbs = (float*)(smi + WP_BYTES + 4*XST_WARP);
    float* gbs = fbs + 32;

    int tid = threadIdx.x, warp = tid >> 5, lane = tid & 31;

    for (int e = tid; e < WP_BYTES/16; e += 128)
        *(float4*)(smi + e*16) = *(const float4*)(((const char*)g_Wph) + e*16);
    if (tid < 32) { fbs[tid] = g_fbias[tid]; gbs[tid] = g_gbias[tid]; }

    int p = blockIdx.x * 4 + warp;
    int n = p >> 5, b = p & 31;
    uint32_t sX = sX0 + warp*XST_WARP;
    {
        int i0 = (lane & 15) * 2;
        int t0 = (lane >> 4) * 32;
        const float* xr0 = &x[((size_t)(b*C_R + i0)*NV + n)*NT + t0];
        const float* xr1 = xr0 + (size_t)NV*NT;
        #pragma unroll
        for (int q = 0; q < 8; q++) {
            float4 v0 = *(const float4*)&xr0[q*4];
            float4 v1 = *(const float4*)&xr1[q*4];
            const float* a0 = &v0.x; const float* a1 = &v1.x;
            #pragma unroll
            for (int r = 0; r < 4; r++) {
                int t = t0 + q*4 + r;
                *(__half2*)(smi + (sX - smem_u32(smi)) + t*XST_STRB + i0*2) =
                    __floats2half2_rn(a0[r], a1[r]);
            }
        }
    }
    __syncthreads();

    float c[4][7][4];
    #pragma unroll
    for (int mi = 0; mi < 4; mi++)
        #pragma unroll
        for (int nt = 0; nt < 7; nt++)
            #pragma unroll
            for (int q = 0; q < 4; q++) c[mi][nt][q] = 0.f;

    #pragma unroll
    for (int j = 0; j < 7; j++) {
        uint32_t wbase = sW + j*64*WP_STRB;
        #pragma unroll
        for (int kst = 0; kst < 2; kst++) {
            int kb = (kst*16 + (lane >> 4)*8) * 2;
            uint32_t a[4][4];
            #pragma unroll
            for (int mi = 0; mi < 4; mi++)
                ldmx4(a[mi], wbase + (mi*16 + (lane & 15))*WP_STRB + kb);
            uint32_t bf[4][4];
            int kbb = (kst*16 + ((lane >> 3) & 1)*8) * 2;
            #pragma unroll
            for (int nb8 = 0; nb8 < 4; nb8++) {
                int trow = nb8*16 + (lane & 7) + ((lane >> 4) << 3) + 2*j;
                ldmx4(bf[nb8], sX + trow*XST_STRB + kbb);
            }
            #pragma unroll
            for (int mi = 0; mi < 4; mi++)
                #pragma unroll
                for (int nt = 0; nt < 7; nt++)
                    mma_f16(c[mi][nt], a[mi], &bf[nt >> 1][(nt & 1)*2]);
        }
    }

    int gr = lane >> 2, qc = (lane & 3)*2;
    __half* hout = &g_hh[(size_t)(n*NB + b)*HVEC];
    #pragma unroll
    for (int mi = 0; mi < 2; mi++) {
        #pragma unroll
        for (int hf = 0; hf < 2; hf++) {
            int o = mi*16 + gr + hf*8;
            float fb = fbs[o], gb = gbs[o];
            #pragma unroll
            for (int nt = 0; nt < 7; nt++) {
                int t = nt*8 + qc;
                if (t < NK) {
                    float h0 = fast_tanh(c[mi][nt][hf*2+0] + fb) * fast_sig(c[mi+2][nt][hf*2+0] + gb);
                    float h1 = fast_tanh(c[mi][nt][hf*2+1] + fb) * fast_sig(c[mi+2][nt][hf*2+1] + gb);
                    *(__half2*)&hout[o*NK + t] = __floats2half2_rn(h0, h1);
                }
            }
        }
    }
}

// ---------------- skip conv as per-node HMMA GEMM ----------------
#define SK_WBYTES (64*272)
#define SK_BBYTES (32*272)
#define SK_BUF (SK_WBYTES + SK_BBYTES)
#define SKIP_SMEM (2*SK_BUF)
__global__ __launch_bounds__(128) void skip_mma(const float* __restrict__ skipb,
                                                float* __restrict__ sout)
{
    extern __shared__ __align__(16) char sks[];
    int n = blockIdx.x;
    int tid = threadIdx.x, warp = tid >> 5, lane = tid & 31;
    int m0 = warp * 16;
    uint32_t sb = smem_u32(sks);

    const __half* Bg = &g_hh[(size_t)n*NMCOL];

    float c[4][4];
    #pragma unroll
    for (int i = 0; i < 4; i++)
        #pragma unroll
        for (int j = 0; j < 4; j++) c[i][j] = 0.f;

    auto load_chunk = [&](int buf, int ch) {
        int k0 = ch * 128;
        uint32_t sW = sb + buf*SK_BUF;
        uint32_t sB = sW + SK_WBYTES;
        #pragma unroll
        for (int j = 0; j < 8; j++) {
            int lin = tid + j*128;
            int r = lin >> 4, q = lin & 15;
            CP_ASYNC16(sW + r*272 + q*16, &g_swh[r*HVEC + k0 + q*8]);
        }
        #pragma unroll
        for (int j = 0; j < 4; j++) {
            int lin = tid + j*128;
            int r = lin >> 4, q = lin & 15;
            CP_ASYNC16(sB + r*272 + q*16, &Bg[r*HVEC + k0 + q*8]);
        }
        CP_COMMIT();
    };

    load_chunk(0, 0);
    load_chunk(1, 1);

    for (int ch = 0; ch < 13; ch++) {
        if (ch == 12) { CP_WAIT0(); } else { CP_WAIT1(); }
        __syncthreads();
        int buf = ch & 1;
        uint32_t sW = sb + buf*SK_BUF;
        uint32_t sB = sW + SK_WBYTES;
        #pragma unroll
        for (int ks = 0; ks < 8; ks++) {
            int k0 = ks * 16;
            uint32_t a[4];
            ldmx4(a, sW + (m0 + (lane & 15))*272 + (k0 + (lane >> 4)*8)*2);
            uint32_t bfr[2][4];
            #pragma unroll
            for (int np = 0; np < 2; np++)
                ldmx4(bfr[np], sB + (np*16 + (lane & 7) + ((lane >> 4) << 3))*272
                               + (k0 + ((lane >> 3) & 1)*8)*2);
            #pragma unroll
            for (int ni = 0; ni < 4; ni++)
                mma_f16(c[ni], a, &bfr[ni >> 1][(ni & 1)*2]);
        }
        __syncthreads();
        if (ch + 2 < 13) load_chunk(buf, ch + 2);
    }

    int gr = lane >> 2, qc = (lane & 3)*2;
    #pragma unroll
    for (int ni = 0; ni < 4; ni++) {
        int b0 = ni*8 + qc;
        int cs0 = m0 + gr;
        float bi0 = skipb[cs0], bi1 = skipb[cs0 + 8];
        sout[(b0*C_S + cs0)*NV + n]       = c[ni][0] + bi0;
        sout[((b0+1)*C_S + cs0)*NV + n]   = c[ni][1] + bi0;
        sout[(b0*C_S + cs0+8)*NV + n]     = c[ni][2] + bi1;
        sout[((b0+1)*C_S + cs0+8)*NV + n] = c[ni][3] + bi1;
    }
}

// ---------------- single-launch fp16 HMMA prop (BK=64): {h1,h2} x {a,b} = B{1,2}[side] @ h ----------------
#define PA_STRB 144
#define PA_BYTES (128*PA_STRB)     // 18432
#define PB_STRB 272
#define PB_BYTES (64*PB_STRB)      // 17408
#define PBUF (PA_BYTES + PB_BYTES) // 35840
#define PROP_SMEM (2*PBUF)
__global__ __launch_bounds__(256,2) void prop_mma()
{
    extern __shared__ __align__(16) char smp[];
    int z = blockIdx.z;
    int side = z >> 1, which = z & 1;
    const __half* Aadj = which ? g_B2h[side] : g_B1h[side];
    const __half* Bin = g_hh;
    __half* Hout = (z == 0) ? g_h1ah : (z == 1) ? g_h2ah : (z == 2) ? g_h1bh : g_h2bh;

    int tid = threadIdx.x, warp = tid >> 5, lane = tid & 31;
    int nbase = blockIdx.x * 128;
    int vt = blockIdx.y;
    int wm = (warp >> 2)*64, wn = (warp & 3)*32;
    uint32_t sb = smem_u32(smp);

    float c[4][4][4];
    #pragma unroll
    for (int i = 0; i < 4; i++)
        #pragma unroll
        for (int j = 0; j < 4; j++)
            #pragma unroll
            for (int q = 0; q < 4; q++) c[i][j][q] = 0.f;

    auto load_chunk = [&](int buf, int ch) {
        int w0 = ch * 64;
        uint32_t sA = sb + buf*PBUF;
        uint32_t sB = sA + PA_BYTES;
        #pragma unroll
        for (int j = 0; j < 4; j++) {
            int lin = tid + j*256;
            int r = lin >> 3, q = lin & 7;
            CP_ASYNC16(sA + r*PA_STRB + q*16, &Aadj[(vt*128 + r)*VP + w0 + q*8]);
        }
        #pragma unroll
        for (int j = 0; j < 4; j++) {
            int lin = tid + j*256;
            int r = lin >> 4, q = lin & 15;
            CP_ASYNC16(sB + r*PB_STRB + q*16, &Bin[(size_t)(w0 + r)*NMCOL + nbase + q*8]);
        }
        CP_COMMIT();
    };

    load_chunk(0, 0);
    load_chunk(1, 1);

    for (int ch = 0; ch < 8; ch++) {
        if (ch == 7) { CP_WAIT0(); } else { CP_WAIT1(); }
        __syncthreads();
        int buf = ch & 1;
        uint32_t sA = sb + buf*PBUF;
        uint32_t sB = sA + PA_BYTES;
        #pragma unroll
        for (int ks = 0; ks < 4; ks++) {
            int k0 = ks * 16;
            uint32_t a[4][4];
            #pragma unroll
            for (int mi = 0; mi < 4; mi++)
                ldmx4(a[mi], sA + (wm + mi*16 + (lane & 15))*PA_STRB + (k0 + (lane >> 4)*8)*2);
            uint32_t bfr[2][4];
            #pragma unroll
            for (int np = 0; np < 2; np++)
                ldmx4t(bfr[np], sB + (k0 + (lane & 15))*PB_STRB + (wn + np*16 + (lane >> 4)*8)*2);
            #pragma unroll
            for (int mi = 0; mi < 4; mi++)
                #pragma unroll
                for (int ni = 0; ni < 4; ni++)
                    mma_f16(c[mi][ni], a[mi], &bfr[ni >> 1][(ni & 1)*2]);
        }
        __syncthreads();
        if (ch + 2 < 8) load_chunk(buf, ch + 2);
    }

    // identity already folded into B1/B2 -> direct store
    int gr = lane >> 2, qc = (lane & 3)*2;
    #pragma unroll
    for (int mi = 0; mi < 4; mi++) {
        #pragma unroll
        for (int hf = 0; hf < 2; hf++) {
            int v = vt*128 + wm + mi*16 + gr + hf*8;
            if (v < NV) {
                #pragma unroll
                for (int ni = 0; ni < 4; ni++) {
                    size_t off = (size_t)v*NMCOL + nbase + wn + ni*8 + qc;
                    *(__half2*)&Hout[off] =
                        __floats2half2_rn(c[mi][ni][hf*2+0], c[mi][ni][hf*2+1]);
                }
            }
        }
    }
}

// ---------------- combine as per-(v,b) HMMA GEMM: out[c][l] = W[32x160] @ T[160x52] ----------------
#define CW_STRB 336
#define CW_BYTES (32*CW_STRB)              // 10752
#define CT_STRB 144
#define CT_WARP (160*CT_STRB)              // 23040 per warp
#define COMB_SMEM (CW_BYTES + 128 + 4*CT_WARP)
__global__ __launch_bounds__(128,2) void combine_mma(const float* __restrict__ x,
                                                     const float* __restrict__ gc1w,
                                                     const float* __restrict__ gc1b,
                                                     const float* __restrict__ gc2w,
                                                     const float* __restrict__ gc2b)
{
    extern __shared__ __align__(16) char smc[];
    uint32_t sW = smem_u32(smc);
    float* bias = (float*)(smc + CW_BYTES);
    uint32_t sT0 = sW + CW_BYTES + 128;

    int tid = threadIdx.x, warp = tid >> 5, lane = tid & 31;

    for (int e = tid; e < 5120; e += 128) {
        int cch = e / 160, k = e % 160;
        int t = k >> 5, cp = k & 31;
        float val;
        if      (t == 0) val = gc1w[cch*96 + cp] + gc2w[cch*96 + cp];
        else if (t == 1) val = gc1w[cch*96 + 32 + cp];
        else if (t == 2) val = gc1w[cch*96 + 64 + cp];
        else if (t == 3) val = gc2w[cch*96 + 32 + cp];
        else             val = gc2w[cch*96 + 64 + cp];
        *(__half*)(smc + cch*CW_STRB + k*2) = __float2half_rn(val);
    }
    if (tid < 32) bias[tid] = gc1b[tid] + gc2b[tid];

    int p = blockIdx.x * 4 + warp;
    int n = p >> 5, b = p & 31;
    uint32_t sT = sT0 + warp*CT_WARP;
    size_t slab_off = (size_t)(n*NB + b)*HVEC;
    for (int e = lane; e < 160*13; e += 32) {
        int r = e / 13, j = e % 13;
        const __half* slab = (r < 32) ? g_hh : (r < 64) ? g_h1ah : (r < 96) ? g_h2ah
                            : (r < 128) ? g_h1bh : g_h2bh;
        uint2 v = *(const uint2*)&slab[slab_off + (size_t)(r & 31)*NK + j*4];
        *(uint2*)((char*)smc + (sT - smem_u32(smc)) + r*CT_STRB + j*8) = v;
    }
    __syncthreads();

    float c[2][7][4];
    #pragma unroll
    for (int mi = 0; mi < 2; mi++)
        #pragma unroll
        for (int nt = 0; nt < 7; nt++)
            #pragma unroll
            for (int q = 0; q < 4; q++) c[mi][nt][q] = 0.f;

    #pragma unroll
    for (int ks = 0; ks < 10; ks++) {
        int k0 = ks * 16;
        uint32_t a[2][4];
        #pragma unroll
        for (int mi = 0; mi < 2; mi++)
            ldmx4(a[mi], sW + (mi*16 + (lane & 15))*CW_STRB + (k0 + (lane >> 4)*8)*2);
        uint32_t bq[4][4];
        #pragma unroll
        for (int nq = 0; nq < 4; nq++)
            ldmx4t(bq[nq], sT + (k0 + (lane & 15))*CT_STRB + (nq*16 + (lane >> 4)*8)*2);
        #pragma unroll
        for (int mi = 0; mi < 2; mi++)
            #pragma unroll
            for (int nt = 0; nt < 7; nt++)
                mma_f16(c[mi][nt], a[mi], &bq[nt >> 1][(nt & 1)*2]);
    }

    int gr = lane >> 2, qc = (lane & 3)*2;
    float psum = 0.f, psq = 0.f;
    #pragma unroll
    for (int mi = 0; mi < 2; mi++) {
        #pragma unroll
        for (int hf = 0; hf < 2; hf++) {
            int cch = mi*16 + gr + hf*8;
            float bi = bias[cch];
            const float* xr = &x[((size_t)(b*C_R + cch)*NV + n)*NT + 12];
            __half* xoh = &g_xoh[((size_t)(b*C_C + cch)*NV + n)*NK];
            #pragma unroll
            for (int nt = 0; nt < 7; nt++) {
                int l = nt*8 + qc;
                if (l < NK) {
                    float v0 = c[mi][nt][hf*2+0] + bi + xr[l];
                    float v1 = c[mi][nt][hf*2+1] + bi + xr[l+1];
                    *(__half2*)&xoh[l] = __floats2half2_rn(v0, v1);
                    psum += v0 + v1;
                    psq  = fmaf(v0, v0, psq);
                    psq  = fmaf(v1, v1, psq);
                }
            }
        }
    }
    #pragma unroll
    for (int off = 16; off > 0; off >>= 1) {
        psum += __shfl_down_sync(0xffffffffu, psum, off);
        psq  += __shfl_down_sync(0xffffffffu, psq,  off);
    }
    if (lane == 0) {
        atomicAdd(&g_stats[2*b], psum);
        atomicAdd(&g_stats[2*b + 1], psq);
    }
}

// ---------------- LayerNorm apply (reads fp16 xo) ----------------
__global__ __launch_bounds__(256) void norm_kernel(const int* __restrict__ idx,
                                                   const float* __restrict__ lnw,
                                                   const float* __restrict__ lnb,
                                                   float* __restrict__ out)
{
    int gid = blockIdx.x * 256 + threadIdx.x;
    int lq = gid % 13;
    int row = gid / 13;
    int v = row % NV;
    int cch = (row / NV) % C_C;
    int b = row / (C_C*NV);

    float s1 = g_stats[2*b], s2 = g_stats[2*b + 1];
    float mean = s1 * (1.f/(float)CNT_PER_B);
    float var  = s2 * (1.f/(float)CNT_PER_B) - mean*mean;
    float rstd = rsqrtf(var + 1e-5f);
    int nidx = idx[v];

    uint2 raw = *(const uint2*)&g_xoh[(size_t)row*NK + lq*4];
    float2 f01 = __half22float2(*(__half2*)&raw.x);
    float2 f23 = __half22float2(*(__half2*)&raw.y);
    float4 w4 = *(const float4*)&lnw[(cch*NV + nidx)*NK + lq*4];
    float4 b4 = *(const float4*)&lnb[(cch*NV + nidx)*NK + lq*4];
    float4 o;
    o.x = (f01.x - mean)*rstd*w4.x + b4.x;
    o.y = (f01.y - mean)*rstd*w4.y + b4.y;
    o.z = (f23.x - mean)*rstd*w4.z + b4.z;
    o.w = (f23.y - mean)*rstd*w4.w + b4.w;
    *(float4*)&out[row*NK + lq*4] = o;
}

// ---------------- launch ----------------
extern "C" void kernel_launch(void* const* d_in, const int* in_sizes, int n_in,
                              void* d_out, int out_size)
{
    const float* x = (const float*)d_in[0];
    int ia = (in_sizes[1] == NV*NV) ? 1 : 2;
    const float* adp = (const float*)d_in[ia];
    const int*   idx = (const int*)d_in[3 - ia];
    const float* fw2 = (const float*)d_in[3];
    const float* fb2 = (const float*)d_in[4];
    const float* fw3 = (const float*)d_in[5];
    const float* fb3 = (const float*)d_in[6];
    const float* fw6 = (const float*)d_in[7];
    const float* fb6 = (const float*)d_in[8];
    const float* fw7 = (const float*)d_in[9];
    const float* fb7 = (const float*)d_in[10];
    const float* gw2 = (const float*)d_in[11];
    const float* gb2 = (const float*)d_in[12];
    const float* gw3 = (const float*)d_in[13];
    const float* gb3 = (const float*)d_in[14];
    const float* gw6 = (const float*)d_in[15];
    const float* gb6 = (const float*)d_in[16];
    const float* gw7 = (const float*)d_in[17];
    const float* gb7 = (const float*)d_in[18];
    const float* skipw = (const float*)d_in[19];
    const float* skipb = (const float*)d_in[20];
    const float* gc1w = (const float*)d_in[21];
    const float* gc1b = (const float*)d_in[22];
    const float* gc2w = (const float*)d_in[23];
    const float* gc2b = (const float*)d_in[24];
    const float* lnw = (const float*)d_in[25];
    const float* lnb = (const float*)d_in[26];
    float* out = (float*)d_out;
    float* s_out = out + NB*C_C*NV*NK;

    cudaFuncSetAttribute(incept_mma,  cudaFuncAttributeMaxDynamicSharedMemorySize, INCEPT_SMEM);
    cudaFuncSetAttribute(skip_mma,    cudaFuncAttributeMaxDynamicSharedMemorySize, SKIP_SMEM);
    cudaFuncSetAttribute(prop_mma,    cudaFuncAttributeMaxDynamicSharedMemorySize, PROP_SMEM);
    cudaFuncSetAttribute(combine_mma, cudaFuncAttributeMaxDynamicSharedMemorySize, COMB_SMEM);

    pack_kernel<<<64, 256>>>(fw2, fw3, fw6, fw7, fb2, fb3, fb6, fb7,
                             gw2, gw3, gw6, gw7, gb2, gb3, gb6, gb7, skipw);
    sums_kernel<<<NV, 256>>>(adp);
    buildAB_kernel<<<dim3(16, 16), 256>>>(adp);
    asq_part<<<dim3(8, 8, 8), 256>>>();
    asq_fin<<<dim3(1024, 2), 256>>>();
    incept_mma<<<4000, 128, INCEPT_SMEM>>>(x);
    skip_mma<<<NV, 128, SKIP_SMEM>>>(skipb, s_out);
    prop_mma<<<dim3(NMCOL/128, 4, 4), 256, PROP_SMEM>>>();
    combine_mma<<<4000, 128, COMB_SMEM>>>(x, gc1w, gc1b, gc2w, gc2b);
    norm_kernel<<<26000, 256>>>(idx, lnw, lnb, out);
}

// round 14
// speedup vs baseline: 4.3666x; 1.0008x over previous
#include <cuda_runtime.h>
#include <cuda_fp16.h>
#include <cstdint>

// ---------------- problem constants ----------------
#define NB   32
#define C_R  32
#define C_C  32
#define C_S  64
#define NV   500
#define NT   64
#define NK   52
#define NMCOL (NB*C_C*NK)   // 53248
#define VP   512
#define HVEC (C_C*NK)       // 1664
#define CNT_PER_B (C_C*NV*NK)

// ---------------- device scratch (zero-initialized) ----------------
__device__ float  g_a1f[VP*VP];
__device__ float  g_a2f[VP*VP];
__device__ __half g_B1h[2][VP*VP];
__device__ __half g_B2h[2][VP*VP];
__device__ float  g_A2p[8][VP*VP];    // A^2 k-split partials (side*4 + kc)
__device__ float  g_rs[NV];
__device__ float  g_cs[NV];
__device__ __half g_swh[C_S*HVEC];
__device__ __half g_Wph[7*64*40];     // packed inception weights, SMEM-image layout
__device__ float  g_fbias[C_C];
__device__ float  g_gbias[C_C];
// rows (nodes) padded to 512; rows >=500 never written, stay zero
__device__ __half g_hh  [VP*NMCOL];
__device__ __half g_h1ah[VP*NMCOL];
__device__ __half g_h1bh[VP*NMCOL];
__device__ __half g_h2ah[VP*NMCOL];
__device__ __half g_h2bh[VP*NMCOL];
__device__ __half g_xoh[NB*C_C*NV*NK];
__device__ float  g_stats[2*NB];

// ---------------- helpers ----------------
__device__ __forceinline__ uint32_t smem_u32(const void* p){
    uint32_t a; asm("{ .reg .u64 t; cvta.to.shared.u64 t, %1; cvt.u32.u64 %0, t; }":"=r"(a):"l"(p)); return a;
}
#define CP_ASYNC16(s,g) asm volatile("cp.async.cg.shared.global [%0], [%1], 16;"::"r"(s),"l"(g))
#define CP_COMMIT()     asm volatile("cp.async.commit_group;" ::: "memory")
#define CP_WAIT1()      asm volatile("cp.async.wait_group 1;" ::: "memory")
#define CP_WAIT0()      asm volatile("cp.async.wait_group 0;" ::: "memory")

__device__ __forceinline__ void ldmx4(uint32_t* r, uint32_t addr){
    asm volatile("ldmatrix.sync.aligned.m8n8.x4.shared.b16 {%0,%1,%2,%3}, [%4];"
        : "=r"(r[0]),"=r"(r[1]),"=r"(r[2]),"=r"(r[3]) : "r"(addr));
}
__device__ __forceinline__ void ldmx4t(uint32_t* r, uint32_t addr){
    asm volatile("ldmatrix.sync.aligned.m8n8.x4.trans.shared.b16 {%0,%1,%2,%3}, [%4];"
        : "=r"(r[0]),"=r"(r[1]),"=r"(r[2]),"=r"(r[3]) : "r"(addr));
}
__device__ __forceinline__ void mma_f16(float* c, const uint32_t* a, const uint32_t* b){
    asm volatile("mma.sync.aligned.m16n8k16.row.col.f32.f16.f16.f32 "
        "{%0,%1,%2,%3}, {%4,%5,%6,%7}, {%8,%9}, {%0,%1,%2,%3};"
        : "+f"(c[0]),"+f"(c[1]),"+f"(c[2]),"+f"(c[3])
        : "r"(a[0]),"r"(a[1]),"r"(a[2]),"r"(a[3]), "r"(b[0]),"r"(b[1]));
}
__device__ __forceinline__ float fast_tanh(float z){
    float e2 = __expf(fminf(-2.f*z, 40.f));
    return __fdividef(1.f - e2, 1.f + e2);
}
__device__ __forceinline__ float fast_sig(float z){
    return __fdividef(1.f, 1.f + __expf(fminf(-z, 40.f)));
}

// ---------------- pack: fp16 inception weights, half skip weights, zero sums/stats ----------------
__global__ void pack_kernel(const float* __restrict__ fw2,const float* __restrict__ fw3,
    const float* __restrict__ fw6,const float* __restrict__ fw7,
    const float* __restrict__ fb2,const float* __restrict__ fb3,
    const float* __restrict__ fb6,const float* __restrict__ fb7,
    const float* __restrict__ gw2,const float* __restrict__ gw3,
    const float* __restrict__ gw6,const float* __restrict__ gw7,
    const float* __restrict__ gb2,const float* __restrict__ gb3,
    const float* __restrict__ gb6,const float* __restrict__ gb7,
    const float* __restrict__ skipw)
{
    int tid = threadIdx.x;
    int gtid = blockIdx.x * blockDim.x + tid;
    for (int e = gtid; e < C_S*HVEC; e += gridDim.x * blockDim.x)
        g_swh[e] = __float2half_rn(skipw[e]);
    if (blockIdx.x != 0) return;
    if (tid < 2*NB) g_stats[tid] = 0.f;
    for (int e = tid; e < NV; e += blockDim.x) g_cs[e] = 0.f;
    for (int e = tid; e < 7*64*32; e += blockDim.x) {
        int j = e / 2048;
        int o = (e & 2047) >> 5;
        int i = e & 31;
        int oc = o & 31;
        int br = oc >> 3, oo = oc & 7;
        int k = (br==0)?2:(br==1)?3:(br==2)?6:7;
        int j0 = 7 - k;
        float vv = 0.f;
        if (j >= j0) {
            int si = (oo*C_R + i)*k + (j - j0);
            if (o < 32) {
                const float* fw = (br==0)?fw2:(br==1)?fw3:(br==2)?fw6:fw7;
                vv = fw[si];
            } else {
                const float* gw = (br==0)?gw2:(br==1)?gw3:(br==2)?gw6:gw7;
                vv = gw[si];
            }
        }
        g_Wph[(j*64 + o)*40 + i] = __float2half_rn(vv);
    }
    if (tid < C_C) {
        int br = tid >> 3, oo = tid & 7;
        const float* fb = (br==0)?fb2:(br==1)?fb3:(br==2)?fb6:fb7;
        const float* gb = (br==0)?gb2:(br==1)?gb3:(br==2)?gb6:gb7;
        g_fbias[tid] = fb[oo]; g_gbias[tid] = gb[oo];
    }
}

// ---------------- row sums (coalesced) + col sums (atomics) ----------------
__global__ void sums_kernel(const float* __restrict__ adp)
{
    int v = blockIdx.x;
    __shared__ float red[256];
    int tid = threadIdx.x;
    float s = 0.f;
    for (int w = tid; w < NV; w += 256) {
        float val = adp[v*NV + w];
        s += val;
        atomicAdd(&g_cs[w], val);
    }
    red[tid] = s; __syncthreads();
    for (int st = 128; st > 0; st >>= 1) {
        if (tid < st) red[tid] += red[tid + st];
        __syncthreads();
    }
    if (tid == 0) g_rs[v] = red[0] + 1.f;
}

// ---------------- build a1f/a2f fp32 (padded 512) + B1 fp16 for both sides ----------------
__global__ void buildAB_kernel(const float* __restrict__ adp)
{
    __shared__ float tile[32][33];
    int tid = threadIdx.x;
    int I = blockIdx.y*32, J = blockIdx.x*32;
    #pragma unroll
    for (int l = 0; l < 4; l++) {
        int ii = (tid >> 5) + l*8, jj = tid & 31;
        int r = I + ii, c = J + jj;
        tile[ii][jj] = (r < NV && c < NV) ? adp[r*NV + c] : 0.f;
    }
    __syncthreads();
    #pragma unroll
    for (int l = 0; l < 4; l++) {
        int ii = (tid >> 5) + l*8, jj = tid & 31;
        int r = I + ii, c = J + jj;
        float a1 = 0.f;
        if (r < NV && c < NV)
            a1 = (tile[ii][jj] + (r == c ? 1.f : 0.f)) * (1.f / g_rs[r]);
        g_a1f[r*VP + c] = a1;
        g_B1h[0][r*VP + c] = __float2half_rn(0.95f*a1 + ((r == c && r < NV) ? 0.05f : 0.f));
    }
    #pragma unroll
    for (int l = 0; l < 4; l++) {
        int ii = (tid >> 5) + l*8, jj = tid & 31;
        int rr = J + ii, cc = I + jj;      // a2f[rr][cc] = (adp[cc][rr]+d)/(cs[rr]+1)
        float a2 = 0.f;
        if (rr < NV && cc < NV)
            a2 = (tile[jj][ii] + (rr == cc ? 1.f : 0.f)) * (1.f / (g_cs[rr] + 1.f));
        g_a2f[rr*VP + cc] = a2;
        g_B1h[1][rr*VP + cc] = __float2half_rn(0.95f*a2 + ((rr == cc && rr < NV) ? 0.05f : 0.f));
    }
}

// ---------------- A^2 partials: 64x64 tile, 4x4 microtile, K split by 4 ----------------
__global__ __launch_bounds__(256) void asq_part()
{
    int z = blockIdx.z;
    int side = z >> 2, kc = z & 3;
    const float* A = side ? g_a2f : g_a1f;
    float* P = g_A2p[z];
    __shared__ float As[64][17];
    __shared__ float Bs[16][65];
    int tid = threadIdx.x;
    int tx = tid & 15, ty = tid >> 4;
    int vb = blockIdx.y*64, cb = blockIdx.x*64;
    float c[4][4];
    #pragma unroll
    for (int i = 0; i < 4; i++)
        #pragma unroll
        for (int j = 0; j < 4; j++) c[i][j] = 0.f;
    int kbeg = kc * 128;
    for (int k0 = kbeg; k0 < kbeg + 128; k0 += 16) {
        #pragma unroll
        for (int i = 0; i < 4; i++) {
            int e = tid + i*256;
            int r = e >> 4, k = e & 15;
            As[r][k] = A[(vb + r)*VP + k0 + k];
        }
        #pragma unroll
        for (int i = 0; i < 4; i++) {
            int e = tid + i*256;
            int k = e >> 6, cc = e & 63;
            Bs[k][cc] = A[(k0 + k)*VP + cb + cc];
        }
        __syncthreads();
        #pragma unroll
        for (int k = 0; k < 16; k++) {
            float av[4], bv[4];
            #pragma unroll
            for (int i = 0; i < 4; i++) av[i] = As[ty*4 + i][k];
            #pragma unroll
            for (int j = 0; j < 4; j++) bv[j] = Bs[k][tx*4 + j];
            #pragma unroll
            for (int i = 0; i < 4; i++)
                #pragma unroll
                for (int j = 0; j < 4; j++)
                    c[i][j] = fmaf(av[i], bv[j], c[i][j]);
        }
        __syncthreads();
    }
    #pragma unroll
    for (int i = 0; i < 4; i++)
        #pragma unroll
        for (int j = 0; j < 4; j++)
            P[(vb + ty*4 + i)*VP + cb + tx*4 + j] = c[i][j];
}

// ---------------- finalize: B2 = fp16(0.9025*sum(P) + 0.0475*A + 0.05*I) ----------------
__global__ __launch_bounds__(256) void asq_fin()
{
    int side = blockIdx.y;
    const float* A = side ? g_a2f : g_a1f;
    __half* B2 = g_B2h[side];
    int e = blockIdx.x * 256 + threadIdx.x;   // 0 .. VP*VP-1 (grid.x = 1024)
    int r = e >> 9, cc = e & 511;
    float s = g_A2p[side*4 + 0][e] + g_A2p[side*4 + 1][e]
            + g_A2p[side*4 + 2][e] + g_A2p[side*4 + 3][e];
    float val = 0.9025f*s + 0.0475f*A[e] + ((r == cc && r < NV) ? 0.05f : 0.f);
    B2[e] = __float2half_rn(val);
}

// ---------------- HMMA dilated inception + gating -> fp16 h ----------------
#define XST_ROWS 80
#define XST_STRB 80
#define XST_WARP (XST_ROWS*XST_STRB)
#define WP_STRB 80
#define WP_BYTES (7*64*WP_STRB)           // 35840 B
#define INCEPT_SMEM (WP_BYTES + 4*XST_WARP + 512)
__global__ __launch_bounds__(128,2) void incept_mma(const float* __restrict__ x)
{
    extern __shared__ __align__(16) char smi[];
    uint32_t sW = smem_u32(smi);
    uint32_t sX0 = sW + WP_BYTES;
    float* fbs = (float*)(smi + WP_BYTES + 4*XST_WARP);
    float* gbs = fbs + 32;

    int tid = threadIdx.x, warp = tid >> 5, lane = tid & 31;

    for (int e = tid; e < WP_BYTES/16; e += 128)
        *(float4*)(smi + e*16) = *(const float4*)(((const char*)g_Wph) + e*16);
    if (tid < 32) { fbs[tid] = g_fbias[tid]; gbs[tid] = g_gbias[tid]; }

    int p = blockIdx.x * 4 + warp;
    int n = p >> 5, b = p & 31;
    uint32_t sX = sX0 + warp*XST_WARP;
    {
        int i0 = (lane & 15) * 2;
        int t0 = (lane >> 4) * 32;
        const float* xr0 = &x[((size_t)(b*C_R + i0)*NV + n)*NT + t0];
        const float* xr1 = xr0 + (size_t)NV*NT;
        #pragma unroll
        for (int q = 0; q < 8; q++) {
            float4 v0 = *(const float4*)&xr0[q*4];
            float4 v1 = *(const float4*)&xr1[q*4];
            const float* a0 = &v0.x; const float* a1 = &v1.x;
            #pragma unroll
            for (int r = 0; r < 4; r++) {
                int t = t0 + q*4 + r;
                *(__half2*)(smi + (sX - smem_u32(smi)) + t*XST_STRB + i0*2) =
                    __floats2half2_rn(a0[r], a1[r]);
            }
        }
    }
    __syncthreads();

    float c[4][7][4];
    #pragma unroll
    for (int mi = 0; mi < 4; mi++)
        #pragma unroll
        for (int nt = 0; nt < 7; nt++)
            #pragma unroll
            for (int q = 0; q < 4; q++) c[mi][nt][q] = 0.f;

    #pragma unroll
    for (int j = 0; j < 7; j++) {
        uint32_t wbase = sW + j*64*WP_STRB;
        #pragma unroll
        for (int kst = 0; kst < 2; kst++) {
            int kb = (kst*16 + (lane >> 4)*8) * 2;
            uint32_t a[4][4];
            #pragma unroll
            for (int mi = 0; mi < 4; mi++)
                ldmx4(a[mi], wbase + (mi*16 + (lane & 15))*WP_STRB + kb);
            uint32_t bf[4][4];
            int kbb = (kst*16 + ((lane >> 3) & 1)*8) * 2;
            #pragma unroll
            for (int nb8 = 0; nb8 < 4; nb8++) {
                int trow = nb8*16 + (lane & 7) + ((lane >> 4) << 3) + 2*j;
                ldmx4(bf[nb8], sX + trow*XST_STRB + kbb);
            }
            #pragma unroll
            for (int mi = 0; mi < 4; mi++)
                #pragma unroll
                for (int nt = 0; nt < 7; nt++)
                    mma_f16(c[mi][nt], a[mi], &bf[nt >> 1][(nt & 1)*2]);
        }
    }

    int gr = lane >> 2, qc = (lane & 3)*2;
    __half* hout = &g_hh[(size_t)(n*NB + b)*HVEC];
    #pragma unroll
    for (int mi = 0; mi < 2; mi++) {
        #pragma unroll
        for (int hf = 0; hf < 2; hf++) {
            int o = mi*16 + gr + hf*8;
            float fb = fbs[o], gb = gbs[o];
            #pragma unroll
            for (int nt = 0; nt < 7; nt++) {
                int t = nt*8 + qc;
                if (t < NK) {
                    float h0 = fast_tanh(c[mi][nt][hf*2+0] + fb) * fast_sig(c[mi+2][nt][hf*2+0] + gb);
                    float h1 = fast_tanh(c[mi][nt][hf*2+1] + fb) * fast_sig(c[mi+2][nt][hf*2+1] + gb);
                    *(__half2*)&hout[o*NK + t] = __floats2half2_rn(h0, h1);
                }
            }
        }
    }
}

// ---------------- skip conv as per-node HMMA GEMM (3-stage pipeline, race-free) ----------------
#define SK_WBYTES (64*272)
#define SK_BBYTES (32*272)
#define SK_BUF (SK_WBYTES + SK_BBYTES)
#define SKIP_SMEM (3*SK_BUF)
__global__ __launch_bounds__(128) void skip_mma(const float* __restrict__ skipb,
                                                float* __restrict__ sout)
{
    extern __shared__ __align__(16) char sks[];
    int n = blockIdx.x;
    int tid = threadIdx.x, warp = tid >> 5, lane = tid & 31;
    int m0 = warp * 16;
    uint32_t sb = smem_u32(sks);

    const __half* Bg = &g_hh[(size_t)n*NMCOL];

    float c[4][4];
    #pragma unroll
    for (int i = 0; i < 4; i++)
        #pragma unroll
        for (int j = 0; j < 4; j++) c[i][j] = 0.f;

    auto load_chunk = [&](int ch) {
        int buf = ch % 3;
        int k0 = ch * 128;
        uint32_t sW = sb + buf*SK_BUF;
        uint32_t sB = sW + SK_WBYTES;
        #pragma unroll
        for (int j = 0; j < 8; j++) {
            int lin = tid + j*128;
            int r = lin >> 4, q = lin & 15;
            CP_ASYNC16(sW + r*272 + q*16, &g_swh[r*HVEC + k0 + q*8]);
        }
        #pragma unroll
        for (int j = 0; j < 4; j++) {
            int lin = tid + j*128;
            int r = lin >> 4, q = lin & 15;
            CP_ASYNC16(sB + r*272 + q*16, &Bg[r*HVEC + k0 + q*8]);
        }
        CP_COMMIT();
    };

    load_chunk(0);
    load_chunk(1);

    for (int ch = 0; ch < 13; ch++) {
        // wait for chunk ch (committed groups so far: 0..ch+1 -> allow 1 pending)
        if (ch == 12) { CP_WAIT0(); } else { CP_WAIT1(); }
        __syncthreads();   // all warps done reading chunk ch-1's buffer
        if (ch + 2 < 13) load_chunk(ch + 2);   // safe: writes buffer last read at ch-1
        uint32_t sW = sb + (ch % 3)*SK_BUF;
        uint32_t sB = sW + SK_WBYTES;
        #pragma unroll
        for (int ks = 0; ks < 8; ks++) {
            int k0 = ks * 16;
            uint32_t a[4];
            ldmx4(a, sW + (m0 + (lane & 15))*272 + (k0 + (lane >> 4)*8)*2);
            uint32_t bfr[2][4];
            #pragma unroll
            for (int np = 0; np < 2; np++)
                ldmx4(bfr[np], sB + (np*16 + (lane & 7) + ((lane >> 4) << 3))*272
                               + (k0 + ((lane >> 3) & 1)*8)*2);
            #pragma unroll
            for (int ni = 0; ni < 4; ni++)
                mma_f16(c[ni], a, &bfr[ni >> 1][(ni & 1)*2]);
        }
    }

    int gr = lane >> 2, qc = (lane & 3)*2;
    #pragma unroll
    for (int ni = 0; ni < 4; ni++) {
        int b0 = ni*8 + qc;
        int cs0 = m0 + gr;
        float bi0 = skipb[cs0], bi1 = skipb[cs0 + 8];
        sout[(b0*C_S + cs0)*NV + n]       = c[ni][0] + bi0;
        sout[((b0+1)*C_S + cs0)*NV + n]   = c[ni][1] + bi0;
        sout[(b0*C_S + cs0+8)*NV + n]     = c[ni][2] + bi1;
        sout[((b0+1)*C_S + cs0+8)*NV + n] = c[ni][3] + bi1;
    }
}

// ---------------- single-launch fp16 HMMA prop (BK=64, 3-stage, race-free) ----------------
#define PA_STRB 144
#define PA_BYTES (128*PA_STRB)     // 18432
#define PB_STRB 272
#define PB_BYTES (64*PB_STRB)      // 17408
#define PBUF (PA_BYTES + PB_BYTES) // 35840
#define PROP_SMEM (3*PBUF)
__global__ __launch_bounds__(256,2) void prop_mma()
{
    extern __shared__ __align__(16) char smp[];
    int z = blockIdx.z;
    int side = z >> 1, which = z & 1;
    const __half* Aadj = which ? g_B2h[side] : g_B1h[side];
    const __half* Bin = g_hh;
    __half* Hout = (z == 0) ? g_h1ah : (z == 1) ? g_h2ah : (z == 2) ? g_h1bh : g_h2bh;

    int tid = threadIdx.x, warp = tid >> 5, lane = tid & 31;
    int nbase = blockIdx.x * 128;
    int vt = blockIdx.y;
    int wm = (warp >> 2)*64, wn = (warp & 3)*32;
    uint32_t sb = smem_u32(smp);

    float c[4][4][4];
    #pragma unroll
    for (int i = 0; i < 4; i++)
        #pragma unroll
        for (int j = 0; j < 4; j++)
            #pragma unroll
            for (int q = 0; q < 4; q++) c[i][j][q] = 0.f;

    auto load_chunk = [&](int ch) {
        int buf = ch % 3;
        int w0 = ch * 64;
        uint32_t sA = sb + buf*PBUF;
        uint32_t sB = sA + PA_BYTES;
        #pragma unroll
        for (int j = 0; j < 4; j++) {
            int lin = tid + j*256;
            int r = lin >> 3, q = lin & 7;
            CP_ASYNC16(sA + r*PA_STRB + q*16, &Aadj[(vt*128 + r)*VP + w0 + q*8]);
        }
        #pragma unroll
        for (int j = 0; j < 4; j++) {
            int lin = tid + j*256;
            int r = lin >> 4, q = lin & 15;
            CP_ASYNC16(sB + r*PB_STRB + q*16, &Bin[(size_t)(w0 + r)*NMCOL + nbase + q*8]);
        }
        CP_COMMIT();
    };

    load_chunk(0);
    load_chunk(1);

    for (int ch = 0; ch < 8; ch++) {
        if (ch == 7) { CP_WAIT0(); } else { CP_WAIT1(); }
        __syncthreads();   // all warps done reading chunk ch-1's buffer
        if (ch + 2 < 8) load_chunk(ch + 2);   // safe after barrier
        uint32_t sA = sb + (ch % 3)*PBUF;
        uint32_t sB = sA + PA_BYTES;
        #pragma unroll
        for (int ks = 0; ks < 4; ks++) {
            int k0 = ks * 16;
            uint32_t a[4][4];
            #pragma unroll
            for (int mi = 0; mi < 4; mi++)
                ldmx4(a[mi], sA + (wm + mi*16 + (lane & 15))*PA_STRB + (k0 + (lane >> 4)*8)*2);
            uint32_t bfr[2][4];
            #pragma unroll
            for (int np = 0; np < 2; np++)
                ldmx4t(bfr[np], sB + (k0 + (lane & 15))*PB_STRB + (wn + np*16 + (lane >> 4)*8)*2);
            #pragma unroll
            for (int mi = 0; mi < 4; mi++)
                #pragma unroll
                for (int ni = 0; ni < 4; ni++)
                    mma_f16(c[mi][ni], a[mi], &bfr[ni >> 1][(ni & 1)*2]);
        }
    }

    // identity already folded into B1/B2 -> direct store
    int gr = lane >> 2, qc = (lane & 3)*2;
    #pragma unroll
    for (int mi = 0; mi < 4; mi++) {
        #pragma unroll
        for (int hf = 0; hf < 2; hf++) {
            int v = vt*128 + wm + mi*16 + gr + hf*8;
            if (v < NV) {
                #pragma unroll
                for (int ni = 0; ni < 4; ni++) {
                    size_t off = (size_t)v*NMCOL + nbase + wn + ni*8 + qc;
                    *(__half2*)&Hout[off] =
                        __floats2half2_rn(c[mi][ni][hf*2+0], c[mi][ni][hf*2+1]);
                }
            }
        }
    }
}

// ---------------- combine as per-(v,b) HMMA GEMM: out[c][l] = W[32x160] @ T[160x52] ----------------
#define CW_STRB 336
#define CW_BYTES (32*CW_STRB)              // 10752
#define CT_STRB 144
#define CT_WARP (160*CT_STRB)              // 23040 per warp
#define COMB_SMEM (CW_BYTES + 128 + 4*CT_WARP)
__global__ __launch_bounds__(128,2) void combine_mma(const float* __restrict__ x,
                                                     const float* __restrict__ gc1w,
                                                     const float* __restrict__ gc1b,
                                                     const float* __restrict__ gc2w,
                                                     const float* __restrict__ gc2b)
{
    extern __shared__ __align__(16) char smc[];
    uint32_t sW = smem_u32(smc);
    float* bias = (float*)(smc + CW_BYTES);
    uint32_t sT0 = sW + CW_BYTES + 128;

    int tid = threadIdx.x, warp = tid >> 5, lane = tid & 31;

    for (int e = tid; e < 5120; e += 128) {
        int cch = e / 160, k = e % 160;
        int t = k >> 5, cp = k & 31;
        float val;
        if      (t == 0) val = gc1w[cch*96 + cp] + gc2w[cch*96 + cp];
        else if (t == 1) val = gc1w[cch*96 + 32 + cp];
        else if (t == 2) val = gc1w[cch*96 + 64 + cp];
        else if (t == 3) val = gc2w[cch*96 + 32 + cp];
        else             val = gc2w[cch*96 + 64 + cp];
        *(__half*)(smc + cch*CW_STRB + k*2) = __float2half_rn(val);
    }
    if (tid < 32) bias[tid] = gc1b[tid] + gc2b[tid];

    int p = blockIdx.x * 4 + warp;
    int n = p >> 5, b = p & 31;
    uint32_t sT = sT0 + warp*CT_WARP;
    size_t slab_off = (size_t)(n*NB + b)*HVEC;
    for (int e = lane; e < 160*13; e += 32) {
        int r = e / 13, j = e % 13;
        const __half* slab = (r < 32) ? g_hh : (r < 64) ? g_h1ah : (r < 96) ? g_h2ah
                            : (r < 128) ? g_h1bh : g_h2bh;
        uint2 v = *(const uint2*)&slab[slab_off + (size_t)(r & 31)*NK + j*4];
        *(uint2*)((char*)smc + (sT - smem_u32(smc)) + r*CT_STRB + j*8) = v;
    }
    __syncthreads();

    float c[2][7][4];
    #pragma unroll
    for (int mi = 0; mi < 2; mi++)
        #pragma unroll
        for (int nt = 0; nt < 7; nt++)
            #pragma unroll
            for (int q = 0; q < 4; q++) c[mi][nt][q] = 0.f;

    #pragma unroll
    for (int ks = 0; ks < 10; ks++) {
        int k0 = ks * 16;
        uint32_t a[2][4];
        #pragma unroll
        for (int mi = 0; mi < 2; mi++)
            ldmx4(a[mi], sW + (mi*16 + (lane & 15))*CW_STRB + (k0 + (lane >> 4)*8)*2);
        uint32_t bq[4][4];
        #pragma unroll
        for (int nq = 0; nq < 4; nq++)
            ldmx4t(bq[nq], sT + (k0 + (lane & 15))*CT_STRB + (nq*16 + (lane >> 4)*8)*2);
        #pragma unroll
        for (int mi = 0; mi < 2; mi++)
            #pragma unroll
            for (int nt = 0; nt < 7; nt++)
                mma_f16(c[mi][nt], a[mi], &bq[nt >> 1][(nt & 1)*2]);
    }

    int gr = lane >> 2, qc = (lane & 3)*2;
    float psum = 0.f, psq = 0.f;
    #pragma unroll
    for (int mi = 0; mi < 2; mi++) {
        #pragma unroll
        for (int hf = 0; hf < 2; hf++) {
            int cch = mi*16 + gr + hf*8;
            float bi = bias[cch];
            const float* xr = &x[((size_t)(b*C_R + cch)*NV + n)*NT + 12];
            __half* xoh = &g_xoh[((size_t)(b*C_C + cch)*NV + n)*NK];
            #pragma unroll
            for (int nt = 0; nt < 7; nt++) {
                int l = nt*8 + qc;
                if (l < NK) {
                    float v0 = c[mi][nt][hf*2+0] + bi + xr[l];
                    float v1 = c[mi][nt][hf*2+1] + bi + xr[l+1];
                    *(__half2*)&xoh[l] = __floats2half2_rn(v0, v1);
                    psum += v0 + v1;
                    psq  = fmaf(v0, v0, psq);
                    psq  = fmaf(v1, v1, psq);
                }
            }
        }
    }
    #pragma unroll
    for (int off = 16; off > 0; off >>= 1) {
        psum += __shfl_down_sync(0xffffffffu, psum, off);
        psq  += __shfl_down_sync(0xffffffffu, psq,  off);
    }
    if (lane == 0) {
        atomicAdd(&g_stats[2*b], psum);
        atomicAdd(&g_stats[2*b + 1], psq);
    }
}

// ---------------- LayerNorm apply (reads fp16 xo) ----------------
__global__ __launch_bounds__(256) void norm_kernel(const int* __restrict__ idx,
                                                   const float* __restrict__ lnw,
                                                   const float* __restrict__ lnb,
                                                   float* __restrict__ out)
{
    int gid = blockIdx.x * 256 + threadIdx.x;
    int lq = gid % 13;
    int row = gid / 13;
    int v = row % NV;
    int cch = (row / NV) % C_C;
    int b = row / (C_C*NV);

    float s1 = g_stats[2*b], s2 = g_stats[2*b + 1];
    float mean = s1 * (1.f/(float)CNT_PER_B);
    float var  = s2 * (1.f/(float)CNT_PER_B) - mean*mean;
    float rstd = rsqrtf(var + 1e-5f);
    int nidx = idx[v];

    uint2 raw = *(const uint2*)&g_xoh[(size_t)row*NK + lq*4];
    float2 f01 = __half22float2(*(__half2*)&raw.x);
    float2 f23 = __half22float2(*(__half2*)&raw.y);
    float4 w4 = *(const float4*)&lnw[(cch*NV + nidx)*NK + lq*4];
    float4 b4 = *(const float4*)&lnb[(cch*NV + nidx)*NK + lq*4];
    float4 o;
    o.x = (f01.x - mean)*rstd*w4.x + b4.x;
    o.y = (f01.y - mean)*rstd*w4.y + b4.y;
    o.z = (f23.x - mean)*rstd*w4.z + b4.z;
    o.w = (f23.y - mean)*rstd*w4.w + b4.w;
    *(float4*)&out[row*NK + lq*4] = o;
}

// ---------------- launch ----------------
extern "C" void kernel_launch(void* const* d_in, const int* in_sizes, int n_in,
                              void* d_out, int out_size)
{
    const float* x = (const float*)d_in[0];
    int ia = (in_sizes[1] == NV*NV) ? 1 : 2;
    const float* adp = (const float*)d_in[ia];
    const int*   idx = (const int*)d_in[3 - ia];
    const float* fw2 = (const float*)d_in[3];
    const float* fb2 = (const float*)d_in[4];
    const float* fw3 = (const float*)d_in[5];
    const float* fb3 = (const float*)d_in[6];
    const float* fw6 = (const float*)d_in[7];
    const float* fb6 = (const float*)d_in[8];
    const float* fw7 = (const float*)d_in[9];
    const float* fb7 = (const float*)d_in[10];
    const float* gw2 = (const float*)d_in[11];
    const float* gb2 = (const float*)d_in[12];
    const float* gw3 = (const float*)d_in[13];
    const float* gb3 = (const float*)d_in[14];
    const float* gw6 = (const float*)d_in[15];
    const float* gb6 = (const float*)d_in[16];
    const float* gw7 = (const float*)d_in[17];
    const float* gb7 = (const float*)d_in[18];
    const float* skipw = (const float*)d_in[19];
    const float* skipb = (const float*)d_in[20];
    const float* gc1w = (const float*)d_in[21];
    const float* gc1b = (const float*)d_in[22];
    const float* gc2w = (const float*)d_in[23];
    const float* gc2b = (const float*)d_in[24];
    const float* lnw = (const float*)d_in[25];
    const float* lnb = (const float*)d_in[26];
    float* out = (float*)d_out;
    float* s_out = out + NB*C_C*NV*NK;

    cudaFuncSetAttribute(incept_mma,  cudaFuncAttributeMaxDynamicSharedMemorySize, INCEPT_SMEM);
    cudaFuncSetAttribute(skip_mma,    cudaFuncAttributeMaxDynamicSharedMemorySize, SKIP_SMEM);
    cudaFuncSetAttribute(prop_mma,    cudaFuncAttributeMaxDynamicSharedMemorySize, PROP_SMEM);
    cudaFuncSetAttribute(combine_mma, cudaFuncAttributeMaxDynamicSharedMemorySize, COMB_SMEM);

    pack_kernel<<<64, 256>>>(fw2, fw3, fw6, fw7, fb2, fb3, fb6, fb7,
                             gw2, gw3, gw6, gw7, gb2, gb3, gb6, gb7, skipw);
    sums_kernel<<<NV, 256>>>(adp);
    buildAB_kernel<<<dim3(16, 16), 256>>>(adp);
    incept_mma<<<4000, 128, INCEPT_SMEM>>>(x);          // slot 4: captured by ncu
    asq_part<<<dim3(8, 8, 8), 256>>>();
    asq_fin<<<dim3(1024, 2), 256>>>();
    skip_mma<<<NV, 128, SKIP_SMEM>>>(skipb, s_out);
    prop_mma<<<dim3(NMCOL/128, 4, 4), 256, PROP_SMEM>>>();
    combine_mma<<<4000, 128, COMB_SMEM>>>(x, gc1w, gc1b, gc2w, gc2b);
    norm_kernel<<<26000, 256>>>(idx, lnw, lnb, out);
}

// round 15
// speedup vs baseline: 4.4412x; 1.0171x over previous
#include <cuda_runtime.h>
#include <cuda_fp16.h>
#include <cstdint>

// ---------------- problem constants ----------------
#define NB   32
#define C_R  32
#define C_C  32
#define C_S  64
#define NV   500
#define NT   64
#define NK   52
#define NMCOL (NB*C_C*NK)   // 53248
#define VP   512
#define HVEC (C_C*NK)       // 1664
#define CNT_PER_B (C_C*NV*NK)

// ---------------- device scratch (zero-initialized) ----------------
__device__ float  g_a1f[VP*VP];
__device__ float  g_a2f[VP*VP];
__device__ __half g_B1h[2][VP*VP];
__device__ __half g_B2h[2][VP*VP];
__device__ float  g_A2p[8][VP*VP];    // A^2 k-split partials (side*4 + kc)
__device__ float  g_rs[NV];
__device__ float  g_cs[NV];
__device__ __half g_swh[C_S*HVEC];
__device__ __half g_Wph[7*64*40];     // packed inception weights, SMEM-image layout
__device__ float  g_fbias[C_C];
__device__ float  g_gbias[C_C];
// rows (nodes) padded to 512; rows >=500 never written, stay zero
__device__ __half g_hh  [VP*NMCOL];
__device__ __half g_h1ah[VP*NMCOL];
__device__ __half g_h1bh[VP*NMCOL];
__device__ __half g_h2ah[VP*NMCOL];
__device__ __half g_h2bh[VP*NMCOL];
__device__ __half g_xoh[NB*C_C*NV*NK];
__device__ float  g_stats[2*NB];

// ---------------- helpers ----------------
__device__ __forceinline__ uint32_t smem_u32(const void* p){
    uint32_t a; asm("{ .reg .u64 t; cvta.to.shared.u64 t, %1; cvt.u32.u64 %0, t; }":"=r"(a):"l"(p)); return a;
}
#define CP_ASYNC16(s,g) asm volatile("cp.async.cg.shared.global [%0], [%1], 16;"::"r"(s),"l"(g))
#define CP_COMMIT()     asm volatile("cp.async.commit_group;" ::: "memory")
#define CP_WAIT1()      asm volatile("cp.async.wait_group 1;" ::: "memory")
#define CP_WAIT0()      asm volatile("cp.async.wait_group 0;" ::: "memory")

__device__ __forceinline__ void ldmx4(uint32_t* r, uint32_t addr){
    asm volatile("ldmatrix.sync.aligned.m8n8.x4.shared.b16 {%0,%1,%2,%3}, [%4];"
        : "=r"(r[0]),"=r"(r[1]),"=r"(r[2]),"=r"(r[3]) : "r"(addr));
}
__device__ __forceinline__ void ldmx4t(uint32_t* r, uint32_t addr){
    asm volatile("ldmatrix.sync.aligned.m8n8.x4.trans.shared.b16 {%0,%1,%2,%3}, [%4];"
        : "=r"(r[0]),"=r"(r[1]),"=r"(r[2]),"=r"(r[3]) : "r"(addr));
}
__device__ __forceinline__ void mma_f16(float* c, const uint32_t* a, const uint32_t* b){
    asm volatile("mma.sync.aligned.m16n8k16.row.col.f32.f16.f16.f32 "
        "{%0,%1,%2,%3}, {%4,%5,%6,%7}, {%8,%9}, {%0,%1,%2,%3};"
        : "+f"(c[0]),"+f"(c[1]),"+f"(c[2]),"+f"(c[3])
        : "r"(a[0]),"r"(a[1]),"r"(a[2]),"r"(a[3]), "r"(b[0]),"r"(b[1]));
}
__device__ __forceinline__ float fast_tanh(float z){
    float e2 = __expf(fminf(-2.f*z, 40.f));
    return __fdividef(1.f - e2, 1.f + e2);
}
__device__ __forceinline__ float fast_sig(float z){
    return __fdividef(1.f, 1.f + __expf(fminf(-z, 40.f)));
}

// ---------------- pack: fp16 inception weights, half skip weights, zero sums/stats ----------------
__global__ void pack_kernel(const float* __restrict__ fw2,const float* __restrict__ fw3,
    const float* __restrict__ fw6,const float* __restrict__ fw7,
    const float* __restrict__ fb2,const float* __restrict__ fb3,
    const float* __restrict__ fb6,const float* __restrict__ fb7,
    const float* __restrict__ gw2,const float* __restrict__ gw3,
    const float* __restrict__ gw6,const float* __restrict__ gw7,
    const float* __restrict__ gb2,const float* __restrict__ gb3,
    const float* __restrict__ gb6,const float* __restrict__ gb7,
    const float* __restrict__ skipw)
{
    int tid = threadIdx.x;
    int gtid = blockIdx.x * blockDim.x + tid;
    for (int e = gtid; e < C_S*HVEC; e += gridDim.x * blockDim.x)
        g_swh[e] = __float2half_rn(skipw[e]);
    if (blockIdx.x != 0) return;
    if (tid < 2*NB) g_stats[tid] = 0.f;
    for (int e = tid; e < NV; e += blockDim.x) g_cs[e] = 0.f;
    for (int e = tid; e < 7*64*32; e += blockDim.x) {
        int j = e / 2048;
        int o = (e & 2047) >> 5;
        int i = e & 31;
        int oc = o & 31;
        int br = oc >> 3, oo = oc & 7;
        int k = (br==0)?2:(br==1)?3:(br==2)?6:7;
        int j0 = 7 - k;
        float vv = 0.f;
        if (j >= j0) {
            int si = (oo*C_R + i)*k + (j - j0);
            if (o < 32) {
                const float* fw = (br==0)?fw2:(br==1)?fw3:(br==2)?fw6:fw7;
                vv = fw[si];
            } else {
                const float* gw = (br==0)?gw2:(br==1)?gw3:(br==2)?gw6:gw7;
                vv = gw[si];
            }
        }
        g_Wph[(j*64 + o)*40 + i] = __float2half_rn(vv);
    }
    if (tid < C_C) {
        int br = tid >> 3, oo = tid & 7;
        const float* fb = (br==0)?fb2:(br==1)?fb3:(br==2)?fb6:fb7;
        const float* gb = (br==0)?gb2:(br==1)?gb3:(br==2)?gb6:gb7;
        g_fbias[tid] = fb[oo]; g_gbias[tid] = gb[oo];
    }
}

// ---------------- row sums (coalesced) + col sums (atomics) ----------------
__global__ void sums_kernel(const float* __restrict__ adp)
{
    int v = blockIdx.x;
    __shared__ float red[256];
    int tid = threadIdx.x;
    float s = 0.f;
    for (int w = tid; w < NV; w += 256) {
        float val = adp[v*NV + w];
        s += val;
        atomicAdd(&g_cs[w], val);
    }
    red[tid] = s; __syncthreads();
    for (int st = 128; st > 0; st >>= 1) {
        if (tid < st) red[tid] += red[tid + st];
        __syncthreads();
    }
    if (tid == 0) g_rs[v] = red[0] + 1.f;
}

// ---------------- build a1f/a2f fp32 (padded 512) + B1 fp16 for both sides ----------------
__global__ void buildAB_kernel(const float* __restrict__ adp)
{
    __shared__ float tile[32][33];
    int tid = threadIdx.x;
    int I = blockIdx.y*32, J = blockIdx.x*32;
    #pragma unroll
    for (int l = 0; l < 4; l++) {
        int ii = (tid >> 5) + l*8, jj = tid & 31;
        int r = I + ii, c = J + jj;
        tile[ii][jj] = (r < NV && c < NV) ? adp[r*NV + c] : 0.f;
    }
    __syncthreads();
    #pragma unroll
    for (int l = 0; l < 4; l++) {
        int ii = (tid >> 5) + l*8, jj = tid & 31;
        int r = I + ii, c = J + jj;
        float a1 = 0.f;
        if (r < NV && c < NV)
            a1 = (tile[ii][jj] + (r == c ? 1.f : 0.f)) * (1.f / g_rs[r]);
        g_a1f[r*VP + c] = a1;
        g_B1h[0][r*VP + c] = __float2half_rn(0.95f*a1 + ((r == c && r < NV) ? 0.05f : 0.f));
    }
    #pragma unroll
    for (int l = 0; l < 4; l++) {
        int ii = (tid >> 5) + l*8, jj = tid & 31;
        int rr = J + ii, cc = I + jj;      // a2f[rr][cc] = (adp[cc][rr]+d)/(cs[rr]+1)
        float a2 = 0.f;
        if (rr < NV && cc < NV)
            a2 = (tile[jj][ii] + (rr == cc ? 1.f : 0.f)) * (1.f / (g_cs[rr] + 1.f));
        g_a2f[rr*VP + cc] = a2;
        g_B1h[1][rr*VP + cc] = __float2half_rn(0.95f*a2 + ((rr == cc && rr < NV) ? 0.05f : 0.f));
    }
}

// ---------------- A^2 partials: 64x64 tile, 4x4 microtile, K split by 4 ----------------
__global__ __launch_bounds__(256) void asq_part()
{
    int z = blockIdx.z;
    int side = z >> 2, kc = z & 3;
    const float* A = side ? g_a2f : g_a1f;
    float* P = g_A2p[z];
    __shared__ float As[64][17];
    __shared__ float Bs[16][65];
    int tid = threadIdx.x;
    int tx = tid & 15, ty = tid >> 4;
    int vb = blockIdx.y*64, cb = blockIdx.x*64;
    float c[4][4];
    #pragma unroll
    for (int i = 0; i < 4; i++)
        #pragma unroll
        for (int j = 0; j < 4; j++) c[i][j] = 0.f;
    int kbeg = kc * 128;
    for (int k0 = kbeg; k0 < kbeg + 128; k0 += 16) {
        #pragma unroll
        for (int i = 0; i < 4; i++) {
            int e = tid + i*256;
            int r = e >> 4, k = e & 15;
            As[r][k] = A[(vb + r)*VP + k0 + k];
        }
        #pragma unroll
        for (int i = 0; i < 4; i++) {
            int e = tid + i*256;
            int k = e >> 6, cc = e & 63;
            Bs[k][cc] = A[(k0 + k)*VP + cb + cc];
        }
        __syncthreads();
        #pragma unroll
        for (int k = 0; k < 16; k++) {
            float av[4], bv[4];
            #pragma unroll
            for (int i = 0; i < 4; i++) av[i] = As[ty*4 + i][k];
            #pragma unroll
            for (int j = 0; j < 4; j++) bv[j] = Bs[k][tx*4 + j];
            #pragma unroll
            for (int i = 0; i < 4; i++)
                #pragma unroll
                for (int j = 0; j < 4; j++)
                    c[i][j] = fmaf(av[i], bv[j], c[i][j]);
        }
        __syncthreads();
    }
    #pragma unroll
    for (int i = 0; i < 4; i++)
        #pragma unroll
        for (int j = 0; j < 4; j++)
            P[(vb + ty*4 + i)*VP + cb + tx*4 + j] = c[i][j];
}

// ---------------- finalize: B2 = fp16(0.9025*sum(P) + 0.0475*A + 0.05*I) ----------------
__global__ __launch_bounds__(256) void asq_fin()
{
    int side = blockIdx.y;
    const float* A = side ? g_a2f : g_a1f;
    __half* B2 = g_B2h[side];
    int e = blockIdx.x * 256 + threadIdx.x;   // 0 .. VP*VP-1 (grid.x = 1024)
    int r = e >> 9, cc = e & 511;
    float s = g_A2p[side*4 + 0][e] + g_A2p[side*4 + 1][e]
            + g_A2p[side*4 + 2][e] + g_A2p[side*4 + 3][e];
    float val = 0.9025f*s + 0.0475f*A[e] + ((r == cc && r < NV) ? 0.05f : 0.f);
    B2[e] = __float2half_rn(val);
}

// ---------------- HMMA dilated inception + gating -> fp16 h ----------------
// 2 warps per (n,b) pair: warp-parity 0 -> m-tiles {0,2}, parity 1 -> {1,3}.
// f/g pairing stays in-thread (local c[0]=f tile, c[1]=g tile).
#define XST_ROWS 80
#define XST_STRB 80
#define XST_WARP (XST_ROWS*XST_STRB)
#define WP_STRB 80
#define WP_BYTES (7*64*WP_STRB)           // 35840 B
#define INCEPT_SMEM (WP_BYTES + 4*XST_WARP + 512)
__global__ __launch_bounds__(256,2) void incept_mma(const float* __restrict__ x)
{
    extern __shared__ __align__(16) char smi[];
    uint32_t sW = smem_u32(smi);
    uint32_t sX0 = sW + WP_BYTES;
    float* fbs = (float*)(smi + WP_BYTES + 4*XST_WARP);
    float* gbs = fbs + 32;

    int tid = threadIdx.x, warp = tid >> 5, lane = tid & 31;
    int pairidx = warp >> 1, wpar = warp & 1;

    for (int e = tid; e < WP_BYTES/16; e += 256)
        *(float4*)(smi + e*16) = *(const float4*)(((const char*)g_Wph) + e*16);
    if (tid < 32) { fbs[tid] = g_fbias[tid]; gbs[tid] = g_gbias[tid]; }

    int p = blockIdx.x * 4 + pairidx;
    int n = p >> 5, b = p & 31;
    uint32_t sX = sX0 + pairidx*XST_WARP;
    {
        // 64 threads (both warps of the pair) stage xst[t][i]
        int tid64 = tid & 63;
        int i0 = (tid64 & 15) * 2;
        int t0 = (tid64 >> 4) * 16;
        const float* xr0 = &x[((size_t)(b*C_R + i0)*NV + n)*NT + t0];
        const float* xr1 = xr0 + (size_t)NV*NT;
        #pragma unroll
        for (int q = 0; q < 4; q++) {
            float4 v0 = *(const float4*)&xr0[q*4];
            float4 v1 = *(const float4*)&xr1[q*4];
            const float* a0 = &v0.x; const float* a1 = &v1.x;
            #pragma unroll
            for (int r = 0; r < 4; r++) {
                int t = t0 + q*4 + r;
                *(__half2*)(smi + (sX - smem_u32(smi)) + t*XST_STRB + i0*2) =
                    __floats2half2_rn(a0[r], a1[r]);
            }
        }
    }
    __syncthreads();

    float c[2][7][4];
    #pragma unroll
    for (int ml = 0; ml < 2; ml++)
        #pragma unroll
        for (int nt = 0; nt < 7; nt++)
            #pragma unroll
            for (int q = 0; q < 4; q++) c[ml][nt][q] = 0.f;

    #pragma unroll
    for (int j = 0; j < 7; j++) {
        uint32_t wbase = sW + j*64*WP_STRB;
        #pragma unroll
        for (int kst = 0; kst < 2; kst++) {
            int kb = (kst*16 + (lane >> 4)*8) * 2;
            uint32_t a[2][4];
            #pragma unroll
            for (int ml = 0; ml < 2; ml++) {
                int mi = wpar + ml*2;
                ldmx4(a[ml], wbase + (mi*16 + (lane & 15))*WP_STRB + kb);
            }
            uint32_t bf[4][4];
            int kbb = (kst*16 + ((lane >> 3) & 1)*8) * 2;
            #pragma unroll
            for (int nb8 = 0; nb8 < 4; nb8++) {
                int trow = nb8*16 + (lane & 7) + ((lane >> 4) << 3) + 2*j;
                ldmx4(bf[nb8], sX + trow*XST_STRB + kbb);
            }
            #pragma unroll
            for (int ml = 0; ml < 2; ml++)
                #pragma unroll
                for (int nt = 0; nt < 7; nt++)
                    mma_f16(c[ml][nt], a[ml], &bf[nt >> 1][(nt & 1)*2]);
        }
    }

    // epilogue: this warp owns f tile wpar (c[0]) and g tile wpar+2 (c[1])
    int gr = lane >> 2, qc = (lane & 3)*2;
    __half* hout = &g_hh[(size_t)(n*NB + b)*HVEC];
    #pragma unroll
    for (int hf = 0; hf < 2; hf++) {
        int o = wpar*16 + gr + hf*8;
        float fb = fbs[o], gb = gbs[o];
        #pragma unroll
        for (int nt = 0; nt < 7; nt++) {
            int t = nt*8 + qc;
            if (t < NK) {
                float h0 = fast_tanh(c[0][nt][hf*2+0] + fb) * fast_sig(c[1][nt][hf*2+0] + gb);
                float h1 = fast_tanh(c[0][nt][hf*2+1] + fb) * fast_sig(c[1][nt][hf*2+1] + gb);
                *(__half2*)&hout[o*NK + t] = __floats2half2_rn(h0, h1);
            }
        }
    }
}

// ---------------- skip conv as per-node HMMA GEMM (3-stage pipeline, race-free) ----------------
#define SK_WBYTES (64*272)
#define SK_BBYTES (32*272)
#define SK_BUF (SK_WBYTES + SK_BBYTES)
#define SKIP_SMEM (3*SK_BUF)
__global__ __launch_bounds__(128) void skip_mma(const float* __restrict__ skipb,
                                                float* __restrict__ sout)
{
    extern __shared__ __align__(16) char sks[];
    int n = blockIdx.x;
    int tid = threadIdx.x, warp = tid >> 5, lane = tid & 31;
    int m0 = warp * 16;
    uint32_t sb = smem_u32(sks);

    const __half* Bg = &g_hh[(size_t)n*NMCOL];

    float c[4][4];
    #pragma unroll
    for (int i = 0; i < 4; i++)
        #pragma unroll
        for (int j = 0; j < 4; j++) c[i][j] = 0.f;

    auto load_chunk = [&](int ch) {
        int buf = ch % 3;
        int k0 = ch * 128;
        uint32_t sW = sb + buf*SK_BUF;
        uint32_t sB = sW + SK_WBYTES;
        #pragma unroll
        for (int j = 0; j < 8; j++) {
            int lin = tid + j*128;
            int r = lin >> 4, q = lin & 15;
            CP_ASYNC16(sW + r*272 + q*16, &g_swh[r*HVEC + k0 + q*8]);
        }
        #pragma unroll
        for (int j = 0; j < 4; j++) {
            int lin = tid + j*128;
            int r = lin >> 4, q = lin & 15;
            CP_ASYNC16(sB + r*272 + q*16, &Bg[r*HVEC + k0 + q*8]);
        }
        CP_COMMIT();
    };

    load_chunk(0);
    load_chunk(1);

    for (int ch = 0; ch < 13; ch++) {
        if (ch == 12) { CP_WAIT0(); } else { CP_WAIT1(); }
        __syncthreads();   // all warps done reading chunk ch-1's buffer
        if (ch + 2 < 13) load_chunk(ch + 2);   // safe: writes buffer last read at ch-1
        uint32_t sW = sb + (ch % 3)*SK_BUF;
        uint32_t sB = sW + SK_WBYTES;
        #pragma unroll
        for (int ks = 0; ks < 8; ks++) {
            int k0 = ks * 16;
            uint32_t a[4];
            ldmx4(a, sW + (m0 + (lane & 15))*272 + (k0 + (lane >> 4)*8)*2);
            uint32_t bfr[2][4];
            #pragma unroll
            for (int np = 0; np < 2; np++)
                ldmx4(bfr[np], sB + (np*16 + (lane & 7) + ((lane >> 4) << 3))*272
                               + (k0 + ((lane >> 3) & 1)*8)*2);
            #pragma unroll
            for (int ni = 0; ni < 4; ni++)
                mma_f16(c[ni], a, &bfr[ni >> 1][(ni & 1)*2]);
        }
    }

    int gr = lane >> 2, qc = (lane & 3)*2;
    #pragma unroll
    for (int ni = 0; ni < 4; ni++) {
        int b0 = ni*8 + qc;
        int cs0 = m0 + gr;
        float bi0 = skipb[cs0], bi1 = skipb[cs0 + 8];
        sout[(b0*C_S + cs0)*NV + n]       = c[ni][0] + bi0;
        sout[((b0+1)*C_S + cs0)*NV + n]   = c[ni][1] + bi0;
        sout[(b0*C_S + cs0+8)*NV + n]     = c[ni][2] + bi1;
        sout[((b0+1)*C_S + cs0+8)*NV + n] = c[ni][3] + bi1;
    }
}

// ---------------- single-launch fp16 HMMA prop (BK=64, 3-stage, race-free) ----------------
#define PA_STRB 144
#define PA_BYTES (128*PA_STRB)     // 18432
#define PB_STRB 272
#define PB_BYTES (64*PB_STRB)      // 17408
#define PBUF (PA_BYTES + PB_BYTES) // 35840
#define PROP_SMEM (3*PBUF)
__global__ __launch_bounds__(256,2) void prop_mma()
{
    extern __shared__ __align__(16) char smp[];
    int z = blockIdx.z;
    int side = z >> 1, which = z & 1;
    const __half* Aadj = which ? g_B2h[side] : g_B1h[side];
    const __half* Bin = g_hh;
    __half* Hout = (z == 0) ? g_h1ah : (z == 1) ? g_h2ah : (z == 2) ? g_h1bh : g_h2bh;

    int tid = threadIdx.x, warp = tid >> 5, lane = tid & 31;
    int nbase = blockIdx.x * 128;
    int vt = blockIdx.y;
    int wm = (warp >> 2)*64, wn = (warp & 3)*32;
    uint32_t sb = smem_u32(smp);

    float c[4][4][4];
    #pragma unroll
    for (int i = 0; i < 4; i++)
        #pragma unroll
        for (int j = 0; j < 4; j++)
            #pragma unroll
            for (int q = 0; q < 4; q++) c[i][j][q] = 0.f;

    auto load_chunk = [&](int ch) {
        int buf = ch % 3;
        int w0 = ch * 64;
        uint32_t sA = sb + buf*PBUF;
        uint32_t sB = sA + PA_BYTES;
        #pragma unroll
        for (int j = 0; j < 4; j++) {
            int lin = tid + j*256;
            int r = lin >> 3, q = lin & 7;
            CP_ASYNC16(sA + r*PA_STRB + q*16, &Aadj[(vt*128 + r)*VP + w0 + q*8]);
        }
        #pragma unroll
        for (int j = 0; j < 4; j++) {
            int lin = tid + j*256;
            int r = lin >> 4, q = lin & 15;
            CP_ASYNC16(sB + r*PB_STRB + q*16, &Bin[(size_t)(w0 + r)*NMCOL + nbase + q*8]);
        }
        CP_COMMIT();
    };

    load_chunk(0);
    load_chunk(1);

    for (int ch = 0; ch < 8; ch++) {
        if (ch == 7) { CP_WAIT0(); } else { CP_WAIT1(); }
        __syncthreads();   // all warps done reading chunk ch-1's buffer
        if (ch + 2 < 8) load_chunk(ch + 2);   // safe after barrier
        uint32_t sA = sb + (ch % 3)*PBUF;
        uint32_t sB = sA + PA_BYTES;
        #pragma unroll
        for (int ks = 0; ks < 4; ks++) {
            int k0 = ks * 16;
            uint32_t a[4][4];
            #pragma unroll
            for (int mi = 0; mi < 4; mi++)
                ldmx4(a[mi], sA + (wm + mi*16 + (lane & 15))*PA_STRB + (k0 + (lane >> 4)*8)*2);
            uint32_t bfr[2][4];
            #pragma unroll
            for (int np = 0; np < 2; np++)
                ldmx4t(bfr[np], sB + (k0 + (lane & 15))*PB_STRB + (wn + np*16 + (lane >> 4)*8)*2);
            #pragma unroll
            for (int mi = 0; mi < 4; mi++)
                #pragma unroll
                for (int ni = 0; ni < 4; ni++)
                    mma_f16(c[mi][ni], a[mi], &bfr[ni >> 1][(ni & 1)*2]);
        }
    }

    // identity already folded into B1/B2 -> direct store
    int gr = lane >> 2, qc = (lane & 3)*2;
    #pragma unroll
    for (int mi = 0; mi < 4; mi++) {
        #pragma unroll
        for (int hf = 0; hf < 2; hf++) {
            int v = vt*128 + wm + mi*16 + gr + hf*8;
            if (v < NV) {
                #pragma unroll
                for (int ni = 0; ni < 4; ni++) {
                    size_t off = (size_t)v*NMCOL + nbase + wn + ni*8 + qc;
                    *(__half2*)&Hout[off] =
                        __floats2half2_rn(c[mi][ni][hf*2+0], c[mi][ni][hf*2+1]);
                }
            }
        }
    }
}

// ---------------- combine as per-(v,b) HMMA GEMM: out[c][l] = W[32x160] @ T[160x52] ----------------
#define CW_STRB 336
#define CW_BYTES (32*CW_STRB)              // 10752
#define CT_STRB 144
#define CT_WARP (160*CT_STRB)              // 23040 per warp
#define COMB_SMEM (CW_BYTES + 128 + 4*CT_WARP)
__global__ __launch_bounds__(128,2) void combine_mma(const float* __restrict__ x,
                                                     const float* __restrict__ gc1w,
                                                     const float* __restrict__ gc1b,
                                                     const float* __restrict__ gc2w,
                                                     const float* __restrict__ gc2b)
{
    extern __shared__ __align__(16) char smc[];
    uint32_t sW = smem_u32(smc);
    float* bias = (float*)(smc + CW_BYTES);
    uint32_t sT0 = sW + CW_BYTES + 128;

    int tid = threadIdx.x, warp = tid >> 5, lane = tid & 31;

    for (int e = tid; e < 5120; e += 128) {
        int cch = e / 160, k = e % 160;
        int t = k >> 5, cp = k & 31;
        float val;
        if      (t == 0) val = gc1w[cch*96 + cp] + gc2w[cch*96 + cp];
        else if (t == 1) val = gc1w[cch*96 + 32 + cp];
        else if (t == 2) val = gc1w[cch*96 + 64 + cp];
        else if (t == 3) val = gc2w[cch*96 + 32 + cp];
        else             val = gc2w[cch*96 + 64 + cp];
        *(__half*)(smc + cch*CW_STRB + k*2) = __float2half_rn(val);
    }
    if (tid < 32) bias[tid] = gc1b[tid] + gc2b[tid];

    int p = blockIdx.x * 4 + warp;
    int n = p >> 5, b = p & 31;
    uint32_t sT = sT0 + warp*CT_WARP;
    size_t slab_off = (size_t)(n*NB + b)*HVEC;
    for (int e = lane; e < 160*13; e += 32) {
        int r = e / 13, j = e % 13;
        const __half* slab = (r < 32) ? g_hh : (r < 64) ? g_h1ah : (r < 96) ? g_h2ah
                            : (r < 128) ? g_h1bh : g_h2bh;
        uint2 v = *(const uint2*)&slab[slab_off + (size_t)(r & 31)*NK + j*4];
        *(uint2*)((char*)smc + (sT - smem_u32(smc)) + r*CT_STRB + j*8) = v;
    }
    __syncthreads();

    float c[2][7][4];
    #pragma unroll
    for (int mi = 0; mi < 2; mi++)
        #pragma unroll
        for (int nt = 0; nt < 7; nt++)
            #pragma unroll
            for (int q = 0; q < 4; q++) c[mi][nt][q] = 0.f;

    #pragma unroll
    for (int ks = 0; ks < 10; ks++) {
        int k0 = ks * 16;
        uint32_t a[2][4];
        #pragma unroll
        for (int mi = 0; mi < 2; mi++)
            ldmx4(a[mi], sW + (mi*16 + (lane & 15))*CW_STRB + (k0 + (lane >> 4)*8)*2);
        uint32_t bq[4][4];
        #pragma unroll
        for (int nq = 0; nq < 4; nq++)
            ldmx4t(bq[nq], sT + (k0 + (lane & 15))*CT_STRB + (nq*16 + (lane >> 4)*8)*2);
        #pragma unroll
        for (int mi = 0; mi < 2; mi++)
            #pragma unroll
            for (int nt = 0; nt < 7; nt++)
                mma_f16(c[mi][nt], a[mi], &bq[nt >> 1][(nt & 1)*2]);
    }

    int gr = lane >> 2, qc = (lane & 3)*2;
    float psum = 0.f, psq = 0.f;
    #pragma unroll
    for (int mi = 0; mi < 2; mi++) {
        #pragma unroll
        for (int hf = 0; hf < 2; hf++) {
            int cch = mi*16 + gr + hf*8;
            float bi = bias[cch];
            const float* xr = &x[((size_t)(b*C_R + cch)*NV + n)*NT + 12];
            __half* xoh = &g_xoh[((size_t)(b*C_C + cch)*NV + n)*NK];
            #pragma unroll
            for (int nt = 0; nt < 7; nt++) {
                int l = nt*8 + qc;
                if (l < NK) {
                    float v0 = c[mi][nt][hf*2+0] + bi + xr[l];
                    float v1 = c[mi][nt][hf*2+1] + bi + xr[l+1];
                    *(__half2*)&xoh[l] = __floats2half2_rn(v0, v1);
                    psum += v0 + v1;
                    psq  = fmaf(v0, v0, psq);
                    psq  = fmaf(v1, v1, psq);
                }
            }
        }
    }
    #pragma unroll
    for (int off = 16; off > 0; off >>= 1) {
        psum += __shfl_down_sync(0xffffffffu, psum, off);
        psq  += __shfl_down_sync(0xffffffffu, psq,  off);
    }
    if (lane == 0) {
        atomicAdd(&g_stats[2*b], psum);
        atomicAdd(&g_stats[2*b + 1], psq);
    }
}

// ---------------- LayerNorm apply (reads fp16 xo) ----------------
__global__ __launch_bounds__(256) void norm_kernel(const int* __restrict__ idx,
                                                   const float* __restrict__ lnw,
                                                   const float* __restrict__ lnb,
                                                   float* __restrict__ out)
{
    int gid = blockIdx.x * 256 + threadIdx.x;
    int lq = gid % 13;
    int row = gid / 13;
    int v = row % NV;
    int cch = (row / NV) % C_C;
    int b = row / (C_C*NV);

    float s1 = g_stats[2*b], s2 = g_stats[2*b + 1];
    float mean = s1 * (1.f/(float)CNT_PER_B);
    float var  = s2 * (1.f/(float)CNT_PER_B) - mean*mean;
    float rstd = rsqrtf(var + 1e-5f);
    int nidx = idx[v];

    uint2 raw = *(const uint2*)&g_xoh[(size_t)row*NK + lq*4];
    float2 f01 = __half22float2(*(__half2*)&raw.x);
    float2 f23 = __half22float2(*(__half2*)&raw.y);
    float4 w4 = *(const float4*)&lnw[(cch*NV + nidx)*NK + lq*4];
    float4 b4 = *(const float4*)&lnb[(cch*NV + nidx)*NK + lq*4];
    float4 o;
    o.x = (f01.x - mean)*rstd*w4.x + b4.x;
    o.y = (f01.y - mean)*rstd*w4.y + b4.y;
    o.z = (f23.x - mean)*rstd*w4.z + b4.z;
    o.w = (f23.y - mean)*rstd*w4.w + b4.w;
    *(float4*)&out[row*NK + lq*4] = o;
}

// ---------------- launch ----------------
extern "C" void kernel_launch(void* const* d_in, const int* in_sizes, int n_in,
                              void* d_out, int out_size)
{
    const float* x = (const float*)d_in[0];
    int ia = (in_sizes[1] == NV*NV) ? 1 : 2;
    const float* adp = (const float*)d_in[ia];
    const int*   idx = (const int*)d_in[3 - ia];
    const float* fw2 = (const float*)d_in[3];
    const float* fb2 = (const float*)d_in[4];
    const float* fw3 = (const float*)d_in[5];
    const float* fb3 = (const float*)d_in[6];
    const float* fw6 = (const float*)d_in[7];
    const float* fb6 = (const float*)d_in[8];
    const float* fw7 = (const float*)d_in[9];
    const float* fb7 = (const float*)d_in[10];
    const float* gw2 = (const float*)d_in[11];
    const float* gb2 = (const float*)d_in[12];
    const float* gw3 = (const float*)d_in[13];
    const float* gb3 = (const float*)d_in[14];
    const float* gw6 = (const float*)d_in[15];
    const float* gb6 = (const float*)d_in[16];
    const float* gw7 = (const float*)d_in[17];
    const float* gb7 = (const float*)d_in[18];
    const float* skipw = (const float*)d_in[19];
    const float* skipb = (const float*)d_in[20];
    const float* gc1w = (const float*)d_in[21];
    const float* gc1b = (const float*)d_in[22];
    const float* gc2w = (const float*)d_in[23];
    const float* gc2b = (const float*)d_in[24];
    const float* lnw = (const float*)d_in[25];
    const float* lnb = (const float*)d_in[26];
    float* out = (float*)d_out;
    float* s_out = out + NB*C_C*NV*NK;

    cudaFuncSetAttribute(incept_mma,  cudaFuncAttributeMaxDynamicSharedMemorySize, INCEPT_SMEM);
    cudaFuncSetAttribute(skip_mma,    cudaFuncAttributeMaxDynamicSharedMemorySize, SKIP_SMEM);
    cudaFuncSetAttribute(prop_mma,    cudaFuncAttributeMaxDynamicSharedMemorySize, PROP_SMEM);
    cudaFuncSetAttribute(combine_mma, cudaFuncAttributeMaxDynamicSharedMemorySize, COMB_SMEM);

    pack_kernel<<<64, 256>>>(fw2, fw3, fw6, fw7, fb2, fb3, fb6, fb7,
                             gw2, gw3, gw6, gw7, gb2, gb3, gb6, gb7, skipw);
    sums_kernel<<<NV, 256>>>(adp);
    buildAB_kernel<<<dim3(16, 16), 256>>>(adp);
    incept_mma<<<4000, 256, INCEPT_SMEM>>>(x);          // slot 4: captured by ncu
    asq_part<<<dim3(8, 8, 8), 256>>>();
    asq_fin<<<dim3(1024, 2), 256>>>();
    skip_mma<<<NV, 128, SKIP_SMEM>>>(skipb, s_out);
    prop_mma<<<dim3(NMCOL/128, 4, 4), 256, PROP_SMEM>>>();
    combine_mma<<<4000, 128, COMB_SMEM>>>(x, gc1w, gc1b, gc2w, gc2b);
    norm_kernel<<<26000, 256>>>(idx, lnw, lnb, out);
}

// round 16
// speedup vs baseline: 4.4782x; 1.0083x over previous
#include <cuda_runtime.h>
#include <cuda_fp16.h>
#include <cstdint>

// ---------------- problem constants ----------------
#define NB   32
#define C_R  32
#define C_C  32
#define C_S  64
#define NV   500
#define NT   64
#define NK   52
#define NMCOL (NB*C_C*NK)   // 53248
#define VP   512
#define HVEC (C_C*NK)       // 1664
#define CNT_PER_B (C_C*NV*NK)

// ---------------- device scratch (zero-initialized) ----------------
__device__ float  g_a1f[VP*VP];
__device__ float  g_a2f[VP*VP];
__device__ __half g_Ah[2][VP*VP];     // fp16 normalized adjacency (both sides)
__device__ __half g_B1h[2][VP*VP];
__device__ __half g_B2h[2][VP*VP];
__device__ float  g_rs[NV];
__device__ float  g_cs[NV];
__device__ __half g_swh[C_S*HVEC];
__device__ __half g_Wph[7*64*40];     // packed inception weights, SMEM-image layout
__device__ float  g_fbias[C_C];
__device__ float  g_gbias[C_C];
// rows (nodes) padded to 512; rows >=500 never written, stay zero
__device__ __half g_hh  [VP*NMCOL];
__device__ __half g_h1ah[VP*NMCOL];
__device__ __half g_h1bh[VP*NMCOL];
__device__ __half g_h2ah[VP*NMCOL];
__device__ __half g_h2bh[VP*NMCOL];
__device__ __half g_xoh[NB*C_C*NV*NK];
__device__ float  g_stats[2*NB];

// ---------------- helpers ----------------
__device__ __forceinline__ uint32_t smem_u32(const void* p){
    uint32_t a; asm("{ .reg .u64 t; cvta.to.shared.u64 t, %1; cvt.u32.u64 %0, t; }":"=r"(a):"l"(p)); return a;
}
#define CP_ASYNC16(s,g) asm volatile("cp.async.cg.shared.global [%0], [%1], 16;"::"r"(s),"l"(g))
#define CP_COMMIT()     asm volatile("cp.async.commit_group;" ::: "memory")
#define CP_WAIT1()      asm volatile("cp.async.wait_group 1;" ::: "memory")
#define CP_WAIT0()      asm volatile("cp.async.wait_group 0;" ::: "memory")

__device__ __forceinline__ void ldmx4(uint32_t* r, uint32_t addr){
    asm volatile("ldmatrix.sync.aligned.m8n8.x4.shared.b16 {%0,%1,%2,%3}, [%4];"
        : "=r"(r[0]),"=r"(r[1]),"=r"(r[2]),"=r"(r[3]) : "r"(addr));
}
__device__ __forceinline__ void ldmx4t(uint32_t* r, uint32_t addr){
    asm volatile("ldmatrix.sync.aligned.m8n8.x4.trans.shared.b16 {%0,%1,%2,%3}, [%4];"
        : "=r"(r[0]),"=r"(r[1]),"=r"(r[2]),"=r"(r[3]) : "r"(addr));
}
__device__ __forceinline__ void mma_f16(float* c, const uint32_t* a, const uint32_t* b){
    asm volatile("mma.sync.aligned.m16n8k16.row.col.f32.f16.f16.f32 "
        "{%0,%1,%2,%3}, {%4,%5,%6,%7}, {%8,%9}, {%0,%1,%2,%3};"
        : "+f"(c[0]),"+f"(c[1]),"+f"(c[2]),"+f"(c[3])
        : "r"(a[0]),"r"(a[1]),"r"(a[2]),"r"(a[3]), "r"(b[0]),"r"(b[1]));
}
__device__ __forceinline__ float fast_tanh(float z){
    float e2 = __expf(fminf(-2.f*z, 40.f));
    return __fdividef(1.f - e2, 1.f + e2);
}
__device__ __forceinline__ float fast_sig(float z){
    return __fdividef(1.f, 1.f + __expf(fminf(-z, 40.f)));
}

// ---------------- pack: fp16 inception weights, half skip weights, zero sums/stats ----------------
__global__ void pack_kernel(const float* __restrict__ fw2,const float* __restrict__ fw3,
    const float* __restrict__ fw6,const float* __restrict__ fw7,
    const float* __restrict__ fb2,const float* __restrict__ fb3,
    const float* __restrict__ fb6,const float* __restrict__ fb7,
    const float* __restrict__ gw2,const float* __restrict__ gw3,
    const float* __restrict__ gw6,const float* __restrict__ gw7,
    const float* __restrict__ gb2,const float* __restrict__ gb3,
    const float* __restrict__ gb6,const float* __restrict__ gb7,
    const float* __restrict__ skipw)
{
    int tid = threadIdx.x;
    int gtid = blockIdx.x * blockDim.x + tid;
    for (int e = gtid; e < C_S*HVEC; e += gridDim.x * blockDim.x)
        g_swh[e] = __float2half_rn(skipw[e]);
    if (blockIdx.x != 0) return;
    if (tid < 2*NB) g_stats[tid] = 0.f;
    for (int e = tid; e < NV; e += blockDim.x) g_cs[e] = 0.f;
    for (int e = tid; e < 7*64*32; e += blockDim.x) {
        int j = e / 2048;
        int o = (e & 2047) >> 5;
        int i = e & 31;
        int oc = o & 31;
        int br = oc >> 3, oo = oc & 7;
        int k = (br==0)?2:(br==1)?3:(br==2)?6:7;
        int j0 = 7 - k;
        float vv = 0.f;
        if (j >= j0) {
            int si = (oo*C_R + i)*k + (j - j0);
            if (o < 32) {
                const float* fw = (br==0)?fw2:(br==1)?fw3:(br==2)?fw6:fw7;
                vv = fw[si];
            } else {
                const float* gw = (br==0)?gw2:(br==1)?gw3:(br==2)?gw6:gw7;
                vv = gw[si];
            }
        }
        g_Wph[(j*64 + o)*40 + i] = __float2half_rn(vv);
    }
    if (tid < C_C) {
        int br = tid >> 3, oo = tid & 7;
        const float* fb = (br==0)?fb2:(br==1)?fb3:(br==2)?fb6:fb7;
        const float* gb = (br==0)?gb2:(br==1)?gb3:(br==2)?gb6:gb7;
        g_fbias[tid] = fb[oo]; g_gbias[tid] = gb[oo];
    }
}

// ---------------- row sums (coalesced) + col sums (atomics) ----------------
__global__ void sums_kernel(const float* __restrict__ adp)
{
    int v = blockIdx.x;
    __shared__ float red[256];
    int tid = threadIdx.x;
    float s = 0.f;
    for (int w = tid; w < NV; w += 256) {
        float val = adp[v*NV + w];
        s += val;
        atomicAdd(&g_cs[w], val);
    }
    red[tid] = s; __syncthreads();
    for (int st = 128; st > 0; st >>= 1) {
        if (tid < st) red[tid] += red[tid + st];
        __syncthreads();
    }
    if (tid == 0) g_rs[v] = red[0] + 1.f;
}

// ---------------- build a1f/a2f fp32 + fp16 A + B1 fp16 for both sides ----------------
__global__ void buildAB_kernel(const float* __restrict__ adp)
{
    __shared__ float tile[32][33];
    int tid = threadIdx.x;
    int I = blockIdx.y*32, J = blockIdx.x*32;
    #pragma unroll
    for (int l = 0; l < 4; l++) {
        int ii = (tid >> 5) + l*8, jj = tid & 31;
        int r = I + ii, c = J + jj;
        tile[ii][jj] = (r < NV && c < NV) ? adp[r*NV + c] : 0.f;
    }
    __syncthreads();
    #pragma unroll
    for (int l = 0; l < 4; l++) {
        int ii = (tid >> 5) + l*8, jj = tid & 31;
        int r = I + ii, c = J + jj;
        float a1 = 0.f;
        if (r < NV && c < NV)
            a1 = (tile[ii][jj] + (r == c ? 1.f : 0.f)) * (1.f / g_rs[r]);
        g_a1f[r*VP + c] = a1;
        g_Ah[0][r*VP + c] = __float2half_rn(a1);
        g_B1h[0][r*VP + c] = __float2half_rn(0.95f*a1 + ((r == c && r < NV) ? 0.05f : 0.f));
    }
    #pragma unroll
    for (int l = 0; l < 4; l++) {
        int ii = (tid >> 5) + l*8, jj = tid & 31;
        int rr = J + ii, cc = I + jj;      // a2f[rr][cc] = (adp[cc][rr]+d)/(cs[rr]+1)
        float a2 = 0.f;
        if (rr < NV && cc < NV)
            a2 = (tile[jj][ii] + (rr == cc ? 1.f : 0.f)) * (1.f / (g_cs[rr] + 1.f));
        g_a2f[rr*VP + cc] = a2;
        g_Ah[1][rr*VP + cc] = __float2half_rn(a2);
        g_B1h[1][rr*VP + cc] = __float2half_rn(0.95f*a2 + ((rr == cc && rr < NV) ? 0.05f : 0.f));
    }
}

// ---------------- HMMA dilated inception + gating -> fp16 h ----------------
// 2 warps per (n,b) pair: warp-parity 0 -> m-tiles {0,2}, parity 1 -> {1,3}.
#define XST_ROWS 80
#define XST_STRB 80
#define XST_WARP (XST_ROWS*XST_STRB)
#define WP_STRB 80
#define WP_BYTES (7*64*WP_STRB)           // 35840 B
#define INCEPT_SMEM (WP_BYTES + 4*XST_WARP + 512)
__global__ __launch_bounds__(256,2) void incept_mma(const float* __restrict__ x)
{
    extern __shared__ __align__(16) char smi[];
    uint32_t sW = smem_u32(smi);
    uint32_t sX0 = sW + WP_BYTES;
    float* fbs = (float*)(smi + WP_BYTES + 4*XST_WARP);
    float* gbs = fbs + 32;

    int tid = threadIdx.x, warp = tid >> 5, lane = tid & 31;
    int pairidx = warp >> 1, wpar = warp & 1;

    for (int e = tid; e < WP_BYTES/16; e += 256)
        *(float4*)(smi + e*16) = *(const float4*)(((const char*)g_Wph) + e*16);
    if (tid < 32) { fbs[tid] = g_fbias[tid]; gbs[tid] = g_gbias[tid]; }

    int p = blockIdx.x * 4 + pairidx;
    int n = p >> 5, b = p & 31;
    uint32_t sX = sX0 + pairidx*XST_WARP;
    {
        int tid64 = tid & 63;
        int i0 = (tid64 & 15) * 2;
        int t0 = (tid64 >> 4) * 16;
        const float* xr0 = &x[((size_t)(b*C_R + i0)*NV + n)*NT + t0];
        const float* xr1 = xr0 + (size_t)NV*NT;
        #pragma unroll
        for (int q = 0; q < 4; q++) {
            float4 v0 = *(const float4*)&xr0[q*4];
            float4 v1 = *(const float4*)&xr1[q*4];
            const float* a0 = &v0.x; const float* a1 = &v1.x;
            #pragma unroll
            for (int r = 0; r < 4; r++) {
                int t = t0 + q*4 + r;
                *(__half2*)(smi + (sX - smem_u32(smi)) + t*XST_STRB + i0*2) =
                    __floats2half2_rn(a0[r], a1[r]);
            }
        }
    }
    __syncthreads();

    float c[2][7][4];
    #pragma unroll
    for (int ml = 0; ml < 2; ml++)
        #pragma unroll
        for (int nt = 0; nt < 7; nt++)
            #pragma unroll
            for (int q = 0; q < 4; q++) c[ml][nt][q] = 0.f;

    #pragma unroll
    for (int j = 0; j < 7; j++) {
        uint32_t wbase = sW + j*64*WP_STRB;
        #pragma unroll
        for (int kst = 0; kst < 2; kst++) {
            int kb = (kst*16 + (lane >> 4)*8) * 2;
            uint32_t a[2][4];
            #pragma unroll
            for (int ml = 0; ml < 2; ml++) {
                int mi = wpar + ml*2;
                ldmx4(a[ml], wbase + (mi*16 + (lane & 15))*WP_STRB + kb);
            }
            uint32_t bf[4][4];
            int kbb = (kst*16 + ((lane >> 3) & 1)*8) * 2;
            #pragma unroll
            for (int nb8 = 0; nb8 < 4; nb8++) {
                int trow = nb8*16 + (lane & 7) + ((lane >> 4) << 3) + 2*j;
                ldmx4(bf[nb8], sX + trow*XST_STRB + kbb);
            }
            #pragma unroll
            for (int ml = 0; ml < 2; ml++)
                #pragma unroll
                for (int nt = 0; nt < 7; nt++)
                    mma_f16(c[ml][nt], a[ml], &bf[nt >> 1][(nt & 1)*2]);
        }
    }

    int gr = lane >> 2, qc = (lane & 3)*2;
    __half* hout = &g_hh[(size_t)(n*NB + b)*HVEC];
    #pragma unroll
    for (int hf = 0; hf < 2; hf++) {
        int o = wpar*16 + gr + hf*8;
        float fb = fbs[o], gb = gbs[o];
        #pragma unroll
        for (int nt = 0; nt < 7; nt++) {
            int t = nt*8 + qc;
            if (t < NK) {
                float h0 = fast_tanh(c[0][nt][hf*2+0] + fb) * fast_sig(c[1][nt][hf*2+0] + gb);
                float h1 = fast_tanh(c[0][nt][hf*2+1] + fb) * fast_sig(c[1][nt][hf*2+1] + gb);
                *(__half2*)&hout[o*NK + t] = __floats2half2_rn(h0, h1);
            }
        }
    }
}

// ---------------- fp16 HMMA A^2: B2 = fp16(0.9025*Ah@Ah + 0.0475*A + 0.05*I) ----------------
#define PA_STRB 144
#define PA_BYTES (128*PA_STRB)     // 18432
#define PB_STRB 272
#define PB_BYTES (64*PB_STRB)      // 17408
#define PBUF (PA_BYTES + PB_BYTES) // 35840
#define PROP_SMEM (3*PBUF)
__global__ __launch_bounds__(256,2) void asq_mma()
{
    extern __shared__ __align__(16) char smp[];
    int side = blockIdx.z;
    const __half* Ah = g_Ah[side];
    const float* Af = side ? g_a2f : g_a1f;
    __half* B2 = g_B2h[side];

    int tid = threadIdx.x, warp = tid >> 5, lane = tid & 31;
    int nbase = blockIdx.x * 128;     // output column tile
    int vt = blockIdx.y;              // output row tile
    int wm = (warp >> 2)*64, wn = (warp & 3)*32;
    uint32_t sb = smem_u32(smp);

    float c[4][4][4];
    #pragma unroll
    for (int i = 0; i < 4; i++)
        #pragma unroll
        for (int j = 0; j < 4; j++)
            #pragma unroll
            for (int q = 0; q < 4; q++) c[i][j][q] = 0.f;

    auto load_chunk = [&](int ch) {
        int buf = ch % 3;
        int w0 = ch * 64;
        uint32_t sA = sb + buf*PBUF;
        uint32_t sB = sA + PA_BYTES;
        #pragma unroll
        for (int j = 0; j < 4; j++) {
            int lin = tid + j*256;
            int r = lin >> 3, q = lin & 7;
            CP_ASYNC16(sA + r*PA_STRB + q*16, &Ah[(vt*128 + r)*VP + w0 + q*8]);
        }
        #pragma unroll
        for (int j = 0; j < 4; j++) {
            int lin = tid + j*256;
            int r = lin >> 4, q = lin & 15;
            CP_ASYNC16(sB + r*PB_STRB + q*16, &Ah[(size_t)(w0 + r)*VP + nbase + q*8]);
        }
        CP_COMMIT();
    };

    load_chunk(0);
    load_chunk(1);

    for (int ch = 0; ch < 8; ch++) {
        if (ch == 7) { CP_WAIT0(); } else { CP_WAIT1(); }
        __syncthreads();
        if (ch + 2 < 8) load_chunk(ch + 2);
        uint32_t sA = sb + (ch % 3)*PBUF;
        uint32_t sB = sA + PA_BYTES;
        #pragma unroll
        for (int ks = 0; ks < 4; ks++) {
            int k0 = ks * 16;
            uint32_t a[4][4];
            #pragma unroll
            for (int mi = 0; mi < 4; mi++)
                ldmx4(a[mi], sA + (wm + mi*16 + (lane & 15))*PA_STRB + (k0 + (lane >> 4)*8)*2);
            uint32_t bfr[2][4];
            #pragma unroll
            for (int np = 0; np < 2; np++)
                ldmx4t(bfr[np], sB + (k0 + (lane & 15))*PB_STRB + (wn + np*16 + (lane >> 4)*8)*2);
            #pragma unroll
            for (int mi = 0; mi < 4; mi++)
                #pragma unroll
                for (int ni = 0; ni < 4; ni++)
                    mma_f16(c[mi][ni], a[mi], &bfr[ni >> 1][(ni & 1)*2]);
        }
    }

    int gr = lane >> 2, qc = (lane & 3)*2;
    #pragma unroll
    for (int mi = 0; mi < 4; mi++) {
        #pragma unroll
        for (int hf = 0; hf < 2; hf++) {
            int v = vt*128 + wm + mi*16 + gr + hf*8;
            #pragma unroll
            for (int ni = 0; ni < 4; ni++) {
                int col = nbase + wn + ni*8 + qc;
                float2 af = *(const float2*)&Af[(size_t)v*VP + col];
                float v0 = 0.9025f*c[mi][ni][hf*2+0] + 0.0475f*af.x
                         + ((v == col && v < NV) ? 0.05f : 0.f);
                float v1 = 0.9025f*c[mi][ni][hf*2+1] + 0.0475f*af.y
                         + ((v == col+1 && v < NV) ? 0.05f : 0.f);
                *(__half2*)&B2[(size_t)v*VP + col] = __floats2half2_rn(v0, v1);
            }
        }
    }
}

// ---------------- skip conv as per-node HMMA GEMM (3-stage pipeline, race-free) ----------------
#define SK_WBYTES (64*272)
#define SK_BBYTES (32*272)
#define SK_BUF (SK_WBYTES + SK_BBYTES)
#define SKIP_SMEM (3*SK_BUF)
__global__ __launch_bounds__(128) void skip_mma(const float* __restrict__ skipb,
                                                float* __restrict__ sout)
{
    extern __shared__ __align__(16) char sks[];
    int n = blockIdx.x;
    int tid = threadIdx.x, warp = tid >> 5, lane = tid & 31;
    int m0 = warp * 16;
    uint32_t sb = smem_u32(sks);

    const __half* Bg = &g_hh[(size_t)n*NMCOL];

    float c[4][4];
    #pragma unroll
    for (int i = 0; i < 4; i++)
        #pragma unroll
        for (int j = 0; j < 4; j++) c[i][j] = 0.f;

    auto load_chunk = [&](int ch) {
        int buf = ch % 3;
        int k0 = ch * 128;
        uint32_t sW = sb + buf*SK_BUF;
        uint32_t sB = sW + SK_WBYTES;
        #pragma unroll
        for (int j = 0; j < 8; j++) {
            int lin = tid + j*128;
            int r = lin >> 4, q = lin & 15;
            CP_ASYNC16(sW + r*272 + q*16, &g_swh[r*HVEC + k0 + q*8]);
        }
        #pragma unroll
        for (int j = 0; j < 4; j++) {
            int lin = tid + j*128;
            int r = lin >> 4, q = lin & 15;
            CP_ASYNC16(sB + r*272 + q*16, &Bg[r*HVEC + k0 + q*8]);
        }
        CP_COMMIT();
    };

    load_chunk(0);
    load_chunk(1);

    for (int ch = 0; ch < 13; ch++) {
        if (ch == 12) { CP_WAIT0(); } else { CP_WAIT1(); }
        __syncthreads();
        if (ch + 2 < 13) load_chunk(ch + 2);
        uint32_t sW = sb + (ch % 3)*SK_BUF;
        uint32_t sB = sW + SK_WBYTES;
        #pragma unroll
        for (int ks = 0; ks < 8; ks++) {
            int k0 = ks * 16;
            uint32_t a[4];
            ldmx4(a, sW + (m0 + (lane & 15))*272 + (k0 + (lane >> 4)*8)*2);
            uint32_t bfr[2][4];
            #pragma unroll
            for (int np = 0; np < 2; np++)
                ldmx4(bfr[np], sB + (np*16 + (lane & 7) + ((lane >> 4) << 3))*272
                               + (k0 + ((lane >> 3) & 1)*8)*2);
            #pragma unroll
            for (int ni = 0; ni < 4; ni++)
                mma_f16(c[ni], a, &bfr[ni >> 1][(ni & 1)*2]);
        }
    }

    int gr = lane >> 2, qc = (lane & 3)*2;
    #pragma unroll
    for (int ni = 0; ni < 4; ni++) {
        int b0 = ni*8 + qc;
        int cs0 = m0 + gr;
        float bi0 = skipb[cs0], bi1 = skipb[cs0 + 8];
        sout[(b0*C_S + cs0)*NV + n]       = c[ni][0] + bi0;
        sout[((b0+1)*C_S + cs0)*NV + n]   = c[ni][1] + bi0;
        sout[(b0*C_S + cs0+8)*NV + n]     = c[ni][2] + bi1;
        sout[((b0+1)*C_S + cs0+8)*NV + n] = c[ni][3] + bi1;
    }
}

// ---------------- single-launch fp16 HMMA prop (BK=64, 3-stage, race-free) ----------------
__global__ __launch_bounds__(256,2) void prop_mma()
{
    extern __shared__ __align__(16) char smp[];
    int z = blockIdx.z;
    int side = z >> 1, which = z & 1;
    const __half* Aadj = which ? g_B2h[side] : g_B1h[side];
    const __half* Bin = g_hh;
    __half* Hout = (z == 0) ? g_h1ah : (z == 1) ? g_h2ah : (z == 2) ? g_h1bh : g_h2bh;

    int tid = threadIdx.x, warp = tid >> 5, lane = tid & 31;
    int nbase = blockIdx.x * 128;
    int vt = blockIdx.y;
    int wm = (warp >> 2)*64, wn = (warp & 3)*32;
    uint32_t sb = smem_u32(smp);

    float c[4][4][4];
    #pragma unroll
    for (int i = 0; i < 4; i++)
        #pragma unroll
        for (int j = 0; j < 4; j++)
            #pragma unroll
            for (int q = 0; q < 4; q++) c[i][j][q] = 0.f;

    auto load_chunk = [&](int ch) {
        int buf = ch % 3;
        int w0 = ch * 64;
        uint32_t sA = sb + buf*PBUF;
        uint32_t sB = sA + PA_BYTES;
        #pragma unroll
        for (int j = 0; j < 4; j++) {
            int lin = tid + j*256;
            int r = lin >> 3, q = lin & 7;
            CP_ASYNC16(sA + r*PA_STRB + q*16, &Aadj[(vt*128 + r)*VP + w0 + q*8]);
        }
        #pragma unroll
        for (int j = 0; j < 4; j++) {
            int lin = tid + j*256;
            int r = lin >> 4, q = lin & 15;
            CP_ASYNC16(sB + r*PB_STRB + q*16, &Bin[(size_t)(w0 + r)*NMCOL + nbase + q*8]);
        }
        CP_COMMIT();
    };

    load_chunk(0);
    load_chunk(1);

    for (int ch = 0; ch < 8; ch++) {
        if (ch == 7) { CP_WAIT0(); } else { CP_WAIT1(); }
        __syncthreads();
        if (ch + 2 < 8) load_chunk(ch + 2);
        uint32_t sA = sb + (ch % 3)*PBUF;
        uint32_t sB = sA + PA_BYTES;
        #pragma unroll
        for (int ks = 0; ks < 4; ks++) {
            int k0 = ks * 16;
            uint32_t a[4][4];
            #pragma unroll
            for (int mi = 0; mi < 4; mi++)
                ldmx4(a[mi], sA + (wm + mi*16 + (lane & 15))*PA_STRB + (k0 + (lane >> 4)*8)*2);
            uint32_t bfr[2][4];
            #pragma unroll
            for (int np = 0; np < 2; np++)
                ldmx4t(bfr[np], sB + (k0 + (lane & 15))*PB_STRB + (wn + np*16 + (lane >> 4)*8)*2);
            #pragma unroll
            for (int mi = 0; mi < 4; mi++)
                #pragma unroll
                for (int ni = 0; ni < 4; ni++)
                    mma_f16(c[mi][ni], a[mi], &bfr[ni >> 1][(ni & 1)*2]);
        }
    }

    int gr = lane >> 2, qc = (lane & 3)*2;
    #pragma unroll
    for (int mi = 0; mi < 4; mi++) {
        #pragma unroll
        for (int hf = 0; hf < 2; hf++) {
            int v = vt*128 + wm + mi*16 + gr + hf*8;
            if (v < NV) {
                #pragma unroll
                for (int ni = 0; ni < 4; ni++) {
                    size_t off = (size_t)v*NMCOL + nbase + wn + ni*8 + qc;
                    *(__half2*)&Hout[off] =
                        __floats2half2_rn(c[mi][ni][hf*2+0], c[mi][ni][hf*2+1]);
                }
            }
        }
    }
}

// ---------------- combine as per-(v,b) HMMA GEMM: out[c][l] = W[32x160] @ T[160x52] ----------------
#define CW_STRB 336
#define CW_BYTES (32*CW_STRB)              // 10752
#define CT_STRB 144
#define CT_WARP (160*CT_STRB)              // 23040 per warp
#define COMB_SMEM (CW_BYTES + 128 + 4*CT_WARP)
__global__ __launch_bounds__(128,2) void combine_mma(const float* __restrict__ x,
                                                     const float* __restrict__ gc1w,
                                                     const float* __restrict__ gc1b,
                                                     const float* __restrict__ gc2w,
                                                     const float* __restrict__ gc2b)
{
    extern __shared__ __align__(16) char smc[];
    uint32_t sW = smem_u32(smc);
    float* bias = (float*)(smc + CW_BYTES);
    uint32_t sT0 = sW + CW_BYTES + 128;

    int tid = threadIdx.x, warp = tid >> 5, lane = tid & 31;

    for (int e = tid; e < 5120; e += 128) {
        int cch = e / 160, k = e % 160;
        int t = k >> 5, cp = k & 31;
        float val;
        if      (t == 0) val = gc1w[cch*96 + cp] + gc2w[cch*96 + cp];
        else if (t == 1) val = gc1w[cch*96 + 32 + cp];
        else if (t == 2) val = gc1w[cch*96 + 64 + cp];
        else if (t == 3) val = gc2w[cch*96 + 32 + cp];
        else             val = gc2w[cch*96 + 64 + cp];
        *(__half*)(smc + cch*CW_STRB + k*2) = __float2half_rn(val);
    }
    if (tid < 32) bias[tid] = gc1b[tid] + gc2b[tid];

    int p = blockIdx.x * 4 + warp;
    int n = p >> 5, b = p & 31;
    uint32_t sT = sT0 + warp*CT_WARP;
    size_t slab_off = (size_t)(n*NB + b)*HVEC;
    for (int e = lane; e < 160*13; e += 32) {
        int r = e / 13, j = e % 13;
        const __half* slab = (r < 32) ? g_hh : (r < 64) ? g_h1ah : (r < 96) ? g_h2ah
                            : (r < 128) ? g_h1bh : g_h2bh;
        uint2 v = *(const uint2*)&slab[slab_off + (size_t)(r & 31)*NK + j*4];
        *(uint2*)((char*)smc + (sT - smem_u32(smc)) + r*CT_STRB + j*8) = v;
    }
    __syncthreads();

    float c[2][7][4];
    #pragma unroll
    for (int mi = 0; mi < 2; mi++)
        #pragma unroll
        for (int nt = 0; nt < 7; nt++)
            #pragma unroll
            for (int q = 0; q < 4; q++) c[mi][nt][q] = 0.f;

    #pragma unroll
    for (int ks = 0; ks < 10; ks++) {
        int k0 = ks * 16;
        uint32_t a[2][4];
        #pragma unroll
        for (int mi = 0; mi < 2; mi++)
            ldmx4(a[mi], sW + (mi*16 + (lane & 15))*CW_STRB + (k0 + (lane >> 4)*8)*2);
        uint32_t bq[4][4];
        #pragma unroll
        for (int nq = 0; nq < 4; nq++)
            ldmx4t(bq[nq], sT + (k0 + (lane & 15))*CT_STRB + (nq*16 + (lane >> 4)*8)*2);
        #pragma unroll
        for (int mi = 0; mi < 2; mi++)
            #pragma unroll
            for (int nt = 0; nt < 7; nt++)
                mma_f16(c[mi][nt], a[mi], &bq[nt >> 1][(nt & 1)*2]);
    }

    int gr = lane >> 2, qc = (lane & 3)*2;
    float psum = 0.f, psq = 0.f;
    #pragma unroll
    for (int mi = 0; mi < 2; mi++) {
        #pragma unroll
        for (int hf = 0; hf < 2; hf++) {
            int cch = mi*16 + gr + hf*8;
            float bi = bias[cch];
            const float* xr = &x[((size_t)(b*C_R + cch)*NV + n)*NT + 12];
            __half* xoh = &g_xoh[((size_t)(b*C_C + cch)*NV + n)*NK];
            #pragma unroll
            for (int nt = 0; nt < 7; nt++) {
                int l = nt*8 + qc;
                if (l < NK) {
                    float v0 = c[mi][nt][hf*2+0] + bi + xr[l];
                    float v1 = c[mi][nt][hf*2+1] + bi + xr[l+1];
                    *(__half2*)&xoh[l] = __floats2half2_rn(v0, v1);
                    psum += v0 + v1;
                    psq  = fmaf(v0, v0, psq);
                    psq  = fmaf(v1, v1, psq);
                }
            }
        }
    }
    #pragma unroll
    for (int off = 16; off > 0; off >>= 1) {
        psum += __shfl_down_sync(0xffffffffu, psum, off);
        psq  += __shfl_down_sync(0xffffffffu, psq,  off);
    }
    if (lane == 0) {
        atomicAdd(&g_stats[2*b], psum);
        atomicAdd(&g_stats[2*b + 1], psq);
    }
}

// ---------------- LayerNorm apply (reads fp16 xo) ----------------
__global__ __launch_bounds__(256) void norm_kernel(const int* __restrict__ idx,
                                                   const float* __restrict__ lnw,
                                                   const float* __restrict__ lnb,
                                                   float* __restrict__ out)
{
    int gid = blockIdx.x * 256 + threadIdx.x;
    int lq = gid % 13;
    int row = gid / 13;
    int v = row % NV;
    int cch = (row / NV) % C_C;
    int b = row / (C_C*NV);

    float s1 = g_stats[2*b], s2 = g_stats[2*b + 1];
    float mean = s1 * (1.f/(float)CNT_PER_B);
    float var  = s2 * (1.f/(float)CNT_PER_B) - mean*mean;
    float rstd = rsqrtf(var + 1e-5f);
    int nidx = idx[v];

    uint2 raw = *(const uint2*)&g_xoh[(size_t)row*NK + lq*4];
    float2 f01 = __half22float2(*(__half2*)&raw.x);
    float2 f23 = __half22float2(*(__half2*)&raw.y);
    float4 w4 = *(const float4*)&lnw[(cch*NV + nidx)*NK + lq*4];
    float4 b4 = *(const float4*)&lnb[(cch*NV + nidx)*NK + lq*4];
    float4 o;
    o.x = (f01.x - mean)*rstd*w4.x + b4.x;
    o.y = (f01.y - mean)*rstd*w4.y + b4.y;
    o.z = (f23.x - mean)*rstd*w4.z + b4.z;
    o.w = (f23.y - mean)*rstd*w4.w + b4.w;
    *(float4*)&out[row*NK + lq*4] = o;
}

// ---------------- launch ----------------
extern "C" void kernel_launch(void* const* d_in, const int* in_sizes, int n_in,
                              void* d_out, int out_size)
{
    const float* x = (const float*)d_in[0];
    int ia = (in_sizes[1] == NV*NV) ? 1 : 2;
    const float* adp = (const float*)d_in[ia];
    const int*   idx = (const int*)d_in[3 - ia];
    const float* fw2 = (const float*)d_in[3];
    const float* fb2 = (const float*)d_in[4];
    const float* fw3 = (const float*)d_in[5];
    const float* fb3 = (const float*)d_in[6];
    const float* fw6 = (const float*)d_in[7];
    const float* fb6 = (const float*)d_in[8];
    const float* fw7 = (const float*)d_in[9];
    const float* fb7 = (const float*)d_in[10];
    const float* gw2 = (const float*)d_in[11];
    const float* gb2 = (const float*)d_in[12];
    const float* gw3 = (const float*)d_in[13];
    const float* gb3 = (const float*)d_in[14];
    const float* gw6 = (const float*)d_in[15];
    const float* gb6 = (const float*)d_in[16];
    const float* gw7 = (const float*)d_in[17];
    const float* gb7 = (const float*)d_in[18];
    const float* skipw = (const float*)d_in[19];
    const float* skipb = (const float*)d_in[20];
    const float* gc1w = (const float*)d_in[21];
    const float* gc1b = (const float*)d_in[22];
    const float* gc2w = (const float*)d_in[23];
    const float* gc2b = (const float*)d_in[24];
    const float* lnw = (const float*)d_in[25];
    const float* lnb = (const float*)d_in[26];
    float* out = (float*)d_out;
    float* s_out = out + NB*C_C*NV*NK;

    cudaFuncSetAttribute(incept_mma,  cudaFuncAttributeMaxDynamicSharedMemorySize, INCEPT_SMEM);
    cudaFuncSetAttribute(skip_mma,    cudaFuncAttributeMaxDynamicSharedMemorySize, SKIP_SMEM);
    cudaFuncSetAttribute(asq_mma,     cudaFuncAttributeMaxDynamicSharedMemorySize, PROP_SMEM);
    cudaFuncSetAttribute(prop_mma,    cudaFuncAttributeMaxDynamicSharedMemorySize, PROP_SMEM);
    cudaFuncSetAttribute(combine_mma, cudaFuncAttributeMaxDynamicSharedMemorySize, COMB_SMEM);

    pack_kernel<<<64, 256>>>(fw2, fw3, fw6, fw7, fb2, fb3, fb6, fb7,
                             gw2, gw3, gw6, gw7, gb2, gb3, gb6, gb7, skipw);
    sums_kernel<<<NV, 256>>>(adp);
    buildAB_kernel<<<dim3(16, 16), 256>>>(adp);
    incept_mma<<<4000, 256, INCEPT_SMEM>>>(x);          // slot 4: captured by ncu
    asq_mma<<<dim3(4, 4, 2), 256, PROP_SMEM>>>();
    skip_mma<<<NV, 128, SKIP_SMEM>>>(skipb, s_out);
    prop_mma<<<dim3(NMCOL/128, 4, 4), 256, PROP_SMEM>>>();
    combine_mma<<<4000, 128, COMB_SMEM>>>(x, gc1w, gc1b, gc2w, gc2b);
    norm_kernel<<<26000, 256>>>(idx, lnw, lnb, out);
}